// round 11
// baseline (speedup 1.0000x reference)
#include <cuda_runtime.h>
#include <cuda_fp16.h>
#include <math.h>
#include <stdint.h>

// ---------------- problem dims ----------------
#define Bb   4
#define Tt   12
#define Nn   1024
#define Dd   512
#define Hh   8
#define hd   64
#define Cc   128
#define Ss   60
#define BT   48            // Bb*Tt
#define M_BIG  49152       // BT*Nn
#define M_POOL 6144        // BT*Cc
#define Gg   384           // BT*Hh

// ---------------- device scratch (allocation-free) ----------------
__device__ float g_QE [M_BIG  * 1024];   // [m][0:512]=q, [512:1024]=ev (fp32)
__device__ float g_KV [M_POOL * 1024];   // [c][0:512]=k, [512:1024]=v
__device__ float g_OUT[M_BIG  * Dd];     // attention branch output (pre-Wo)
__device__ float g_ADT[Cc * Nn];         // adp_pos transposed [c][n]
__device__ float g_CL [Gg * 64];         // 0.5 / colsum  (s padded to 64)

__device__ __half g_EXP1[(size_t)Gg * Nn * 64];  // exp(e1), [g][n][64], s>=60 -> 0
__device__ __half g_evh [M_BIG  * Dd];   // ev half (fp16 copy from QE gemm epilogue)
__device__ __half g_xh  [M_BIG  * Dd];
__device__ __half g_xph [M_POOL * Dd];
__device__ __half g_oh  [M_BIG  * Dd];
__device__ __half g_wqeh[1024 * Dd];
__device__ __half g_wkvh[1024 * Dd];
__device__ __half g_woh [Dd * Dd];

// ---------------- helpers ----------------
typedef unsigned long long u64t;
__device__ __forceinline__ uint32_t smem_u32(const void* p) {
    uint32_t a;
    asm("{ .reg .u64 t; cvta.to.shared.u64 t, %1; cvt.u32.u64 %0, t; }" : "=r"(a) : "l"(p));
    return a;
}
__device__ __forceinline__ u64t fma2(u64t a, u64t b, u64t c) {
    u64t d; asm("fma.rn.f32x2 %0, %1, %2, %3;" : "=l"(d) : "l"(a), "l"(b), "l"(c)); return d;
}
__device__ __forceinline__ u64t mul2(u64t a, u64t b) {
    u64t d; asm("mul.rn.f32x2 %0, %1, %2;" : "=l"(d) : "l"(a), "l"(b)); return d;
}
__device__ __forceinline__ u64t pack2(float x, float y) {
    u64t d; asm("mov.b64 %0, {%1, %2};" : "=l"(d) : "f"(x), "f"(y)); return d;
}
__device__ __forceinline__ float2 unpack2(u64t v) {
    float2 r; asm("mov.b64 {%0, %1}, %2;" : "=f"(r.x), "=f"(r.y) : "l"(v)); return r;
}
#define CP_ASYNC16(dst, src) \
    asm volatile("cp.async.cg.shared.global [%0], [%1], 16;" :: "r"(dst), "l"(src) : "memory")
#define CP_COMMIT() asm volatile("cp.async.commit_group;" ::: "memory")
#define CP_WAIT2()  asm volatile("cp.async.wait_group 2;" ::: "memory")
#define CP_WAIT0()  asm volatile("cp.async.wait_group 0;" ::: "memory")
#define LDSM4(r, addr) \
    asm volatile("ldmatrix.sync.aligned.m8n8.x4.shared.b16 {%0,%1,%2,%3}, [%4];" \
        : "=r"((r)[0]), "=r"((r)[1]), "=r"((r)[2]), "=r"((r)[3]) : "r"(addr))
__device__ __forceinline__ void mma16816(float* c, const uint32_t* a,
                                         uint32_t b0, uint32_t b1) {
    asm volatile("mma.sync.aligned.m16n8k16.row.col.f32.f16.f16.f32 "
                 "{%0,%1,%2,%3}, {%4,%5,%6,%7}, {%8,%9}, {%0,%1,%2,%3};"
                 : "+f"(c[0]), "+f"(c[1]), "+f"(c[2]), "+f"(c[3])
                 : "r"(a[0]), "r"(a[1]), "r"(a[2]), "r"(a[3]), "r"(b0), "r"(b1));
}

// ---------------- conversions ----------------
__global__ void __launch_bounds__(256) convert_f16(const float* __restrict__ src,
                                                   __half* __restrict__ dst, int n4) {
    int i = blockIdx.x * 256 + threadIdx.x;
    if (i >= n4) return;
    float4 v = ((const float4*)src)[i];
    __half2* D = (__half2*)dst;
    D[2 * i]     = __floats2half2_rn(v.x, v.y);
    D[2 * i + 1] = __floats2half2_rn(v.z, v.w);
}

// all 5 weight matrices in one launch; grid (256, 5), n4 = 65536 each
__global__ void __launch_bounds__(256) convert_w5(
    const float* __restrict__ s0, const float* __restrict__ s1,
    const float* __restrict__ s2, const float* __restrict__ s3,
    const float* __restrict__ s4,
    __half* __restrict__ d0, __half* __restrict__ d1, __half* __restrict__ d2,
    __half* __restrict__ d3, __half* __restrict__ d4) {
    const float* s; __half* d;
    switch (blockIdx.y) {
        case 0:  s = s0; d = d0; break;
        case 1:  s = s1; d = d1; break;
        case 2:  s = s2; d = d2; break;
        case 3:  s = s3; d = d3; break;
        default: s = s4; d = d4; break;
    }
    int i = blockIdx.x * 256 + threadIdx.x;
    float4 v = ((const float4*)s)[i];
    __half2* D = (__half2*)d;
    D[2 * i]     = __floats2half2_rn(v.x, v.y);
    D[2 * i + 1] = __floats2half2_rn(v.z, v.w);
}

__global__ void __launch_bounds__(128) pool_convert_kernel(const float* __restrict__ X,
                                                           __half* __restrict__ XH) {
    int row = blockIdx.x;
    int bt = row >> 7, c = row & 127;
    int tid = threadIdx.x;
    const float4* xr = (const float4*)(X + ((size_t)bt * Nn + (size_t)c * 8) * Dd);
    float4 s = make_float4(0.f, 0.f, 0.f, 0.f);
#pragma unroll
    for (int j = 0; j < 8; j++) {
        float4 v = xr[(size_t)j * (Dd / 4) + tid];
        s.x += v.x; s.y += v.y; s.z += v.z; s.w += v.w;
    }
    s.x *= 0.125f; s.y *= 0.125f; s.z *= 0.125f; s.w *= 0.125f;
    size_t o = (size_t)row * Dd + tid * 4;
    *(__half2*)(XH + o)     = __floats2half2_rn(s.x, s.y);
    *(__half2*)(XH + o + 2) = __floats2half2_rn(s.z, s.w);
}

__global__ void __launch_bounds__(1024) transpose_adp(const float* __restrict__ AP,
                                                      float* __restrict__ ADT) {
    __shared__ float tile[32][33];
    int n0 = blockIdx.x * 32, c0 = blockIdx.y * 32;
    int tx = threadIdx.x & 31, ty = threadIdx.x >> 5;
    tile[ty][tx] = AP[(size_t)(n0 + ty) * Cc + c0 + tx];
    __syncthreads();
    ADT[(size_t)(c0 + ty) * Nn + n0 + tx] = tile[tx][ty];
}

// ---------------- HMMA GEMM fp16: C = Ah.Bh + bias, K=512 ----------------
// 4-stage cp.async ring, ONE syncthreads per k-chunk.
#define ST_BYTES  20480
#define GEMM_SMEM (4 * ST_BYTES)
#define ROWB      80

__global__ void __launch_bounds__(256, 2)
gemm_f16(const __half* __restrict__ Ah, const __half* __restrict__ Bh,
         const float* __restrict__ bias0, const float* __restrict__ bias1,
         float* __restrict__ C, int Nout, __half* __restrict__ EVH) {
    extern __shared__ __align__(1024) char smem[];
    uint32_t sb = smem_u32(smem);
    const int tid = threadIdx.x;
    const int n0 = blockIdx.x * 128;
    const int m0 = blockIdx.y * 128;
    const int l = tid & 31, w = tid >> 5;
    const int wm = w & 3, wn = w >> 2;
    const float* bias = (n0 < 512) ? bias0 : bias1;
    const int nb = (n0 < 512) ? n0 : n0 - 512;

    float acc[2][8][4];
#pragma unroll
    for (int i = 0; i < 2; i++)
#pragma unroll
        for (int j = 0; j < 8; j++)
#pragma unroll
            for (int k = 0; k < 4; k++) acc[i][j][k] = 0.f;

    auto load_stage = [&](int slot, int kc) {
        int kt = kc * 32;
        uint32_t base = sb + (uint32_t)(slot * ST_BYTES);
#pragma unroll
        for (int it = 0; it < 4; ++it) {
            int idx = tid + it * 256;
            int half = idx >> 9;
            int r = (idx >> 2) & 127, ch = idx & 3;
            uint32_t d = base + (uint32_t)(half * 10240 + r * ROWB + ch * 16);
            const __half* src = half ? (Bh + (size_t)(n0 + r) * Dd + kt + ch * 8)
                                     : (Ah + (size_t)(m0 + r) * Dd + kt + ch * 8);
            CP_ASYNC16(d, src);
        }
    };

    load_stage(0, 0); CP_COMMIT();
    load_stage(1, 1); CP_COMMIT();
    load_stage(2, 2); CP_COMMIT();

    const uint32_t lrow = (uint32_t)(l & 15) * ROWB + (uint32_t)(l >> 4) * 16;

    for (int c = 0; c < 16; ++c) {
        CP_WAIT2();
        __syncthreads();
        // slot (c+3)&3 was last read at iteration c-1; the sync above ordered that.
        if (c + 3 < 16) { load_stage((c + 3) & 3, c + 3); }
        CP_COMMIT();

        uint32_t stb = sb + (uint32_t)((c & 3) * ST_BYTES);
#pragma unroll
        for (int kk = 0; kk < 2; ++kk) {
            uint32_t aoff = stb + (uint32_t)(wm * 32) * ROWB + lrow + kk * 32;
            uint32_t boff = stb + 10240 + (uint32_t)(wn * 64) * ROWB + lrow + kk * 32;
            uint32_t a[2][4], b[4][4];
            LDSM4(a[0], aoff);
            LDSM4(a[1], aoff + 16 * ROWB);
#pragma unroll
            for (int fp = 0; fp < 4; ++fp) LDSM4(b[fp], boff + fp * 16 * ROWB);
#pragma unroll
            for (int fm = 0; fm < 2; ++fm)
#pragma unroll
                for (int fp = 0; fp < 4; ++fp) {
                    mma16816(acc[fm][2 * fp],     a[fm], b[fp][0], b[fp][2]);
                    mma16816(acc[fm][2 * fp + 1], a[fm], b[fp][1], b[fp][3]);
                }
        }
    }

#pragma unroll
    for (int fm = 0; fm < 2; ++fm) {
        int mrow = m0 + wm * 32 + fm * 16 + (l >> 2);
#pragma unroll
        for (int fn = 0; fn < 8; ++fn) {
            int nc = wn * 64 + fn * 8 + (l & 3) * 2;
            float b0 = bias[nb + nc], b1 = bias[nb + nc + 1];
            float2 o0, o1;
            o0.x = acc[fm][fn][0] + b0; o0.y = acc[fm][fn][1] + b1;
            o1.x = acc[fm][fn][2] + b0; o1.y = acc[fm][fn][3] + b1;
            *(float2*)(C + (size_t)mrow * Nout + n0 + nc)       = o0;
            *(float2*)(C + (size_t)(mrow + 8) * Nout + n0 + nc) = o1;
            if (EVH != nullptr && n0 >= 512) {
                *(__half2*)(EVH + (size_t)mrow * 512 + (n0 - 512) + nc) =
                    __floats2half2_rn(o0.x, o0.y);
                *(__half2*)(EVH + (size_t)(mrow + 8) * 512 + (n0 - 512) + nc) =
                    __floats2half2_rn(o1.x, o1.y);
            }
        }
    }
}

// ---------------- attention: 512 threads, query split across 4 threads ----------
// quarter skew: KQ_W mod 32 == 8 -> subs hit banks b, b+8, b+16, b+24 (no conflict)
#define KQ_W      2056
#define ATTN_SMEM (8 * KQ_W * 4)     // 65792

__global__ void __launch_bounds__(512, 2) attn_kernel(const float* __restrict__ QE,
                                                      const float* __restrict__ KV,
                                                      const float* __restrict__ ADT,
                                                      float* __restrict__ OUT) {
    extern __shared__ float sh[];
    float* khs = sh;                 // 4 quarters x KQ_W floats
    float* vhs = sh + 4 * KQ_W;
    int g  = blockIdx.x;
    int nt = blockIdx.y;             // 8 tiles of 128 queries
    int bt = g >> 3, hh = g & 7;
    int tid = threadIdx.x;
    int n0 = nt * 128;

    for (int i = tid; i < Cc * hd; i += 512) {
        int c = i >> 6, dd = i & 63;
        int qt = dd >> 4, d = dd & 15;
        int dst = qt * KQ_W + c * 16 + d;
        size_t src = ((size_t)bt * Cc + c) * 1024 + hh * hd + dd;
        khs[dst] = KV[src];
        vhs[dst] = KV[src + 512];
    }
    __syncthreads();

    int qid = tid >> 2, sub = tid & 3;
    int n = n0 + qid;
    u64t q2[8];
    {
        const float4* qp = (const float4*)(QE + ((size_t)bt * Nn + n) * 1024 + hh * hd + sub * 16);
#pragma unroll
        for (int t = 0; t < 4; t++) {
            float4 v = qp[t];
            q2[2 * t]     = pack2(v.x, v.y);
            q2[2 * t + 1] = pack2(v.z, v.w);
        }
    }
    u64t o2[8];
#pragma unroll
    for (int i = 0; i < 8; i++) o2[i] = 0ull;
    float m = -INFINITY, lsum = 0.f;
    const float* kbase = khs + sub * KQ_W;
    const float* vbase = vhs + sub * KQ_W;
    float adp_c = ADT[n];

    for (int c = 0; c < Cc; c++) {
        float adp_n = (c < Cc - 1) ? ADT[(size_t)(c + 1) * Nn + n] : 0.f;
        const ulonglong2* kr = (const ulonglong2*)(kbase + c * 16);
        u64t a0 = 0ull, a1 = 0ull;
#pragma unroll
        for (int t = 0; t < 4; t++) {
            ulonglong2 kk = kr[t];
            a0 = fma2(q2[2 * t],     kk.x, a0);
            a1 = fma2(q2[2 * t + 1], kk.y, a1);
        }
        float2 fa = unpack2(a0), fb = unpack2(a1);
        float sp = (fa.x + fa.y) + (fb.x + fb.y);
        sp += __shfl_xor_sync(0xffffffffu, sp, 1);
        sp += __shfl_xor_sync(0xffffffffu, sp, 2);
        float s = sp * 0.125f + adp_c;
        float p;
        if (s > m) {
            float sc = __expf(m - s);   // 0 on first iteration
            m = s;
            lsum *= sc;
            u64t ss = pack2(sc, sc);
#pragma unroll
            for (int i = 0; i < 8; i++) o2[i] = mul2(ss, o2[i]);
            p = 1.f;
        } else {
            p = __expf(s - m);
        }
        lsum += p;
        u64t pp = pack2(p, p);
        const ulonglong2* vr = (const ulonglong2*)(vbase + c * 16);
#pragma unroll
        for (int t = 0; t < 4; t++) {
            ulonglong2 vv = vr[t];
            o2[2 * t]     = fma2(pp, vv.x, o2[2 * t]);
            o2[2 * t + 1] = fma2(pp, vv.y, o2[2 * t + 1]);
        }
        adp_c = adp_n;
    }
    float inv = 1.f / lsum;
    u64t ii = pack2(inv, inv);
    float4* op = (float4*)(OUT + ((size_t)bt * Nn + n) * Dd + hh * hd + sub * 16);
#pragma unroll
    for (int t = 0; t < 4; t++) {
        float2 p0 = unpack2(mul2(o2[2 * t], ii));
        float2 p1 = unpack2(mul2(o2[2 * t + 1], ii));
        float4 v; v.x = p0.x; v.y = p0.y; v.z = p1.x; v.w = p1.y;
        op[t] = v;
    }
}

// ---------------- external branch, tensor-core version ----------------
#define EPITCH 144   // smem row pitch (bytes): 64 halfs data + pad

__global__ void __launch_bounds__(256) e1_gemm(const __half* __restrict__ EVH,
                                               const float* __restrict__ U1,
                                               __half* __restrict__ EXP1) {
    __shared__ __align__(16) char sm[128 * EPITCH + 64 * EPITCH];
    uint32_t sb = smem_u32(sm);
    int nt = blockIdx.x, g = blockIdx.y;
    int bt = g >> 3, h = g & 7;
    int tid = threadIdx.x;

#pragma unroll
    for (int it = 0; it < 4; ++it) {
        int idx = tid + it * 256;
        int r = idx >> 3, ch = idx & 7;
        uint32_t d = sb + (uint32_t)(r * EPITCH + ch * 16);
        CP_ASYNC16(d, EVH + ((size_t)(bt * Nn + nt * 128 + r) * 512 + h * hd + ch * 8));
    }
    CP_COMMIT();
    char* Bsm = sm + 128 * EPITCH;
    for (int i = tid; i < 64 * 64; i += 256) {
        int s = i >> 6, d = i & 63;
        float v = (s < Ss) ? U1[d * Ss + s] : 0.f;
        *(__half*)(Bsm + s * EPITCH + d * 2) = __float2half_rn(v);
    }
    CP_WAIT0();
    __syncthreads();

    int l = tid & 31, w = tid >> 5;
    int wm = w & 3, wn = w >> 2;
    float acc[2][4][4];
#pragma unroll
    for (int i = 0; i < 2; i++)
#pragma unroll
        for (int j = 0; j < 4; j++)
#pragma unroll
            for (int k = 0; k < 4; k++) acc[i][j][k] = 0.f;

    uint32_t lrow = (uint32_t)(l & 15) * EPITCH + (uint32_t)(l >> 4) * 16;
    uint32_t Abase = sb + (uint32_t)(wm * 32) * EPITCH;
    uint32_t Bbase = sb + 128 * EPITCH + (uint32_t)(wn * 32) * EPITCH;
#pragma unroll
    for (int k = 0; k < 4; ++k) {
        uint32_t a0[4], a1[4], b0[4], b1[4];
        LDSM4(a0, Abase + lrow + k * 32);
        LDSM4(a1, Abase + 16 * EPITCH + lrow + k * 32);
        LDSM4(b0, Bbase + lrow + k * 32);
        LDSM4(b1, Bbase + 16 * EPITCH + lrow + k * 32);
#pragma unroll
        for (int fm = 0; fm < 2; ++fm) {
            uint32_t* a = fm ? a1 : a0;
            mma16816(acc[fm][0], a, b0[0], b0[2]);
            mma16816(acc[fm][1], a, b0[1], b0[3]);
            mma16816(acc[fm][2], a, b1[0], b1[2]);
            mma16816(acc[fm][3], a, b1[1], b1[3]);
        }
    }
    int baseN = nt * 128 + wm * 32 + (l >> 2);
#pragma unroll
    for (int fm = 0; fm < 2; ++fm) {
        int n = baseN + fm * 16;
#pragma unroll
        for (int fn = 0; fn < 4; ++fn) {
            int s = wn * 32 + fn * 8 + (l & 3) * 2;
            bool ok = (s < Ss);
            float v0 = ok ? __expf(fminf(acc[fm][fn][0], 11.f)) : 0.f;
            float v1 = ok ? __expf(fminf(acc[fm][fn][1], 11.f)) : 0.f;
            float v2 = ok ? __expf(fminf(acc[fm][fn][2], 11.f)) : 0.f;
            float v3 = ok ? __expf(fminf(acc[fm][fn][3], 11.f)) : 0.f;
            *(__half2*)(EXP1 + ((size_t)g * Nn + n) * 64 + s)     = __floats2half2_rn(v0, v1);
            *(__half2*)(EXP1 + ((size_t)g * Nn + n + 8) * 64 + s) = __floats2half2_rn(v2, v3);
        }
    }
}

__global__ void __launch_bounds__(256) colsum_kernel(const __half* __restrict__ EXP1,
                                                     float* __restrict__ CL) {
    __shared__ float red[4][64];
    int g = blockIdx.x;
    int tid = threadIdx.x;
    int s = tid & 63, lane = tid >> 6;
    float sum = 0.f;
    const __half* base = EXP1 + (size_t)g * Nn * 64 + s;
    for (int n = lane; n < Nn; n += 4)
        sum += __half2float(base[(size_t)n * 64]);
    red[lane][s] = sum;
    __syncthreads();
    if (tid < 64) {
        float t = red[0][tid] + red[1][tid] + red[2][tid] + red[3][tid];
        CL[g * 64 + tid] = 0.5f / fmaxf(t, 1e-30f);
    }
}

__global__ void __launch_bounds__(256) apply_gemm(const __half* __restrict__ EXP1,
                                                  const float* __restrict__ U2,
                                                  const float* __restrict__ CL,
                                                  const float* __restrict__ QE,
                                                  const float* __restrict__ OUT,
                                                  __half* __restrict__ OH) {
    __shared__ __align__(16) char sm[128 * EPITCH + 64 * EPITCH];
    __shared__ float rls[64];
    uint32_t sb = smem_u32(sm);
    int nt = blockIdx.x, g = blockIdx.y;
    int bt = g >> 3, h = g & 7;
    int tid = threadIdx.x;

#pragma unroll
    for (int it = 0; it < 4; ++it) {
        int idx = tid + it * 256;
        int r = idx >> 3, ch = idx & 7;
        uint32_t d = sb + (uint32_t)(r * EPITCH + ch * 16);
        CP_ASYNC16(d, EXP1 + ((size_t)g * Nn + nt * 128 + r) * 64 + ch * 8);
    }
    CP_COMMIT();
    if (tid < 64) rls[tid] = CL[g * 64 + tid];
    __syncthreads();
    char* Bsm = sm + 128 * EPITCH;
    for (int i = tid; i < 64 * 64; i += 256) {
        int d = i >> 6, s = i & 63;
        float v = (s < Ss) ? U2[s * hd + d] * rls[s] : 0.f;
        *(__half*)(Bsm + d * EPITCH + s * 2) = __float2half_rn(v);
    }
    CP_WAIT0();
    __syncthreads();

    int l = tid & 31, w = tid >> 5;
    int wm = w & 3, wn = w >> 2;
    float acc[2][4][4];
#pragma unroll
    for (int i = 0; i < 2; i++)
#pragma unroll
        for (int j = 0; j < 4; j++)
#pragma unroll
            for (int k = 0; k < 4; k++) acc[i][j][k] = 0.f;

    uint32_t lrow = (uint32_t)(l & 15) * EPITCH + (uint32_t)(l >> 4) * 16;
    uint32_t Abase = sb + (uint32_t)(wm * 32) * EPITCH;
    uint32_t Bbase = sb + 128 * EPITCH + (uint32_t)(wn * 32) * EPITCH;
#pragma unroll
    for (int k = 0; k < 4; ++k) {
        uint32_t a0[4], a1[4], b0[4], b1[4];
        LDSM4(a0, Abase + lrow + k * 32);
        LDSM4(a1, Abase + 16 * EPITCH + lrow + k * 32);
        LDSM4(b0, Bbase + lrow + k * 32);
        LDSM4(b1, Bbase + 16 * EPITCH + lrow + k * 32);
#pragma unroll
        for (int fm = 0; fm < 2; ++fm) {
            uint32_t* a = fm ? a1 : a0;
            mma16816(acc[fm][0], a, b0[0], b0[2]);
            mma16816(acc[fm][1], a, b0[1], b0[3]);
            mma16816(acc[fm][2], a, b1[0], b1[2]);
            mma16816(acc[fm][3], a, b1[1], b1[3]);
        }
    }
    int baseN = nt * 128 + wm * 32 + (l >> 2);
#pragma unroll
    for (int fm = 0; fm < 2; ++fm) {
        int n = baseN + fm * 16;
#pragma unroll
        for (int fn = 0; fn < 4; ++fn) {
            int d = wn * 32 + fn * 8 + (l & 3) * 2;
            size_t m0i = (size_t)bt * Nn + n;
            size_t m1i = m0i + 8;
            float2 ov0 = *(const float2*)(OUT + m0i * Dd + h * hd + d);
            float2 ev0 = *(const float2*)(QE + m0i * 1024 + 512 + h * hd + d);
            float2 ov1 = *(const float2*)(OUT + m1i * Dd + h * hd + d);
            float2 ev1 = *(const float2*)(QE + m1i * 1024 + 512 + h * hd + d);
            *(__half2*)(OH + m0i * Dd + h * hd + d) =
                __floats2half2_rn(acc[fm][fn][0] + ov0.x + ev0.x,
                                  acc[fm][fn][1] + ov0.y + ev0.y);
            *(__half2*)(OH + m1i * Dd + h * hd + d) =
                __floats2half2_rn(acc[fm][fn][2] + ov1.x + ev1.x,
                                  acc[fm][fn][3] + ov1.y + ev1.y);
        }
    }
}

// ---------------- launch ----------------
extern "C" void kernel_launch(void* const* d_in, const int* in_sizes, int n_in,
                              void* d_out, int out_size) {
    const float* x   = (const float*)d_in[0];
    const float* Wq  = (const float*)d_in[1];
    const float* bq  = (const float*)d_in[2];
    const float* Wk  = (const float*)d_in[3];
    const float* bk  = (const float*)d_in[4];
    const float* Wv  = (const float*)d_in[5];
    const float* bv  = (const float*)d_in[6];
    const float* We  = (const float*)d_in[7];
    const float* be  = (const float*)d_in[8];
    const float* Wo  = (const float*)d_in[9];
    const float* bo  = (const float*)d_in[10];
    const float* adp = (const float*)d_in[11];
    const float* U1  = (const float*)d_in[12];
    const float* U2  = (const float*)d_in[13];
    float* out = (float*)d_out;

    float *QE, *KV, *OUT, *ADT, *CL;
    cudaGetSymbolAddress((void**)&QE,  g_QE);
    cudaGetSymbolAddress((void**)&KV,  g_KV);
    cudaGetSymbolAddress((void**)&OUT, g_OUT);
    cudaGetSymbolAddress((void**)&ADT, g_ADT);
    cudaGetSymbolAddress((void**)&CL,  g_CL);

    __half *xh, *xph, *oh, *wqeh, *wkvh, *woh, *evh, *EXP1;
    cudaGetSymbolAddress((void**)&xh,   g_xh);
    cudaGetSymbolAddress((void**)&xph,  g_xph);
    cudaGetSymbolAddress((void**)&oh,   g_oh);
    cudaGetSymbolAddress((void**)&wqeh, g_wqeh);
    cudaGetSymbolAddress((void**)&wkvh, g_wkvh);
    cudaGetSymbolAddress((void**)&woh,  g_woh);
    cudaGetSymbolAddress((void**)&evh,  g_evh);
    cudaGetSymbolAddress((void**)&EXP1, g_EXP1);

    cudaFuncSetAttribute(gemm_f16, cudaFuncAttributeMaxDynamicSharedMemorySize, GEMM_SMEM);
    cudaFuncSetAttribute(attn_kernel, cudaFuncAttributeMaxDynamicSharedMemorySize, ATTN_SMEM);

    const int WN = Dd * Dd;            // 262144

    // launch order: index 3 (QE GEMM) targeted for the ncu capture window
    convert_f16<<<(M_BIG * Dd / 4 + 255) / 256, 256>>>(x, xh, M_BIG * Dd / 4);          // 0
    convert_w5<<<dim3(256, 5), 256>>>(Wq, We, Wk, Wv, Wo,
                                      wqeh, wqeh + WN, wkvh, wkvh + WN, woh);           // 1
    pool_convert_kernel<<<M_POOL, 128>>>(x, xph);                                       // 2
    gemm_f16<<<dim3(8, M_BIG / 128), 256, GEMM_SMEM>>>(xh, wqeh, bq, be, QE, 1024, evh);// 3 <- profiled
    transpose_adp<<<dim3(32, 4), 1024>>>(adp, ADT);                                     // 4
    gemm_f16<<<dim3(8, M_POOL / 128), 256, GEMM_SMEM>>>(xph, wkvh, bk, bv, KV, 1024,
                                                        nullptr);                       // 5
    attn_kernel<<<dim3(Gg, 8), 512, ATTN_SMEM>>>(QE, KV, ADT, OUT);                     // 6
    e1_gemm<<<dim3(8, Gg), 256>>>(evh, U1, EXP1);                                       // 7
    colsum_kernel<<<Gg, 256>>>(EXP1, CL);                                               // 8
    apply_gemm<<<dim3(8, Gg), 256>>>(EXP1, U2, CL, QE, OUT, oh);                        // 9
    gemm_f16<<<dim3(4, M_BIG / 128), 256, GEMM_SMEM>>>(oh, woh, bo, bo, out, Dd,
                                                       nullptr);                        // 10
}

// round 12
// speedup vs baseline: 1.2260x; 1.2260x over previous
#include <cuda_runtime.h>
#include <cuda_fp16.h>
#include <math.h>
#include <stdint.h>

// ---------------- problem dims ----------------
#define Bb   4
#define Tt   12
#define Nn   1024
#define Dd   512
#define Hh   8
#define hd   64
#define Cc   128
#define Ss   60
#define BT   48            // Bb*Tt
#define M_BIG  49152       // BT*Nn
#define M_POOL 6144        // BT*Cc
#define Gg   384           // BT*Hh

// ---------------- device scratch (allocation-free) ----------------
__device__ float g_QE [M_BIG  * 1024];   // [m][0:512]=q, [512:1024]=ev (fp32)
__device__ float g_KV [M_POOL * 1024];   // [c][0:512]=k, [512:1024]=v
__device__ float g_OUT[M_BIG  * Dd];     // attention branch output (pre-Wo)
__device__ float g_ADT[Cc * Nn];         // adp_pos transposed [c][n]
__device__ float g_CL [Gg * 64];         // 0.5 / colsum  (s padded to 64)

__device__ __half g_EXP1[(size_t)Gg * Nn * 64];  // exp(e1), [g][n][64], s>=60 -> 0
__device__ __half g_evh [M_BIG  * Dd];   // ev half (fp16 copy from QE gemm epilogue)
__device__ __half g_xh  [M_BIG  * Dd];
__device__ __half g_xph [M_POOL * Dd];
__device__ __half g_oh  [M_BIG  * Dd];
__device__ __half g_wqeh[1024 * Dd];
__device__ __half g_wkvh[1024 * Dd];
__device__ __half g_woh [Dd * Dd];

// ---------------- helpers ----------------
typedef unsigned long long u64t;
__device__ __forceinline__ uint32_t smem_u32(const void* p) {
    uint32_t a;
    asm("{ .reg .u64 t; cvta.to.shared.u64 t, %1; cvt.u32.u64 %0, t; }" : "=r"(a) : "l"(p));
    return a;
}
__device__ __forceinline__ u64t fma2(u64t a, u64t b, u64t c) {
    u64t d; asm("fma.rn.f32x2 %0, %1, %2, %3;" : "=l"(d) : "l"(a), "l"(b), "l"(c)); return d;
}
__device__ __forceinline__ u64t mul2(u64t a, u64t b) {
    u64t d; asm("mul.rn.f32x2 %0, %1, %2;" : "=l"(d) : "l"(a), "l"(b)); return d;
}
__device__ __forceinline__ u64t pack2(float x, float y) {
    u64t d; asm("mov.b64 %0, {%1, %2};" : "=l"(d) : "f"(x), "f"(y)); return d;
}
__device__ __forceinline__ float2 unpack2(u64t v) {
    float2 r; asm("mov.b64 {%0, %1}, %2;" : "=f"(r.x), "=f"(r.y) : "l"(v)); return r;
}
#define CP_ASYNC16(dst, src) \
    asm volatile("cp.async.cg.shared.global [%0], [%1], 16;" :: "r"(dst), "l"(src) : "memory")
#define CP_COMMIT() asm volatile("cp.async.commit_group;" ::: "memory")
#define CP_WAIT2()  asm volatile("cp.async.wait_group 2;" ::: "memory")
#define CP_WAIT0()  asm volatile("cp.async.wait_group 0;" ::: "memory")
#define LDSM4(r, addr) \
    asm volatile("ldmatrix.sync.aligned.m8n8.x4.shared.b16 {%0,%1,%2,%3}, [%4];" \
        : "=r"((r)[0]), "=r"((r)[1]), "=r"((r)[2]), "=r"((r)[3]) : "r"(addr))
__device__ __forceinline__ void mma16816(float* c, const uint32_t* a,
                                         uint32_t b0, uint32_t b1) {
    asm volatile("mma.sync.aligned.m16n8k16.row.col.f32.f16.f16.f32 "
                 "{%0,%1,%2,%3}, {%4,%5,%6,%7}, {%8,%9}, {%0,%1,%2,%3};"
                 : "+f"(c[0]), "+f"(c[1]), "+f"(c[2]), "+f"(c[3])
                 : "r"(a[0]), "r"(a[1]), "r"(a[2]), "r"(a[3]), "r"(b0), "r"(b1));
}

// ---------------- conversions ----------------
__global__ void __launch_bounds__(256) convert_f16(const float* __restrict__ src,
                                                   __half* __restrict__ dst, int n4) {
    int i = blockIdx.x * 256 + threadIdx.x;
    if (i >= n4) return;
    float4 v = ((const float4*)src)[i];
    __half2* D = (__half2*)dst;
    D[2 * i]     = __floats2half2_rn(v.x, v.y);
    D[2 * i + 1] = __floats2half2_rn(v.z, v.w);
}

// all 5 weight matrices in one launch; grid (256, 5)
__global__ void __launch_bounds__(256) convert_w5(
    const float* __restrict__ s0, const float* __restrict__ s1,
    const float* __restrict__ s2, const float* __restrict__ s3,
    const float* __restrict__ s4,
    __half* __restrict__ d0, __half* __restrict__ d1, __half* __restrict__ d2,
    __half* __restrict__ d3, __half* __restrict__ d4) {
    const float* s; __half* d;
    switch (blockIdx.y) {
        case 0:  s = s0; d = d0; break;
        case 1:  s = s1; d = d1; break;
        case 2:  s = s2; d = d2; break;
        case 3:  s = s3; d = d3; break;
        default: s = s4; d = d4; break;
    }
    int i = blockIdx.x * 256 + threadIdx.x;
    float4 v = ((const float4*)s)[i];
    __half2* D = (__half2*)d;
    D[2 * i]     = __floats2half2_rn(v.x, v.y);
    D[2 * i + 1] = __floats2half2_rn(v.z, v.w);
}

__global__ void __launch_bounds__(128) pool_convert_kernel(const float* __restrict__ X,
                                                           __half* __restrict__ XH) {
    int row = blockIdx.x;
    int bt = row >> 7, c = row & 127;
    int tid = threadIdx.x;
    const float4* xr = (const float4*)(X + ((size_t)bt * Nn + (size_t)c * 8) * Dd);
    float4 s = make_float4(0.f, 0.f, 0.f, 0.f);
#pragma unroll
    for (int j = 0; j < 8; j++) {
        float4 v = xr[(size_t)j * (Dd / 4) + tid];
        s.x += v.x; s.y += v.y; s.z += v.z; s.w += v.w;
    }
    s.x *= 0.125f; s.y *= 0.125f; s.z *= 0.125f; s.w *= 0.125f;
    size_t o = (size_t)row * Dd + tid * 4;
    *(__half2*)(XH + o)     = __floats2half2_rn(s.x, s.y);
    *(__half2*)(XH + o + 2) = __floats2half2_rn(s.z, s.w);
}

__global__ void __launch_bounds__(1024) transpose_adp(const float* __restrict__ AP,
                                                      float* __restrict__ ADT) {
    __shared__ float tile[32][33];
    int n0 = blockIdx.x * 32, c0 = blockIdx.y * 32;
    int tx = threadIdx.x & 31, ty = threadIdx.x >> 5;
    tile[ty][tx] = AP[(size_t)(n0 + ty) * Cc + c0 + tx];
    __syncthreads();
    ADT[(size_t)(c0 + ty) * Nn + n0 + tx] = tile[tx][ty];
}

// ---------------- HMMA GEMM fp16: C = Ah.Bh + bias, K=512 ----------------
// 4-stage cp.async ring, ONE syncthreads per k-chunk.
#define ST_BYTES  20480
#define GEMM_SMEM (4 * ST_BYTES)
#define ROWB      80

__global__ void __launch_bounds__(256, 2)
gemm_f16(const __half* __restrict__ Ah, const __half* __restrict__ Bh,
         const float* __restrict__ bias0, const float* __restrict__ bias1,
         float* __restrict__ C, int Nout, __half* __restrict__ EVH) {
    extern __shared__ __align__(1024) char smem[];
    uint32_t sb = smem_u32(smem);
    const int tid = threadIdx.x;
    const int n0 = blockIdx.x * 128;
    const int m0 = blockIdx.y * 128;
    const int l = tid & 31, w = tid >> 5;
    const int wm = w & 3, wn = w >> 2;
    const float* bias = (n0 < 512) ? bias0 : bias1;
    const int nb = (n0 < 512) ? n0 : n0 - 512;

    float acc[2][8][4];
#pragma unroll
    for (int i = 0; i < 2; i++)
#pragma unroll
        for (int j = 0; j < 8; j++)
#pragma unroll
            for (int k = 0; k < 4; k++) acc[i][j][k] = 0.f;

    auto load_stage = [&](int slot, int kc) {
        int kt = kc * 32;
        uint32_t base = sb + (uint32_t)(slot * ST_BYTES);
#pragma unroll
        for (int it = 0; it < 4; ++it) {
            int idx = tid + it * 256;
            int half = idx >> 9;
            int r = (idx >> 2) & 127, ch = idx & 3;
            uint32_t d = base + (uint32_t)(half * 10240 + r * ROWB + ch * 16);
            const __half* src = half ? (Bh + (size_t)(n0 + r) * Dd + kt + ch * 8)
                                     : (Ah + (size_t)(m0 + r) * Dd + kt + ch * 8);
            CP_ASYNC16(d, src);
        }
    };

    load_stage(0, 0); CP_COMMIT();
    load_stage(1, 1); CP_COMMIT();
    load_stage(2, 2); CP_COMMIT();

    const uint32_t lrow = (uint32_t)(l & 15) * ROWB + (uint32_t)(l >> 4) * 16;

    for (int c = 0; c < 16; ++c) {
        CP_WAIT2();
        __syncthreads();
        // slot (c+3)&3 was last read at iteration c-1; the sync above ordered that.
        if (c + 3 < 16) { load_stage((c + 3) & 3, c + 3); }
        CP_COMMIT();

        uint32_t stb = sb + (uint32_t)((c & 3) * ST_BYTES);
#pragma unroll
        for (int kk = 0; kk < 2; ++kk) {
            uint32_t aoff = stb + (uint32_t)(wm * 32) * ROWB + lrow + kk * 32;
            uint32_t boff = stb + 10240 + (uint32_t)(wn * 64) * ROWB + lrow + kk * 32;
            uint32_t a[2][4], b[4][4];
            LDSM4(a[0], aoff);
            LDSM4(a[1], aoff + 16 * ROWB);
#pragma unroll
            for (int fp = 0; fp < 4; ++fp) LDSM4(b[fp], boff + fp * 16 * ROWB);
#pragma unroll
            for (int fm = 0; fm < 2; ++fm)
#pragma unroll
                for (int fp = 0; fp < 4; ++fp) {
                    mma16816(acc[fm][2 * fp],     a[fm], b[fp][0], b[fp][2]);
                    mma16816(acc[fm][2 * fp + 1], a[fm], b[fp][1], b[fp][3]);
                }
        }
    }

#pragma unroll
    for (int fm = 0; fm < 2; ++fm) {
        int mrow = m0 + wm * 32 + fm * 16 + (l >> 2);
#pragma unroll
        for (int fn = 0; fn < 8; ++fn) {
            int nc = wn * 64 + fn * 8 + (l & 3) * 2;
            float b0 = bias[nb + nc], b1 = bias[nb + nc + 1];
            float2 o0, o1;
            o0.x = acc[fm][fn][0] + b0; o0.y = acc[fm][fn][1] + b1;
            o1.x = acc[fm][fn][2] + b0; o1.y = acc[fm][fn][3] + b1;
            *(float2*)(C + (size_t)mrow * Nout + n0 + nc)       = o0;
            *(float2*)(C + (size_t)(mrow + 8) * Nout + n0 + nc) = o1;
            if (EVH != nullptr && n0 >= 512) {
                *(__half2*)(EVH + (size_t)mrow * 512 + (n0 - 512) + nc) =
                    __floats2half2_rn(o0.x, o0.y);
                *(__half2*)(EVH + (size_t)(mrow + 8) * 512 + (n0 - 512) + nc) =
                    __floats2half2_rn(o1.x, o1.y);
            }
        }
    }
}

// ---------------- attention: 512 threads, query split across thread pairs ----------
// (round-10 verified version)
#define KHALF_W   4112
#define ATTN_SMEM (2 * 16448 * 2)

__global__ void __launch_bounds__(512, 1) attn_kernel(const float* __restrict__ QE,
                                                      const float* __restrict__ KV,
                                                      const float* __restrict__ ADT,
                                                      float* __restrict__ OUT) {
    extern __shared__ float sh[];
    float* khs = sh;
    float* vhs = sh + 2 * KHALF_W;
    int g  = blockIdx.x;
    int nt = blockIdx.y;
    int bt = g >> 3, hh = g & 7;
    int tid = threadIdx.x;
    int n0 = nt * 256;

    for (int i = tid; i < Cc * hd; i += 512) {
        int c = i >> 6, dd = i & 63;
        int hf = dd >> 5, d = dd & 31;
        int dst = hf * KHALF_W + c * 32 + d;
        size_t src = ((size_t)bt * Cc + c) * 1024 + hh * hd + dd;
        khs[dst] = KV[src];
        vhs[dst] = KV[src + 512];
    }
    __syncthreads();

    int q = tid >> 1, half = tid & 1;
    int n = n0 + q;
    u64t q2[16];
    {
        const float4* qp = (const float4*)(QE + ((size_t)bt * Nn + n) * 1024 + hh * hd + half * 32);
#pragma unroll
        for (int t = 0; t < 8; t++) {
            float4 v = qp[t];
            q2[2 * t]     = pack2(v.x, v.y);
            q2[2 * t + 1] = pack2(v.z, v.w);
        }
    }
    u64t o2[16];
#pragma unroll
    for (int i = 0; i < 16; i++) o2[i] = 0ull;
    float m = -INFINITY, lsum = 0.f;
    const float* kbase = khs + half * KHALF_W;
    const float* vbase = vhs + half * KHALF_W;
    float adp_c = ADT[n];

    for (int c = 0; c < Cc; c++) {
        float adp_n = (c < Cc - 1) ? ADT[(size_t)(c + 1) * Nn + n] : 0.f;
        const ulonglong2* kr = (const ulonglong2*)(kbase + c * 32);
        u64t a0 = 0ull, a1 = 0ull;
#pragma unroll
        for (int t = 0; t < 8; t++) {
            ulonglong2 kk = kr[t];
            a0 = fma2(q2[2 * t],     kk.x, a0);
            a1 = fma2(q2[2 * t + 1], kk.y, a1);
        }
        float2 fa = unpack2(a0), fb = unpack2(a1);
        float sp = (fa.x + fa.y) + (fb.x + fb.y);
        sp += __shfl_xor_sync(0xffffffffu, sp, 1);
        float s = sp * 0.125f + adp_c;
        float p;
        if (s > m) {
            float sc = __expf(m - s);
            m = s;
            lsum *= sc;
            u64t ss = pack2(sc, sc);
#pragma unroll
            for (int i = 0; i < 16; i++) o2[i] = mul2(ss, o2[i]);
            p = 1.f;
        } else {
            p = __expf(s - m);
        }
        lsum += p;
        u64t pp = pack2(p, p);
        const ulonglong2* vr = (const ulonglong2*)(vbase + c * 32);
#pragma unroll
        for (int t = 0; t < 8; t++) {
            ulonglong2 vv = vr[t];
            o2[2 * t]     = fma2(pp, vv.x, o2[2 * t]);
            o2[2 * t + 1] = fma2(pp, vv.y, o2[2 * t + 1]);
        }
        adp_c = adp_n;
    }
    float inv = 1.f / lsum;
    u64t ii = pack2(inv, inv);
    float4* op = (float4*)(OUT + ((size_t)bt * Nn + n) * Dd + hh * hd + half * 32);
#pragma unroll
    for (int t = 0; t < 8; t++) {
        float2 p0 = unpack2(mul2(o2[2 * t], ii));
        float2 p1 = unpack2(mul2(o2[2 * t + 1], ii));
        float4 v; v.x = p0.x; v.y = p0.y; v.z = p1.x; v.w = p1.y;
        op[t] = v;
    }
}

// ---------------- external branch, tensor-core version ----------------
#define EPITCH 144   // smem row pitch (bytes): 64 halfs data + pad

__global__ void __launch_bounds__(256) e1_gemm(const __half* __restrict__ EVH,
                                               const float* __restrict__ U1,
                                               __half* __restrict__ EXP1) {
    __shared__ __align__(16) char sm[128 * EPITCH + 64 * EPITCH];
    uint32_t sb = smem_u32(sm);
    int nt = blockIdx.x, g = blockIdx.y;
    int bt = g >> 3, h = g & 7;
    int tid = threadIdx.x;

#pragma unroll
    for (int it = 0; it < 4; ++it) {
        int idx = tid + it * 256;
        int r = idx >> 3, ch = idx & 7;
        uint32_t d = sb + (uint32_t)(r * EPITCH + ch * 16);
        CP_ASYNC16(d, EVH + ((size_t)(bt * Nn + nt * 128 + r) * 512 + h * hd + ch * 8));
    }
    CP_COMMIT();
    char* Bsm = sm + 128 * EPITCH;
    for (int i = tid; i < 64 * 64; i += 256) {
        int s = i >> 6, d = i & 63;
        float v = (s < Ss) ? U1[d * Ss + s] : 0.f;
        *(__half*)(Bsm + s * EPITCH + d * 2) = __float2half_rn(v);
    }
    CP_WAIT0();
    __syncthreads();

    int l = tid & 31, w = tid >> 5;
    int wm = w & 3, wn = w >> 2;
    float acc[2][4][4];
#pragma unroll
    for (int i = 0; i < 2; i++)
#pragma unroll
        for (int j = 0; j < 4; j++)
#pragma unroll
            for (int k = 0; k < 4; k++) acc[i][j][k] = 0.f;

    uint32_t lrow = (uint32_t)(l & 15) * EPITCH + (uint32_t)(l >> 4) * 16;
    uint32_t Abase = sb + (uint32_t)(wm * 32) * EPITCH;
    uint32_t Bbase = sb + 128 * EPITCH + (uint32_t)(wn * 32) * EPITCH;
#pragma unroll
    for (int k = 0; k < 4; ++k) {
        uint32_t a0[4], a1[4], b0[4], b1[4];
        LDSM4(a0, Abase + lrow + k * 32);
        LDSM4(a1, Abase + 16 * EPITCH + lrow + k * 32);
        LDSM4(b0, Bbase + lrow + k * 32);
        LDSM4(b1, Bbase + 16 * EPITCH + lrow + k * 32);
#pragma unroll
        for (int fm = 0; fm < 2; ++fm) {
            uint32_t* a = fm ? a1 : a0;
            mma16816(acc[fm][0], a, b0[0], b0[2]);
            mma16816(acc[fm][1], a, b0[1], b0[3]);
            mma16816(acc[fm][2], a, b1[0], b1[2]);
            mma16816(acc[fm][3], a, b1[1], b1[3]);
        }
    }
    int baseN = nt * 128 + wm * 32 + (l >> 2);
#pragma unroll
    for (int fm = 0; fm < 2; ++fm) {
        int n = baseN + fm * 16;
#pragma unroll
        for (int fn = 0; fn < 4; ++fn) {
            int s = wn * 32 + fn * 8 + (l & 3) * 2;
            bool ok = (s < Ss);
            float v0 = ok ? __expf(fminf(acc[fm][fn][0], 11.f)) : 0.f;
            float v1 = ok ? __expf(fminf(acc[fm][fn][1], 11.f)) : 0.f;
            float v2 = ok ? __expf(fminf(acc[fm][fn][2], 11.f)) : 0.f;
            float v3 = ok ? __expf(fminf(acc[fm][fn][3], 11.f)) : 0.f;
            *(__half2*)(EXP1 + ((size_t)g * Nn + n) * 64 + s)     = __floats2half2_rn(v0, v1);
            *(__half2*)(EXP1 + ((size_t)g * Nn + n + 8) * 64 + s) = __floats2half2_rn(v2, v3);
        }
    }
}

__global__ void __launch_bounds__(256) colsum_kernel(const __half* __restrict__ EXP1,
                                                     float* __restrict__ CL) {
    __shared__ float red[4][64];
    int g = blockIdx.x;
    int tid = threadIdx.x;
    int s = tid & 63, lane = tid >> 6;
    float sum = 0.f;
    const __half* base = EXP1 + (size_t)g * Nn * 64 + s;
    for (int n = lane; n < Nn; n += 4)
        sum += __half2float(base[(size_t)n * 64]);
    red[lane][s] = sum;
    __syncthreads();
    if (tid < 64) {
        float t = red[0][tid] + red[1][tid] + red[2][tid] + red[3][tid];
        CL[g * 64 + tid] = 0.5f / fmaxf(t, 1e-30f);
    }
}

__global__ void __launch_bounds__(256) apply_gemm(const __half* __restrict__ EXP1,
                                                  const float* __restrict__ U2,
                                                  const float* __restrict__ CL,
                                                  const float* __restrict__ QE,
                                                  const float* __restrict__ OUT,
                                                  __half* __restrict__ OH) {
    __shared__ __align__(16) char sm[128 * EPITCH + 64 * EPITCH];
    __shared__ float rls[64];
    uint32_t sb = smem_u32(sm);
    int nt = blockIdx.x, g = blockIdx.y;
    int bt = g >> 3, h = g & 7;
    int tid = threadIdx.x;

#pragma unroll
    for (int it = 0; it < 4; ++it) {
        int idx = tid + it * 256;
        int r = idx >> 3, ch = idx & 7;
        uint32_t d = sb + (uint32_t)(r * EPITCH + ch * 16);
        CP_ASYNC16(d, EXP1 + ((size_t)g * Nn + nt * 128 + r) * 64 + ch * 8);
    }
    CP_COMMIT();
    if (tid < 64) rls[tid] = CL[g * 64 + tid];
    __syncthreads();
    char* Bsm = sm + 128 * EPITCH;
    for (int i = tid; i < 64 * 64; i += 256) {
        int d = i >> 6, s = i & 63;
        float v = (s < Ss) ? U2[s * hd + d] * rls[s] : 0.f;
        *(__half*)(Bsm + d * EPITCH + s * 2) = __float2half_rn(v);
    }
    CP_WAIT0();
    __syncthreads();

    int l = tid & 31, w = tid >> 5;
    int wm = w & 3, wn = w >> 2;
    float acc[2][4][4];
#pragma unroll
    for (int i = 0; i < 2; i++)
#pragma unroll
        for (int j = 0; j < 4; j++)
#pragma unroll
            for (int k = 0; k < 4; k++) acc[i][j][k] = 0.f;

    uint32_t lrow = (uint32_t)(l & 15) * EPITCH + (uint32_t)(l >> 4) * 16;
    uint32_t Abase = sb + (uint32_t)(wm * 32) * EPITCH;
    uint32_t Bbase = sb + 128 * EPITCH + (uint32_t)(wn * 32) * EPITCH;
#pragma unroll
    for (int k = 0; k < 4; ++k) {
        uint32_t a0[4], a1[4], b0[4], b1[4];
        LDSM4(a0, Abase + lrow + k * 32);
        LDSM4(a1, Abase + 16 * EPITCH + lrow + k * 32);
        LDSM4(b0, Bbase + lrow + k * 32);
        LDSM4(b1, Bbase + 16 * EPITCH + lrow + k * 32);
#pragma unroll
        for (int fm = 0; fm < 2; ++fm) {
            uint32_t* a = fm ? a1 : a0;
            mma16816(acc[fm][0], a, b0[0], b0[2]);
            mma16816(acc[fm][1], a, b0[1], b0[3]);
            mma16816(acc[fm][2], a, b1[0], b1[2]);
            mma16816(acc[fm][3], a, b1[1], b1[3]);
        }
    }
    int baseN = nt * 128 + wm * 32 + (l >> 2);
#pragma unroll
    for (int fm = 0; fm < 2; ++fm) {
        int n = baseN + fm * 16;
#pragma unroll
        for (int fn = 0; fn < 4; ++fn) {
            int d = wn * 32 + fn * 8 + (l & 3) * 2;
            size_t m0i = (size_t)bt * Nn + n;
            size_t m1i = m0i + 8;
            float2 ov0 = *(const float2*)(OUT + m0i * Dd + h * hd + d);
            float2 ev0 = *(const float2*)(QE + m0i * 1024 + 512 + h * hd + d);
            float2 ov1 = *(const float2*)(OUT + m1i * Dd + h * hd + d);
            float2 ev1 = *(const float2*)(QE + m1i * 1024 + 512 + h * hd + d);
            *(__half2*)(OH + m0i * Dd + h * hd + d) =
                __floats2half2_rn(acc[fm][fn][0] + ov0.x + ev0.x,
                                  acc[fm][fn][1] + ov0.y + ev0.y);
            *(__half2*)(OH + m1i * Dd + h * hd + d) =
                __floats2half2_rn(acc[fm][fn][2] + ov1.x + ev1.x,
                                  acc[fm][fn][3] + ov1.y + ev1.y);
        }
    }
}

// ---------------- launch ----------------
extern "C" void kernel_launch(void* const* d_in, const int* in_sizes, int n_in,
                              void* d_out, int out_size) {
    const float* x   = (const float*)d_in[0];
    const float* Wq  = (const float*)d_in[1];
    const float* bq  = (const float*)d_in[2];
    const float* Wk  = (const float*)d_in[3];
    const float* bk  = (const float*)d_in[4];
    const float* Wv  = (const float*)d_in[5];
    const float* bv  = (const float*)d_in[6];
    const float* We  = (const float*)d_in[7];
    const float* be  = (const float*)d_in[8];
    const float* Wo  = (const float*)d_in[9];
    const float* bo  = (const float*)d_in[10];
    const float* adp = (const float*)d_in[11];
    const float* U1  = (const float*)d_in[12];
    const float* U2  = (const float*)d_in[13];
    float* out = (float*)d_out;

    float *QE, *KV, *OUT, *ADT, *CL;
    cudaGetSymbolAddress((void**)&QE,  g_QE);
    cudaGetSymbolAddress((void**)&KV,  g_KV);
    cudaGetSymbolAddress((void**)&OUT, g_OUT);
    cudaGetSymbolAddress((void**)&ADT, g_ADT);
    cudaGetSymbolAddress((void**)&CL,  g_CL);

    __half *xh, *xph, *oh, *wqeh, *wkvh, *woh, *evh, *EXP1;
    cudaGetSymbolAddress((void**)&xh,   g_xh);
    cudaGetSymbolAddress((void**)&xph,  g_xph);
    cudaGetSymbolAddress((void**)&oh,   g_oh);
    cudaGetSymbolAddress((void**)&wqeh, g_wqeh);
    cudaGetSymbolAddress((void**)&wkvh, g_wkvh);
    cudaGetSymbolAddress((void**)&woh,  g_woh);
    cudaGetSymbolAddress((void**)&evh,  g_evh);
    cudaGetSymbolAddress((void**)&EXP1, g_EXP1);

    cudaFuncSetAttribute(gemm_f16, cudaFuncAttributeMaxDynamicSharedMemorySize, GEMM_SMEM);
    cudaFuncSetAttribute(attn_kernel, cudaFuncAttributeMaxDynamicSharedMemorySize, ATTN_SMEM);

    const int WN = Dd * Dd;            // 262144

    // launch order: index 3 (QE GEMM) targeted for the ncu capture window
    convert_f16<<<(M_BIG * Dd / 4 + 255) / 256, 256>>>(x, xh, M_BIG * Dd / 4);          // 0
    convert_w5<<<dim3(256, 5), 256>>>(Wq, We, Wk, Wv, Wo,
                                      wqeh, wqeh + WN, wkvh, wkvh + WN, woh);           // 1
    pool_convert_kernel<<<M_POOL, 128>>>(x, xph);                                       // 2
    gemm_f16<<<dim3(8, M_BIG / 128), 256, GEMM_SMEM>>>(xh, wqeh, bq, be, QE, 1024, evh);// 3 <- profiled
    transpose_adp<<<dim3(32, 4), 1024>>>(adp, ADT);                                     // 4
    gemm_f16<<<dim3(8, M_POOL / 128), 256, GEMM_SMEM>>>(xph, wkvh, bk, bv, KV, 1024,
                                                        nullptr);                       // 5
    attn_kernel<<<dim3(Gg, 4), 512, ATTN_SMEM>>>(QE, KV, ADT, OUT);                     // 6
    e1_gemm<<<dim3(8, Gg), 256>>>(evh, U1, EXP1);                                       // 7
    colsum_kernel<<<Gg, 256>>>(EXP1, CL);                                               // 8
    apply_gemm<<<dim3(8, Gg), 256>>>(EXP1, U2, CL, QE, OUT, oh);                        // 9
    gemm_f16<<<dim3(4, M_BIG / 128), 256, GEMM_SMEM>>>(oh, woh, bo, bo, out, Dd,
                                                       nullptr);                        // 10
}

// round 13
// speedup vs baseline: 1.2520x; 1.0212x over previous
#include <cuda_runtime.h>
#include <cuda_fp16.h>
#include <math.h>
#include <stdint.h>

// ---------------- problem dims ----------------
#define Bb   4
#define Tt   12
#define Nn   1024
#define Dd   512
#define Hh   8
#define hd   64
#define Cc   128
#define Ss   60
#define BT   48            // Bb*Tt
#define M_BIG  49152       // BT*Nn
#define M_POOL 6144        // BT*Cc
#define Gg   384           // BT*Hh

// ---------------- device scratch (allocation-free) ----------------
__device__ float g_QE [M_BIG  * 1024];   // [m][0:512]=q, [512:1024]=ev (fp32)
__device__ float g_KV [M_POOL * 1024];   // [c][0:512]=k, [512:1024]=v
__device__ float g_ADT[Cc * Nn];         // adp_pos transposed [c][n]
__device__ float g_CL [Gg * 64];         // 0.5 / colsum  (s padded to 64)

__device__ __half g_OUTh[M_BIG * Dd];    // attention branch output (fp16)
__device__ __half g_EXP1[(size_t)Gg * Nn * 64];  // exp(e1), [g][n][64], s>=60 -> 0
__device__ __half g_evh [M_BIG  * Dd];   // ev half (fp16 copy from QE gemm epilogue)
__device__ __half g_xh  [M_BIG  * Dd];
__device__ __half g_xph [M_POOL * Dd];
__device__ __half g_oh  [M_BIG  * Dd];
__device__ __half g_wqeh[1024 * Dd];
__device__ __half g_wkvh[1024 * Dd];
__device__ __half g_woh [Dd * Dd];

// ---------------- helpers ----------------
typedef unsigned long long u64t;
__device__ __forceinline__ uint32_t smem_u32(const void* p) {
    uint32_t a;
    asm("{ .reg .u64 t; cvta.to.shared.u64 t, %1; cvt.u32.u64 %0, t; }" : "=r"(a) : "l"(p));
    return a;
}
__device__ __forceinline__ u64t fma2(u64t a, u64t b, u64t c) {
    u64t d; asm("fma.rn.f32x2 %0, %1, %2, %3;" : "=l"(d) : "l"(a), "l"(b), "l"(c)); return d;
}
__device__ __forceinline__ u64t mul2(u64t a, u64t b) {
    u64t d; asm("mul.rn.f32x2 %0, %1, %2;" : "=l"(d) : "l"(a), "l"(b)); return d;
}
__device__ __forceinline__ u64t pack2(float x, float y) {
    u64t d; asm("mov.b64 %0, {%1, %2};" : "=l"(d) : "f"(x), "f"(y)); return d;
}
__device__ __forceinline__ float2 unpack2(u64t v) {
    float2 r; asm("mov.b64 {%0, %1}, %2;" : "=f"(r.x), "=f"(r.y) : "l"(v)); return r;
}
#define CP_ASYNC16(dst, src) \
    asm volatile("cp.async.cg.shared.global [%0], [%1], 16;" :: "r"(dst), "l"(src) : "memory")
#define CP_COMMIT() asm volatile("cp.async.commit_group;" ::: "memory")
#define CP_WAIT2()  asm volatile("cp.async.wait_group 2;" ::: "memory")
#define CP_WAIT0()  asm volatile("cp.async.wait_group 0;" ::: "memory")
#define LDSM4(r, addr) \
    asm volatile("ldmatrix.sync.aligned.m8n8.x4.shared.b16 {%0,%1,%2,%3}, [%4];" \
        : "=r"((r)[0]), "=r"((r)[1]), "=r"((r)[2]), "=r"((r)[3]) : "r"(addr))
__device__ __forceinline__ void mma16816(float* c, const uint32_t* a,
                                         uint32_t b0, uint32_t b1) {
    asm volatile("mma.sync.aligned.m16n8k16.row.col.f32.f16.f16.f32 "
                 "{%0,%1,%2,%3}, {%4,%5,%6,%7}, {%8,%9}, {%0,%1,%2,%3};"
                 : "+f"(c[0]), "+f"(c[1]), "+f"(c[2]), "+f"(c[3])
                 : "r"(a[0]), "r"(a[1]), "r"(a[2]), "r"(a[3]), "r"(b0), "r"(b1));
}

// ---------------- conversions ----------------
__global__ void __launch_bounds__(256) convert_f16(const float* __restrict__ src,
                                                   __half* __restrict__ dst, int n4) {
    int i = blockIdx.x * 256 + threadIdx.x;
    if (i >= n4) return;
    float4 v = ((const float4*)src)[i];
    __half2* D = (__half2*)dst;
    D[2 * i]     = __floats2half2_rn(v.x, v.y);
    D[2 * i + 1] = __floats2half2_rn(v.z, v.w);
}

// all 5 weight matrices in one launch; grid (256, 5)
__global__ void __launch_bounds__(256) convert_w5(
    const float* __restrict__ s0, const float* __restrict__ s1,
    const float* __restrict__ s2, const float* __restrict__ s3,
    const float* __restrict__ s4,
    __half* __restrict__ d0, __half* __restrict__ d1, __half* __restrict__ d2,
    __half* __restrict__ d3, __half* __restrict__ d4) {
    const float* s; __half* d;
    switch (blockIdx.y) {
        case 0:  s = s0; d = d0; break;
        case 1:  s = s1; d = d1; break;
        case 2:  s = s2; d = d2; break;
        case 3:  s = s3; d = d3; break;
        default: s = s4; d = d4; break;
    }
    int i = blockIdx.x * 256 + threadIdx.x;
    float4 v = ((const float4*)s)[i];
    __half2* D = (__half2*)d;
    D[2 * i]     = __floats2half2_rn(v.x, v.y);
    D[2 * i + 1] = __floats2half2_rn(v.z, v.w);
}

__global__ void __launch_bounds__(128) pool_convert_kernel(const float* __restrict__ X,
                                                           __half* __restrict__ XH) {
    int row = blockIdx.x;
    int bt = row >> 7, c = row & 127;
    int tid = threadIdx.x;
    const float4* xr = (const float4*)(X + ((size_t)bt * Nn + (size_t)c * 8) * Dd);
    float4 s = make_float4(0.f, 0.f, 0.f, 0.f);
#pragma unroll
    for (int j = 0; j < 8; j++) {
        float4 v = xr[(size_t)j * (Dd / 4) + tid];
        s.x += v.x; s.y += v.y; s.z += v.z; s.w += v.w;
    }
    s.x *= 0.125f; s.y *= 0.125f; s.z *= 0.125f; s.w *= 0.125f;
    size_t o = (size_t)row * Dd + tid * 4;
    *(__half2*)(XH + o)     = __floats2half2_rn(s.x, s.y);
    *(__half2*)(XH + o + 2) = __floats2half2_rn(s.z, s.w);
}

__global__ void __launch_bounds__(1024) transpose_adp(const float* __restrict__ AP,
                                                      float* __restrict__ ADT) {
    __shared__ float tile[32][33];
    int n0 = blockIdx.x * 32, c0 = blockIdx.y * 32;
    int tx = threadIdx.x & 31, ty = threadIdx.x >> 5;
    tile[ty][tx] = AP[(size_t)(n0 + ty) * Cc + c0 + tx];
    __syncthreads();
    ADT[(size_t)(c0 + ty) * Nn + n0 + tx] = tile[tx][ty];
}

// ---------------- HMMA GEMM fp16: C = Ah.Bh + bias, K=512 ----------------
#define ST_BYTES  20480
#define GEMM_SMEM (4 * ST_BYTES)
#define ROWB      80

__global__ void __launch_bounds__(256, 2)
gemm_f16(const __half* __restrict__ Ah, const __half* __restrict__ Bh,
         const float* __restrict__ bias0, const float* __restrict__ bias1,
         float* __restrict__ C, int Nout, __half* __restrict__ EVH) {
    extern __shared__ __align__(1024) char smem[];
    uint32_t sb = smem_u32(smem);
    const int tid = threadIdx.x;
    const int n0 = blockIdx.x * 128;
    const int m0 = blockIdx.y * 128;
    const int l = tid & 31, w = tid >> 5;
    const int wm = w & 3, wn = w >> 2;
    const float* bias = (n0 < 512) ? bias0 : bias1;
    const int nb = (n0 < 512) ? n0 : n0 - 512;

    float acc[2][8][4];
#pragma unroll
    for (int i = 0; i < 2; i++)
#pragma unroll
        for (int j = 0; j < 8; j++)
#pragma unroll
            for (int k = 0; k < 4; k++) acc[i][j][k] = 0.f;

    auto load_stage = [&](int slot, int kc) {
        int kt = kc * 32;
        uint32_t base = sb + (uint32_t)(slot * ST_BYTES);
#pragma unroll
        for (int it = 0; it < 4; ++it) {
            int idx = tid + it * 256;
            int half = idx >> 9;
            int r = (idx >> 2) & 127, ch = idx & 3;
            uint32_t d = base + (uint32_t)(half * 10240 + r * ROWB + ch * 16);
            const __half* src = half ? (Bh + (size_t)(n0 + r) * Dd + kt + ch * 8)
                                     : (Ah + (size_t)(m0 + r) * Dd + kt + ch * 8);
            CP_ASYNC16(d, src);
        }
    };

    load_stage(0, 0); CP_COMMIT();
    load_stage(1, 1); CP_COMMIT();
    load_stage(2, 2); CP_COMMIT();

    const uint32_t lrow = (uint32_t)(l & 15) * ROWB + (uint32_t)(l >> 4) * 16;

    for (int c = 0; c < 16; ++c) {
        CP_WAIT2();
        __syncthreads();
        if (c + 3 < 16) { load_stage((c + 3) & 3, c + 3); }
        CP_COMMIT();

        uint32_t stb = sb + (uint32_t)((c & 3) * ST_BYTES);
#pragma unroll
        for (int kk = 0; kk < 2; ++kk) {
            uint32_t aoff = stb + (uint32_t)(wm * 32) * ROWB + lrow + kk * 32;
            uint32_t boff = stb + 10240 + (uint32_t)(wn * 64) * ROWB + lrow + kk * 32;
            uint32_t a[2][4], b[4][4];
            LDSM4(a[0], aoff);
            LDSM4(a[1], aoff + 16 * ROWB);
#pragma unroll
            for (int fp = 0; fp < 4; ++fp) LDSM4(b[fp], boff + fp * 16 * ROWB);
#pragma unroll
            for (int fm = 0; fm < 2; ++fm)
#pragma unroll
                for (int fp = 0; fp < 4; ++fp) {
                    mma16816(acc[fm][2 * fp],     a[fm], b[fp][0], b[fp][2]);
                    mma16816(acc[fm][2 * fp + 1], a[fm], b[fp][1], b[fp][3]);
                }
        }
    }

#pragma unroll
    for (int fm = 0; fm < 2; ++fm) {
        int mrow = m0 + wm * 32 + fm * 16 + (l >> 2);
#pragma unroll
        for (int fn = 0; fn < 8; ++fn) {
            int nc = wn * 64 + fn * 8 + (l & 3) * 2;
            float b0 = bias[nb + nc], b1 = bias[nb + nc + 1];
            float2 o0, o1;
            o0.x = acc[fm][fn][0] + b0; o0.y = acc[fm][fn][1] + b1;
            o1.x = acc[fm][fn][2] + b0; o1.y = acc[fm][fn][3] + b1;
            *(float2*)(C + (size_t)mrow * Nout + n0 + nc)       = o0;
            *(float2*)(C + (size_t)(mrow + 8) * Nout + n0 + nc) = o1;
            if (EVH != nullptr && n0 >= 512) {
                *(__half2*)(EVH + (size_t)mrow * 512 + (n0 - 512) + nc) =
                    __floats2half2_rn(o0.x, o0.y);
                *(__half2*)(EVH + (size_t)(mrow + 8) * 512 + (n0 - 512) + nc) =
                    __floats2half2_rn(o1.x, o1.y);
            }
        }
    }
}

// ---------------- attention: 512 threads, query split across thread pairs ----------
#define KHALF_W   4112
#define ATTN_SMEM (2 * 16448 * 2)

__global__ void __launch_bounds__(512, 1) attn_kernel(const float* __restrict__ QE,
                                                      const float* __restrict__ KV,
                                                      const float* __restrict__ ADT,
                                                      __half* __restrict__ OUT) {
    extern __shared__ float sh[];
    float* khs = sh;
    float* vhs = sh + 2 * KHALF_W;
    int g  = blockIdx.x;
    int nt = blockIdx.y;
    int bt = g >> 3, hh = g & 7;
    int tid = threadIdx.x;
    int n0 = nt * 256;

    for (int i = tid; i < Cc * hd; i += 512) {
        int c = i >> 6, dd = i & 63;
        int hf = dd >> 5, d = dd & 31;
        int dst = hf * KHALF_W + c * 32 + d;
        size_t src = ((size_t)bt * Cc + c) * 1024 + hh * hd + dd;
        khs[dst] = KV[src];
        vhs[dst] = KV[src + 512];
    }
    __syncthreads();

    int q = tid >> 1, half = tid & 1;
    int n = n0 + q;
    u64t q2[16];
    {
        const float4* qp = (const float4*)(QE + ((size_t)bt * Nn + n) * 1024 + hh * hd + half * 32);
#pragma unroll
        for (int t = 0; t < 8; t++) {
            float4 v = qp[t];
            q2[2 * t]     = pack2(v.x, v.y);
            q2[2 * t + 1] = pack2(v.z, v.w);
        }
    }
    u64t o2[16];
#pragma unroll
    for (int i = 0; i < 16; i++) o2[i] = 0ull;
    float m = -INFINITY, lsum = 0.f;
    const float* kbase = khs + half * KHALF_W;
    const float* vbase = vhs + half * KHALF_W;
    float adp_c = ADT[n];

    for (int c = 0; c < Cc; c++) {
        float adp_n = (c < Cc - 1) ? ADT[(size_t)(c + 1) * Nn + n] : 0.f;
        const ulonglong2* kr = (const ulonglong2*)(kbase + c * 32);
        u64t a0 = 0ull, a1 = 0ull;
#pragma unroll
        for (int t = 0; t < 8; t++) {
            ulonglong2 kk = kr[t];
            a0 = fma2(q2[2 * t],     kk.x, a0);
            a1 = fma2(q2[2 * t + 1], kk.y, a1);
        }
        float2 fa = unpack2(a0), fb = unpack2(a1);
        float sp = (fa.x + fa.y) + (fb.x + fb.y);
        sp += __shfl_xor_sync(0xffffffffu, sp, 1);
        float s = sp * 0.125f + adp_c;
        float p;
        if (s > m) {
            float sc = __expf(m - s);
            m = s;
            lsum *= sc;
            u64t ss = pack2(sc, sc);
#pragma unroll
            for (int i = 0; i < 16; i++) o2[i] = mul2(ss, o2[i]);
            p = 1.f;
        } else {
            p = __expf(s - m);
        }
        lsum += p;
        u64t pp = pack2(p, p);
        const ulonglong2* vr = (const ulonglong2*)(vbase + c * 32);
#pragma unroll
        for (int t = 0; t < 8; t++) {
            ulonglong2 vv = vr[t];
            o2[2 * t]     = fma2(pp, vv.x, o2[2 * t]);
            o2[2 * t + 1] = fma2(pp, vv.y, o2[2 * t + 1]);
        }
        adp_c = adp_n;
    }
    float inv = 1.f / lsum;
    u64t ii = pack2(inv, inv);
    __half2* op = (__half2*)(OUT + ((size_t)bt * Nn + n) * Dd + hh * hd + half * 32);
#pragma unroll
    for (int t = 0; t < 8; t++) {
        float2 p0 = unpack2(mul2(o2[2 * t], ii));
        float2 p1 = unpack2(mul2(o2[2 * t + 1], ii));
        op[2 * t]     = __floats2half2_rn(p0.x, p0.y);
        op[2 * t + 1] = __floats2half2_rn(p1.x, p1.y);
    }
}

// ---------------- external branch, tensor-core version ----------------
#define EPITCH 144   // smem row pitch (bytes): 64 halfs data + pad

__global__ void __launch_bounds__(256) e1_gemm(const __half* __restrict__ EVH,
                                               const float* __restrict__ U1,
                                               __half* __restrict__ EXP1) {
    __shared__ __align__(16) char sm[128 * EPITCH + 64 * EPITCH];
    uint32_t sb = smem_u32(sm);
    int nt = blockIdx.x, g = blockIdx.y;
    int bt = g >> 3, h = g & 7;
    int tid = threadIdx.x;

#pragma unroll
    for (int it = 0; it < 4; ++it) {
        int idx = tid + it * 256;
        int r = idx >> 3, ch = idx & 7;
        uint32_t d = sb + (uint32_t)(r * EPITCH + ch * 16);
        CP_ASYNC16(d, EVH + ((size_t)(bt * Nn + nt * 128 + r) * 512 + h * hd + ch * 8));
    }
    CP_COMMIT();
    char* Bsm = sm + 128 * EPITCH;
    for (int i = tid; i < 64 * 64; i += 256) {
        int s = i >> 6, d = i & 63;
        float v = (s < Ss) ? U1[d * Ss + s] : 0.f;
        *(__half*)(Bsm + s * EPITCH + d * 2) = __float2half_rn(v);
    }
    CP_WAIT0();
    __syncthreads();

    int l = tid & 31, w = tid >> 5;
    int wm = w & 3, wn = w >> 2;
    float acc[2][4][4];
#pragma unroll
    for (int i = 0; i < 2; i++)
#pragma unroll
        for (int j = 0; j < 4; j++)
#pragma unroll
            for (int k = 0; k < 4; k++) acc[i][j][k] = 0.f;

    uint32_t lrow = (uint32_t)(l & 15) * EPITCH + (uint32_t)(l >> 4) * 16;
    uint32_t Abase = sb + (uint32_t)(wm * 32) * EPITCH;
    uint32_t Bbase = sb + 128 * EPITCH + (uint32_t)(wn * 32) * EPITCH;
#pragma unroll
    for (int k = 0; k < 4; ++k) {
        uint32_t a0[4], a1[4], b0[4], b1[4];
        LDSM4(a0, Abase + lrow + k * 32);
        LDSM4(a1, Abase + 16 * EPITCH + lrow + k * 32);
        LDSM4(b0, Bbase + lrow + k * 32);
        LDSM4(b1, Bbase + 16 * EPITCH + lrow + k * 32);
#pragma unroll
        for (int fm = 0; fm < 2; ++fm) {
            uint32_t* a = fm ? a1 : a0;
            mma16816(acc[fm][0], a, b0[0], b0[2]);
            mma16816(acc[fm][1], a, b0[1], b0[3]);
            mma16816(acc[fm][2], a, b1[0], b1[2]);
            mma16816(acc[fm][3], a, b1[1], b1[3]);
        }
    }
    int baseN = nt * 128 + wm * 32 + (l >> 2);
#pragma unroll
    for (int fm = 0; fm < 2; ++fm) {
        int n = baseN + fm * 16;
#pragma unroll
        for (int fn = 0; fn < 4; ++fn) {
            int s = wn * 32 + fn * 8 + (l & 3) * 2;
            bool ok = (s < Ss);
            float v0 = ok ? __expf(fminf(acc[fm][fn][0], 11.f)) : 0.f;
            float v1 = ok ? __expf(fminf(acc[fm][fn][1], 11.f)) : 0.f;
            float v2 = ok ? __expf(fminf(acc[fm][fn][2], 11.f)) : 0.f;
            float v3 = ok ? __expf(fminf(acc[fm][fn][3], 11.f)) : 0.f;
            *(__half2*)(EXP1 + ((size_t)g * Nn + n) * 64 + s)     = __floats2half2_rn(v0, v1);
            *(__half2*)(EXP1 + ((size_t)g * Nn + n + 8) * 64 + s) = __floats2half2_rn(v2, v3);
        }
    }
}

__global__ void __launch_bounds__(256) colsum_kernel(const __half* __restrict__ EXP1,
                                                     float* __restrict__ CL) {
    __shared__ float red[4][64];
    int g = blockIdx.x;
    int tid = threadIdx.x;
    int s = tid & 63, lane = tid >> 6;
    float sum = 0.f;
    const __half* base = EXP1 + (size_t)g * Nn * 64 + s;
    for (int n = lane; n < Nn; n += 4)
        sum += __half2float(base[(size_t)n * 64]);
    red[lane][s] = sum;
    __syncthreads();
    if (tid < 64) {
        float t = red[0][tid] + red[1][tid] + red[2][tid] + red[3][tid];
        CL[g * 64 + tid] = 0.5f / fmaxf(t, 1e-30f);
    }
}

__global__ void __launch_bounds__(256) apply_gemm(const __half* __restrict__ EXP1,
                                                  const float* __restrict__ U2,
                                                  const float* __restrict__ CL,
                                                  const float* __restrict__ QE,
                                                  const __half* __restrict__ OUT,
                                                  __half* __restrict__ OH) {
    __shared__ __align__(16) char sm[128 * EPITCH + 64 * EPITCH];
    __shared__ float rls[64];
    uint32_t sb = smem_u32(sm);
    int nt = blockIdx.x, g = blockIdx.y;
    int bt = g >> 3, h = g & 7;
    int tid = threadIdx.x;

#pragma unroll
    for (int it = 0; it < 4; ++it) {
        int idx = tid + it * 256;
        int r = idx >> 3, ch = idx & 7;
        uint32_t d = sb + (uint32_t)(r * EPITCH + ch * 16);
        CP_ASYNC16(d, EXP1 + ((size_t)g * Nn + nt * 128 + r) * 64 + ch * 8);
    }
    CP_COMMIT();
    if (tid < 64) rls[tid] = CL[g * 64 + tid];
    __syncthreads();
    char* Bsm = sm + 128 * EPITCH;
    for (int i = tid; i < 64 * 64; i += 256) {
        int d = i >> 6, s = i & 63;
        float v = (s < Ss) ? U2[s * hd + d] * rls[s] : 0.f;
        *(__half*)(Bsm + d * EPITCH + s * 2) = __float2half_rn(v);
    }
    CP_WAIT0();
    __syncthreads();

    int l = tid & 31, w = tid >> 5;
    int wm = w & 3, wn = w >> 2;
    float acc[2][4][4];
#pragma unroll
    for (int i = 0; i < 2; i++)
#pragma unroll
        for (int j = 0; j < 4; j++)
#pragma unroll
            for (int k = 0; k < 4; k++) acc[i][j][k] = 0.f;

    uint32_t lrow = (uint32_t)(l & 15) * EPITCH + (uint32_t)(l >> 4) * 16;
    uint32_t Abase = sb + (uint32_t)(wm * 32) * EPITCH;
    uint32_t Bbase = sb + 128 * EPITCH + (uint32_t)(wn * 32) * EPITCH;
#pragma unroll
    for (int k = 0; k < 4; ++k) {
        uint32_t a0[4], a1[4], b0[4], b1[4];
        LDSM4(a0, Abase + lrow + k * 32);
        LDSM4(a1, Abase + 16 * EPITCH + lrow + k * 32);
        LDSM4(b0, Bbase + lrow + k * 32);
        LDSM4(b1, Bbase + 16 * EPITCH + lrow + k * 32);
#pragma unroll
        for (int fm = 0; fm < 2; ++fm) {
            uint32_t* a = fm ? a1 : a0;
            mma16816(acc[fm][0], a, b0[0], b0[2]);
            mma16816(acc[fm][1], a, b0[1], b0[3]);
            mma16816(acc[fm][2], a, b1[0], b1[2]);
            mma16816(acc[fm][3], a, b1[1], b1[3]);
        }
    }
    int baseN = nt * 128 + wm * 32 + (l >> 2);
#pragma unroll
    for (int fm = 0; fm < 2; ++fm) {
        int n = baseN + fm * 16;
#pragma unroll
        for (int fn = 0; fn < 4; ++fn) {
            int d = wn * 32 + fn * 8 + (l & 3) * 2;
            size_t m0i = (size_t)bt * Nn + n;
            size_t m1i = m0i + 8;
            float2 ov0 = __half22float2(*(const __half2*)(OUT + m0i * Dd + h * hd + d));
            float2 ov1 = __half22float2(*(const __half2*)(OUT + m1i * Dd + h * hd + d));
            float2 ev0 = *(const float2*)(QE + m0i * 1024 + 512 + h * hd + d);
            float2 ev1 = *(const float2*)(QE + m1i * 1024 + 512 + h * hd + d);
            *(__half2*)(OH + m0i * Dd + h * hd + d) =
                __floats2half2_rn(acc[fm][fn][0] + ov0.x + ev0.x,
                                  acc[fm][fn][1] + ov0.y + ev0.y);
            *(__half2*)(OH + m1i * Dd + h * hd + d) =
                __floats2half2_rn(acc[fm][fn][2] + ov1.x + ev1.x,
                                  acc[fm][fn][3] + ov1.y + ev1.y);
        }
    }
}

// ---------------- launch ----------------
extern "C" void kernel_launch(void* const* d_in, const int* in_sizes, int n_in,
                              void* d_out, int out_size) {
    const float* x   = (const float*)d_in[0];
    const float* Wq  = (const float*)d_in[1];
    const float* bq  = (const float*)d_in[2];
    const float* Wk  = (const float*)d_in[3];
    const float* bk  = (const float*)d_in[4];
    const float* Wv  = (const float*)d_in[5];
    const float* bv  = (const float*)d_in[6];
    const float* We  = (const float*)d_in[7];
    const float* be  = (const float*)d_in[8];
    const float* Wo  = (const float*)d_in[9];
    const float* bo  = (const float*)d_in[10];
    const float* adp = (const float*)d_in[11];
    const float* U1  = (const float*)d_in[12];
    const float* U2  = (const float*)d_in[13];
    float* out = (float*)d_out;

    float *QE, *KV, *ADT, *CL;
    cudaGetSymbolAddress((void**)&QE,  g_QE);
    cudaGetSymbolAddress((void**)&KV,  g_KV);
    cudaGetSymbolAddress((void**)&ADT, g_ADT);
    cudaGetSymbolAddress((void**)&CL,  g_CL);

    __half *OUTh, *xh, *xph, *oh, *wqeh, *wkvh, *woh, *evh, *EXP1;
    cudaGetSymbolAddress((void**)&OUTh, g_OUTh);
    cudaGetSymbolAddress((void**)&xh,   g_xh);
    cudaGetSymbolAddress((void**)&xph,  g_xph);
    cudaGetSymbolAddress((void**)&oh,   g_oh);
    cudaGetSymbolAddress((void**)&wqeh, g_wqeh);
    cudaGetSymbolAddress((void**)&wkvh, g_wkvh);
    cudaGetSymbolAddress((void**)&woh,  g_woh);
    cudaGetSymbolAddress((void**)&evh,  g_evh);
    cudaGetSymbolAddress((void**)&EXP1, g_EXP1);

    cudaFuncSetAttribute(gemm_f16, cudaFuncAttributeMaxDynamicSharedMemorySize, GEMM_SMEM);
    cudaFuncSetAttribute(attn_kernel, cudaFuncAttributeMaxDynamicSharedMemorySize, ATTN_SMEM);

    const int WN = Dd * Dd;            // 262144

    // ---- multi-stream fork/join (capturable; deterministic work) ----
    cudaStream_t s1, s2, s3;
    cudaStreamCreateWithFlags(&s1, cudaStreamNonBlocking);
    cudaStreamCreateWithFlags(&s2, cudaStreamNonBlocking);
    cudaStreamCreateWithFlags(&s3, cudaStreamNonBlocking);
    cudaEvent_t eStart, eW, eKV, eADT, eQE, eE1;
    cudaEventCreateWithFlags(&eStart, cudaEventDisableTiming);
    cudaEventCreateWithFlags(&eW,     cudaEventDisableTiming);
    cudaEventCreateWithFlags(&eKV,    cudaEventDisableTiming);
    cudaEventCreateWithFlags(&eADT,   cudaEventDisableTiming);
    cudaEventCreateWithFlags(&eQE,    cudaEventDisableTiming);
    cudaEventCreateWithFlags(&eE1,    cudaEventDisableTiming);

    cudaEventRecord(eStart, 0);
    cudaStreamWaitEvent(s1, eStart, 0);
    cudaStreamWaitEvent(s2, eStart, 0);

    // s1: weights -> pooled x -> KV GEMM
    convert_w5<<<dim3(256, 5), 256, 0, s1>>>(Wq, We, Wk, Wv, Wo,
                                             wqeh, wqeh + WN, wkvh, wkvh + WN, woh);
    cudaEventRecord(eW, s1);
    pool_convert_kernel<<<M_POOL, 128, 0, s1>>>(x, xph);
    gemm_f16<<<dim3(8, M_POOL / 128), 256, GEMM_SMEM, s1>>>(xph, wkvh, bk, bv, KV, 1024,
                                                            nullptr);
    cudaEventRecord(eKV, s1);

    // s2: adp transpose
    transpose_adp<<<dim3(32, 4), 1024, 0, s2>>>(adp, ADT);
    cudaEventRecord(eADT, s2);

    // s0: x convert -> QE GEMM
    convert_f16<<<(M_BIG * Dd / 4 + 255) / 256, 256>>>(x, xh, M_BIG * Dd / 4);
    cudaStreamWaitEvent(0, eW, 0);
    gemm_f16<<<dim3(8, M_BIG / 128), 256, GEMM_SMEM>>>(xh, wqeh, bq, be, QE, 1024, evh);
    cudaEventRecord(eQE, 0);

    // s3: external-branch e1 + colsum (parallel with attention)
    cudaStreamWaitEvent(s3, eQE, 0);
    e1_gemm<<<dim3(8, Gg), 256, 0, s3>>>(evh, U1, EXP1);
    colsum_kernel<<<Gg, 256, 0, s3>>>(EXP1, CL);
    cudaEventRecord(eE1, s3);

    // s0: attention -> apply -> Wo GEMM
    cudaStreamWaitEvent(0, eKV, 0);
    cudaStreamWaitEvent(0, eADT, 0);
    attn_kernel<<<dim3(Gg, 4), 512, ATTN_SMEM>>>(QE, KV, ADT, OUTh);
    cudaStreamWaitEvent(0, eE1, 0);
    apply_gemm<<<dim3(8, Gg), 256>>>(EXP1, U2, CL, QE, OUTh, oh);
    gemm_f16<<<dim3(4, M_BIG / 128), 256, GEMM_SMEM>>>(oh, woh, bo, bo, out, Dd, nullptr);

    // cleanup: only when not capturing (destroying capture-forked streams is illegal)
    cudaStreamCaptureStatus st = cudaStreamCaptureStatusNone;
    cudaStreamIsCapturing(0, &st);
    if (st == cudaStreamCaptureStatusNone) {
        cudaEventDestroy(eStart); cudaEventDestroy(eW);  cudaEventDestroy(eKV);
        cudaEventDestroy(eADT);   cudaEventDestroy(eQE); cudaEventDestroy(eE1);
        cudaStreamDestroy(s1); cudaStreamDestroy(s2); cudaStreamDestroy(s3);
    }
}

// round 14
// speedup vs baseline: 2.0474x; 1.6354x over previous
#include <cuda_runtime.h>
#include <cuda_fp16.h>
#include <math.h>
#include <stdint.h>

// ---------------- problem dims ----------------
#define Bb   4
#define Tt   12
#define Nn   1024
#define Dd   512
#define Hh   8
#define hd   64
#define Cc   128
#define Ss   60
#define BT   48            // Bb*Tt
#define M_BIG  49152       // BT*Nn
#define M_POOL 6144        // BT*Cc
#define Gg   384           // BT*Hh

// ---------------- device scratch (allocation-free) ----------------
__device__ float g_QE [M_BIG  * 1024];   // [m][0:512]=q, [512:1024]=ev (fp32)
__device__ float g_KV [M_POOL * 1024];   // fp32 KV (unused by attn now, kept by gemm)
__device__ float g_CL [Gg * 64];         // 0.5 / colsum  (s padded to 64)

__device__ __half g_OUTh[M_BIG * Dd];    // attention branch output (fp16)
__device__ __half g_EXP1[(size_t)Gg * Nn * 64];  // exp(e1), [g][n][64]
__device__ __half g_qeh [M_BIG  * 1024]; // fp16 mirror of QE
__device__ __half g_kvh [M_POOL * 1024]; // fp16 mirror of KV
__device__ __half g_xh  [M_BIG  * Dd];
__device__ __half g_xph [M_POOL * Dd];
__device__ __half g_oh  [M_BIG  * Dd];
__device__ __half g_wqeh[1024 * Dd];
__device__ __half g_wkvh[1024 * Dd];
__device__ __half g_woh [Dd * Dd];

// ---------------- helpers ----------------
__device__ __forceinline__ uint32_t smem_u32(const void* p) {
    uint32_t a;
    asm("{ .reg .u64 t; cvta.to.shared.u64 t, %1; cvt.u32.u64 %0, t; }" : "=r"(a) : "l"(p));
    return a;
}
#define CP_ASYNC16(dst, src) \
    asm volatile("cp.async.cg.shared.global [%0], [%1], 16;" :: "r"(dst), "l"(src) : "memory")
#define CP_COMMIT() asm volatile("cp.async.commit_group;" ::: "memory")
#define CP_WAIT2()  asm volatile("cp.async.wait_group 2;" ::: "memory")
#define CP_WAIT0()  asm volatile("cp.async.wait_group 0;" ::: "memory")
#define LDSM4(r, addr) \
    asm volatile("ldmatrix.sync.aligned.m8n8.x4.shared.b16 {%0,%1,%2,%3}, [%4];" \
        : "=r"((r)[0]), "=r"((r)[1]), "=r"((r)[2]), "=r"((r)[3]) : "r"(addr))
__device__ __forceinline__ void mma16816(float* c, const uint32_t* a,
                                         uint32_t b0, uint32_t b1) {
    asm volatile("mma.sync.aligned.m16n8k16.row.col.f32.f16.f16.f32 "
                 "{%0,%1,%2,%3}, {%4,%5,%6,%7}, {%8,%9}, {%0,%1,%2,%3};"
                 : "+f"(c[0]), "+f"(c[1]), "+f"(c[2]), "+f"(c[3])
                 : "r"(a[0]), "r"(a[1]), "r"(a[2]), "r"(a[3]), "r"(b0), "r"(b1));
}

// ---------------- conversions ----------------
__global__ void __launch_bounds__(256) convert_f16(const float* __restrict__ src,
                                                   __half* __restrict__ dst, int n4) {
    int i = blockIdx.x * 256 + threadIdx.x;
    if (i >= n4) return;
    float4 v = ((const float4*)src)[i];
    __half2* D = (__half2*)dst;
    D[2 * i]     = __floats2half2_rn(v.x, v.y);
    D[2 * i + 1] = __floats2half2_rn(v.z, v.w);
}

__global__ void __launch_bounds__(256) convert_w5(
    const float* __restrict__ s0, const float* __restrict__ s1,
    const float* __restrict__ s2, const float* __restrict__ s3,
    const float* __restrict__ s4,
    __half* __restrict__ d0, __half* __restrict__ d1, __half* __restrict__ d2,
    __half* __restrict__ d3, __half* __restrict__ d4) {
    const float* s; __half* d;
    switch (blockIdx.y) {
        case 0:  s = s0; d = d0; break;
        case 1:  s = s1; d = d1; break;
        case 2:  s = s2; d = d2; break;
        case 3:  s = s3; d = d3; break;
        default: s = s4; d = d4; break;
    }
    int i = blockIdx.x * 256 + threadIdx.x;
    float4 v = ((const float4*)s)[i];
    __half2* D = (__half2*)d;
    D[2 * i]     = __floats2half2_rn(v.x, v.y);
    D[2 * i + 1] = __floats2half2_rn(v.z, v.w);
}

__global__ void __launch_bounds__(128) pool_convert_kernel(const float* __restrict__ X,
                                                           __half* __restrict__ XH) {
    int row = blockIdx.x;
    int bt = row >> 7, c = row & 127;
    int tid = threadIdx.x;
    const float4* xr = (const float4*)(X + ((size_t)bt * Nn + (size_t)c * 8) * Dd);
    float4 s = make_float4(0.f, 0.f, 0.f, 0.f);
#pragma unroll
    for (int j = 0; j < 8; j++) {
        float4 v = xr[(size_t)j * (Dd / 4) + tid];
        s.x += v.x; s.y += v.y; s.z += v.z; s.w += v.w;
    }
    s.x *= 0.125f; s.y *= 0.125f; s.z *= 0.125f; s.w *= 0.125f;
    size_t o = (size_t)row * Dd + tid * 4;
    *(__half2*)(XH + o)     = __floats2half2_rn(s.x, s.y);
    *(__half2*)(XH + o + 2) = __floats2half2_rn(s.z, s.w);
}

// ---------------- HMMA GEMM fp16: C = Ah.Bh + bias, K=512 ----------------
#define ST_BYTES  20480
#define GEMM_SMEM (4 * ST_BYTES)
#define ROWB      80

__global__ void __launch_bounds__(256, 2)
gemm_f16(const __half* __restrict__ Ah, const __half* __restrict__ Bh,
         const float* __restrict__ bias0, const float* __restrict__ bias1,
         float* __restrict__ C, int Nout, __half* __restrict__ FH) {
    extern __shared__ __align__(1024) char smem[];
    uint32_t sb = smem_u32(smem);
    const int tid = threadIdx.x;
    const int n0 = blockIdx.x * 128;
    const int m0 = blockIdx.y * 128;
    const int l = tid & 31, w = tid >> 5;
    const int wm = w & 3, wn = w >> 2;
    const float* bias = (n0 < 512) ? bias0 : bias1;
    const int nb = (n0 < 512) ? n0 : n0 - 512;

    float acc[2][8][4];
#pragma unroll
    for (int i = 0; i < 2; i++)
#pragma unroll
        for (int j = 0; j < 8; j++)
#pragma unroll
            for (int k = 0; k < 4; k++) acc[i][j][k] = 0.f;

    auto load_stage = [&](int slot, int kc) {
        int kt = kc * 32;
        uint32_t base = sb + (uint32_t)(slot * ST_BYTES);
#pragma unroll
        for (int it = 0; it < 4; ++it) {
            int idx = tid + it * 256;
            int half = idx >> 9;
            int r = (idx >> 2) & 127, ch = idx & 3;
            uint32_t d = base + (uint32_t)(half * 10240 + r * ROWB + ch * 16);
            const __half* src = half ? (Bh + (size_t)(n0 + r) * Dd + kt + ch * 8)
                                     : (Ah + (size_t)(m0 + r) * Dd + kt + ch * 8);
            CP_ASYNC16(d, src);
        }
    };

    load_stage(0, 0); CP_COMMIT();
    load_stage(1, 1); CP_COMMIT();
    load_stage(2, 2); CP_COMMIT();

    const uint32_t lrow = (uint32_t)(l & 15) * ROWB + (uint32_t)(l >> 4) * 16;

    for (int c = 0; c < 16; ++c) {
        CP_WAIT2();
        __syncthreads();
        if (c + 3 < 16) { load_stage((c + 3) & 3, c + 3); }
        CP_COMMIT();

        uint32_t stb = sb + (uint32_t)((c & 3) * ST_BYTES);
#pragma unroll
        for (int kk = 0; kk < 2; ++kk) {
            uint32_t aoff = stb + (uint32_t)(wm * 32) * ROWB + lrow + kk * 32;
            uint32_t boff = stb + 10240 + (uint32_t)(wn * 64) * ROWB + lrow + kk * 32;
            uint32_t a[2][4], b[4][4];
            LDSM4(a[0], aoff);
            LDSM4(a[1], aoff + 16 * ROWB);
#pragma unroll
            for (int fp = 0; fp < 4; ++fp) LDSM4(b[fp], boff + fp * 16 * ROWB);
#pragma unroll
            for (int fm = 0; fm < 2; ++fm)
#pragma unroll
                for (int fp = 0; fp < 4; ++fp) {
                    mma16816(acc[fm][2 * fp],     a[fm], b[fp][0], b[fp][2]);
                    mma16816(acc[fm][2 * fp + 1], a[fm], b[fp][1], b[fp][3]);
                }
        }
    }

#pragma unroll
    for (int fm = 0; fm < 2; ++fm) {
        int mrow = m0 + wm * 32 + fm * 16 + (l >> 2);
#pragma unroll
        for (int fn = 0; fn < 8; ++fn) {
            int nc = wn * 64 + fn * 8 + (l & 3) * 2;
            float b0 = bias[nb + nc], b1 = bias[nb + nc + 1];
            float2 o0, o1;
            o0.x = acc[fm][fn][0] + b0; o0.y = acc[fm][fn][1] + b1;
            o1.x = acc[fm][fn][2] + b0; o1.y = acc[fm][fn][3] + b1;
            *(float2*)(C + (size_t)mrow * Nout + n0 + nc)       = o0;
            *(float2*)(C + (size_t)(mrow + 8) * Nout + n0 + nc) = o1;
            if (FH != nullptr) {
                *(__half2*)(FH + (size_t)mrow * Nout + n0 + nc) =
                    __floats2half2_rn(o0.x, o0.y);
                *(__half2*)(FH + (size_t)(mrow + 8) * Nout + n0 + nc) =
                    __floats2half2_rn(o1.x, o1.y);
            }
        }
    }
}

// ---------------- tensor-core attention ----------------
// per (g, 128-query tile): S = Qh.Kh^T /8 + adp; row softmax; OUT = P(fp16).V
#define EP1   144                    // pitch for 64-half rows (Q, K, V staging)
#define EP2   272                    // pitch for 128-half rows (P, AD) & Vt
#define AQS   0
#define AKS   18432
#define AVT   36864                  // Vt: 64 x EP2
#define AAD   54272                  // adp fp16: 128 x EP2
#define APS   89088                  // P: 128 x EP2 (also V staging 128 x EP1)
#define ARED  123904                 // float[2][128][2]
#define ATTN_SMEM 125952

__global__ void __launch_bounds__(256, 1)
attn_tc(const __half* __restrict__ QEH, const __half* __restrict__ KVH,
        const float* __restrict__ ADP, __half* __restrict__ OUT) {
    extern __shared__ __align__(1024) char sm[];
    uint32_t sb = smem_u32(sm);
    int nt = blockIdx.x, g = blockIdx.y;
    int bt = g >> 3, hh = g & 7;
    int tid = threadIdx.x;
    int n0 = nt * 128;
    const int l = tid & 31, w = tid >> 5;
    const int wm = w & 3, wn = w >> 2;

    // Q, K, V(staging in P region) via cp.async: 3 x 1024 chunks of 16B
#pragma unroll
    for (int it = 0; it < 12; ++it) {
        int idx = tid + it * 256;
        int tile = idx >> 10, j = idx & 1023;
        int r = j >> 3, ch = j & 7;
        uint32_t d;
        const __half* src;
        if (tile == 0) {
            d = sb + AQS + (uint32_t)(r * EP1 + ch * 16);
            src = QEH + ((size_t)(bt * Nn + n0 + r) * 1024 + hh * hd + ch * 8);
        } else if (tile == 1) {
            d = sb + AKS + (uint32_t)(r * EP1 + ch * 16);
            src = KVH + ((size_t)(bt * Cc + r) * 1024 + hh * hd + ch * 8);
        } else {
            d = sb + APS + (uint32_t)(r * EP1 + ch * 16);
            src = KVH + ((size_t)(bt * Cc + r) * 1024 + 512 + hh * hd + ch * 8);
        }
        CP_ASYNC16(d, src);
    }
    CP_COMMIT();
    // adp tile fp32 -> fp16, [n][c]
#pragma unroll
    for (int it = 0; it < 16; ++it) {
        int i = tid + it * 256;            // 0..4095
        int r = i >> 5, c4 = i & 31;
        float4 v = *(const float4*)(ADP + (size_t)(n0 + r) * Cc + c4 * 4);
        char* p = sm + AAD + r * EP2 + c4 * 8;
        *(__half2*)p       = __floats2half2_rn(v.x, v.y);
        *(__half2*)(p + 4) = __floats2half2_rn(v.z, v.w);
    }
    CP_WAIT0();
    __syncthreads();

    // transpose V staging [c][d] -> Vt [d][c]
#pragma unroll
    for (int it = 0; it < 32; ++it) {
        int i = tid + it * 256;            // 0..8191
        int d = i & 63, c = i >> 6;
        __half v = *(const __half*)(sm + APS + c * EP1 + d * 2);
        *(__half*)(sm + AVT + d * EP2 + c * 2) = v;
    }
    __syncthreads();

    // MMA1: S[128n x 128c] = Q.K^T  (K-dim 64)
    float acc[2][8][4];
#pragma unroll
    for (int i = 0; i < 2; i++)
#pragma unroll
        for (int j = 0; j < 8; j++)
#pragma unroll
            for (int k = 0; k < 4; k++) acc[i][j][k] = 0.f;
    const uint32_t lrow1 = (uint32_t)(l & 15) * EP1 + (uint32_t)(l >> 4) * 16;
#pragma unroll
    for (int kc = 0; kc < 4; ++kc) {
        uint32_t aoff = sb + AQS + (uint32_t)(wm * 32) * EP1 + lrow1 + kc * 32;
        uint32_t boff = sb + AKS + (uint32_t)(wn * 64) * EP1 + lrow1 + kc * 32;
        uint32_t a[2][4], b[4][4];
        LDSM4(a[0], aoff);
        LDSM4(a[1], aoff + 16 * EP1);
#pragma unroll
        for (int fp = 0; fp < 4; ++fp) LDSM4(b[fp], boff + fp * 16 * EP1);
#pragma unroll
        for (int fm = 0; fm < 2; ++fm)
#pragma unroll
            for (int fp = 0; fp < 4; ++fp) {
                mma16816(acc[fm][2 * fp],     a[fm], b[fp][0], b[fp][2]);
                mma16816(acc[fm][2 * fp + 1], a[fm], b[fp][1], b[fp][3]);
            }
    }

    // scale + adp
#pragma unroll
    for (int fm = 0; fm < 2; ++fm) {
        int rbase = wm * 32 + fm * 16 + (l >> 2);
#pragma unroll
        for (int fn = 0; fn < 8; ++fn) {
            int cb = wn * 64 + fn * 8 + (l & 3) * 2;
#pragma unroll
            for (int k2 = 0; k2 < 2; ++k2) {
                int r = rbase + k2 * 8;
                float2 ad = __half22float2(*(const __half2*)(sm + AAD + r * EP2 + cb * 2));
                acc[fm][fn][2 * k2]     = acc[fm][fn][2 * k2]     * 0.125f + ad.x;
                acc[fm][fn][2 * k2 + 1] = acc[fm][fn][2 * k2 + 1] * 0.125f + ad.y;
            }
        }
    }

    float* REDm = (float*)(sm + ARED);         // [128][2]
    float* REDs = (float*)(sm + ARED + 1024);  // [128][2]

    // row max
    float rmax[2][2];
#pragma unroll
    for (int fm = 0; fm < 2; ++fm)
#pragma unroll
        for (int k2 = 0; k2 < 2; ++k2) {
            float m = -1e30f;
#pragma unroll
            for (int fn = 0; fn < 8; ++fn) {
                m = fmaxf(m, acc[fm][fn][2 * k2]);
                m = fmaxf(m, acc[fm][fn][2 * k2 + 1]);
            }
            m = fmaxf(m, __shfl_xor_sync(0xffffffffu, m, 1));
            m = fmaxf(m, __shfl_xor_sync(0xffffffffu, m, 2));
            rmax[fm][k2] = m;
            if ((l & 3) == 0) {
                int r = wm * 32 + fm * 16 + (l >> 2) + k2 * 8;
                REDm[r * 2 + wn] = m;
            }
        }
    __syncthreads();
    float cmax[2][2];
#pragma unroll
    for (int fm = 0; fm < 2; ++fm)
#pragma unroll
        for (int k2 = 0; k2 < 2; ++k2) {
            int r = wm * 32 + fm * 16 + (l >> 2) + k2 * 8;
            cmax[fm][k2] = fmaxf(REDm[r * 2], REDm[r * 2 + 1]);
        }
    // exp + row sum
    float rsum[2][2] = {{0.f, 0.f}, {0.f, 0.f}};
#pragma unroll
    for (int fm = 0; fm < 2; ++fm)
#pragma unroll
        for (int fn = 0; fn < 8; ++fn)
#pragma unroll
            for (int k = 0; k < 4; ++k) {
                float e = __expf(acc[fm][fn][k] - cmax[fm][k >> 1]);
                acc[fm][fn][k] = e;
                rsum[fm][k >> 1] += e;
            }
#pragma unroll
    for (int fm = 0; fm < 2; ++fm)
#pragma unroll
        for (int k2 = 0; k2 < 2; ++k2) {
            float s = rsum[fm][k2];
            s += __shfl_xor_sync(0xffffffffu, s, 1);
            s += __shfl_xor_sync(0xffffffffu, s, 2);
            if ((l & 3) == 0) {
                int r = wm * 32 + fm * 16 + (l >> 2) + k2 * 8;
                REDs[r * 2 + wn] = s;
            }
        }
    __syncthreads();
    // normalize -> P fp16 in smem
#pragma unroll
    for (int fm = 0; fm < 2; ++fm)
#pragma unroll
        for (int k2 = 0; k2 < 2; ++k2) {
            int r = wm * 32 + fm * 16 + (l >> 2) + k2 * 8;
            float inv = 1.f / (REDs[r * 2] + REDs[r * 2 + 1]);
#pragma unroll
            for (int fn = 0; fn < 8; ++fn) {
                int cb = wn * 64 + fn * 8 + (l & 3) * 2;
                *(__half2*)(sm + APS + r * EP2 + cb * 2) =
                    __floats2half2_rn(acc[fm][fn][2 * k2] * inv,
                                      acc[fm][fn][2 * k2 + 1] * inv);
            }
        }
    __syncthreads();

    // MMA2: O[128n x 64d] = P.Vt  (K-dim 128)
    float acc2[2][4][4];
#pragma unroll
    for (int i = 0; i < 2; i++)
#pragma unroll
        for (int j = 0; j < 4; j++)
#pragma unroll
            for (int k = 0; k < 4; k++) acc2[i][j][k] = 0.f;
    const uint32_t lrow2 = (uint32_t)(l & 15) * EP2 + (uint32_t)(l >> 4) * 16;
#pragma unroll
    for (int kc = 0; kc < 8; ++kc) {
        uint32_t aoff = sb + APS + (uint32_t)(wm * 32) * EP2 + lrow2 + kc * 32;
        uint32_t boff = sb + AVT + (uint32_t)(wn * 32) * EP2 + lrow2 + kc * 32;
        uint32_t a0[4], a1[4], b0[4], b1[4];
        LDSM4(a0, aoff);
        LDSM4(a1, aoff + 16 * EP2);
        LDSM4(b0, boff);
        LDSM4(b1, boff + 16 * EP2);
#pragma unroll
        for (int fm = 0; fm < 2; ++fm) {
            uint32_t* a = fm ? a1 : a0;
            mma16816(acc2[fm][0], a, b0[0], b0[2]);
            mma16816(acc2[fm][1], a, b0[1], b0[3]);
            mma16816(acc2[fm][2], a, b1[0], b1[2]);
            mma16816(acc2[fm][3], a, b1[1], b1[3]);
        }
    }
#pragma unroll
    for (int fm = 0; fm < 2; ++fm) {
        int rb = wm * 32 + fm * 16 + (l >> 2);
#pragma unroll
        for (int fn = 0; fn < 4; ++fn) {
            int d = wn * 32 + fn * 8 + (l & 3) * 2;
            size_t m0i = (size_t)(bt * Nn + n0 + rb) * Dd + hh * hd + d;
            size_t m1i = (size_t)(bt * Nn + n0 + rb + 8) * Dd + hh * hd + d;
            *(__half2*)(OUT + m0i) = __floats2half2_rn(acc2[fm][fn][0], acc2[fm][fn][1]);
            *(__half2*)(OUT + m1i) = __floats2half2_rn(acc2[fm][fn][2], acc2[fm][fn][3]);
        }
    }
}

// ---------------- external branch, tensor-core version ----------------
#define EPITCH 144

__global__ void __launch_bounds__(256) e1_gemm(const __half* __restrict__ QEH,
                                               const float* __restrict__ U1,
                                               __half* __restrict__ EXP1) {
    __shared__ __align__(16) char sm[128 * EPITCH + 64 * EPITCH];
    uint32_t sb = smem_u32(sm);
    int nt = blockIdx.x, g = blockIdx.y;
    int bt = g >> 3, h = g & 7;
    int tid = threadIdx.x;

#pragma unroll
    for (int it = 0; it < 4; ++it) {
        int idx = tid + it * 256;
        int r = idx >> 3, ch = idx & 7;
        uint32_t d = sb + (uint32_t)(r * EPITCH + ch * 16);
        CP_ASYNC16(d, QEH + ((size_t)(bt * Nn + nt * 128 + r) * 1024 + 512 + h * hd + ch * 8));
    }
    CP_COMMIT();
    char* Bsm = sm + 128 * EPITCH;
    for (int i = tid; i < 64 * 64; i += 256) {
        int s = i >> 6, d = i & 63;
        float v = (s < Ss) ? U1[d * Ss + s] : 0.f;
        *(__half*)(Bsm + s * EPITCH + d * 2) = __float2half_rn(v);
    }
    CP_WAIT0();
    __syncthreads();

    int l = tid & 31, w = tid >> 5;
    int wm = w & 3, wn = w >> 2;
    float acc[2][4][4];
#pragma unroll
    for (int i = 0; i < 2; i++)
#pragma unroll
        for (int j = 0; j < 4; j++)
#pragma unroll
            for (int k = 0; k < 4; k++) acc[i][j][k] = 0.f;

    uint32_t lrow = (uint32_t)(l & 15) * EPITCH + (uint32_t)(l >> 4) * 16;
    uint32_t Abase = sb + (uint32_t)(wm * 32) * EPITCH;
    uint32_t Bbase = sb + 128 * EPITCH + (uint32_t)(wn * 32) * EPITCH;
#pragma unroll
    for (int k = 0; k < 4; ++k) {
        uint32_t a0[4], a1[4], b0[4], b1[4];
        LDSM4(a0, Abase + lrow + k * 32);
        LDSM4(a1, Abase + 16 * EPITCH + lrow + k * 32);
        LDSM4(b0, Bbase + lrow + k * 32);
        LDSM4(b1, Bbase + 16 * EPITCH + lrow + k * 32);
#pragma unroll
        for (int fm = 0; fm < 2; ++fm) {
            uint32_t* a = fm ? a1 : a0;
            mma16816(acc[fm][0], a, b0[0], b0[2]);
            mma16816(acc[fm][1], a, b0[1], b0[3]);
            mma16816(acc[fm][2], a, b1[0], b1[2]);
            mma16816(acc[fm][3], a, b1[1], b1[3]);
        }
    }
    int baseN = nt * 128 + wm * 32 + (l >> 2);
#pragma unroll
    for (int fm = 0; fm < 2; ++fm) {
        int n = baseN + fm * 16;
#pragma unroll
        for (int fn = 0; fn < 4; ++fn) {
            int s = wn * 32 + fn * 8 + (l & 3) * 2;
            bool ok = (s < Ss);
            float v0 = ok ? __expf(fminf(acc[fm][fn][0], 11.f)) : 0.f;
            float v1 = ok ? __expf(fminf(acc[fm][fn][1], 11.f)) : 0.f;
            float v2 = ok ? __expf(fminf(acc[fm][fn][2], 11.f)) : 0.f;
            float v3 = ok ? __expf(fminf(acc[fm][fn][3], 11.f)) : 0.f;
            *(__half2*)(EXP1 + ((size_t)g * Nn + n) * 64 + s)     = __floats2half2_rn(v0, v1);
            *(__half2*)(EXP1 + ((size_t)g * Nn + n + 8) * 64 + s) = __floats2half2_rn(v2, v3);
        }
    }
}

__global__ void __launch_bounds__(256) colsum_kernel(const __half* __restrict__ EXP1,
                                                     float* __restrict__ CL) {
    __shared__ float red[4][64];
    int g = blockIdx.x;
    int tid = threadIdx.x;
    int s = tid & 63, lane = tid >> 6;
    float sum = 0.f;
    const __half* base = EXP1 + (size_t)g * Nn * 64 + s;
    for (int n = lane; n < Nn; n += 4)
        sum += __half2float(base[(size_t)n * 64]);
    red[lane][s] = sum;
    __syncthreads();
    if (tid < 64) {
        float t = red[0][tid] + red[1][tid] + red[2][tid] + red[3][tid];
        CL[g * 64 + tid] = 0.5f / fmaxf(t, 1e-30f);
    }
}

__global__ void __launch_bounds__(256) apply_gemm(const __half* __restrict__ EXP1,
                                                  const float* __restrict__ U2,
                                                  const float* __restrict__ CL,
                                                  const float* __restrict__ QE,
                                                  const __half* __restrict__ OUT,
                                                  __half* __restrict__ OH) {
    __shared__ __align__(16) char sm[128 * EPITCH + 64 * EPITCH];
    __shared__ float rls[64];
    uint32_t sb = smem_u32(sm);
    int nt = blockIdx.x, g = blockIdx.y;
    int bt = g >> 3, h = g & 7;
    int tid = threadIdx.x;

#pragma unroll
    for (int it = 0; it < 4; ++it) {
        int idx = tid + it * 256;
        int r = idx >> 3, ch = idx & 7;
        uint32_t d = sb + (uint32_t)(r * EPITCH + ch * 16);
        CP_ASYNC16(d, EXP1 + ((size_t)g * Nn + nt * 128 + r) * 64 + ch * 8);
    }
    CP_COMMIT();
    if (tid < 64) rls[tid] = CL[g * 64 + tid];
    __syncthreads();
    char* Bsm = sm + 128 * EPITCH;
    for (int i = tid; i < 64 * 64; i += 256) {
        int d = i >> 6, s = i & 63;
        float v = (s < Ss) ? U2[s * hd + d] * rls[s] : 0.f;
        *(__half*)(Bsm + d * EPITCH + s * 2) = __float2half_rn(v);
    }
    CP_WAIT0();
    __syncthreads();

    int l = tid & 31, w = tid >> 5;
    int wm = w & 3, wn = w >> 2;
    float acc[2][4][4];
#pragma unroll
    for (int i = 0; i < 2; i++)
#pragma unroll
        for (int j = 0; j < 4; j++)
#pragma unroll
            for (int k = 0; k < 4; k++) acc[i][j][k] = 0.f;

    uint32_t lrow = (uint32_t)(l & 15) * EPITCH + (uint32_t)(l >> 4) * 16;
    uint32_t Abase = sb + (uint32_t)(wm * 32) * EPITCH;
    uint32_t Bbase = sb + 128 * EPITCH + (uint32_t)(wn * 32) * EPITCH;
#pragma unroll
    for (int k = 0; k < 4; ++k) {
        uint32_t a0[4], a1[4], b0[4], b1[4];
        LDSM4(a0, Abase + lrow + k * 32);
        LDSM4(a1, Abase + 16 * EPITCH + lrow + k * 32);
        LDSM4(b0, Bbase + lrow + k * 32);
        LDSM4(b1, Bbase + 16 * EPITCH + lrow + k * 32);
#pragma unroll
        for (int fm = 0; fm < 2; ++fm) {
            uint32_t* a = fm ? a1 : a0;
            mma16816(acc[fm][0], a, b0[0], b0[2]);
            mma16816(acc[fm][1], a, b0[1], b0[3]);
            mma16816(acc[fm][2], a, b1[0], b1[2]);
            mma16816(acc[fm][3], a, b1[1], b1[3]);
        }
    }
    int baseN = nt * 128 + wm * 32 + (l >> 2);
#pragma unroll
    for (int fm = 0; fm < 2; ++fm) {
        int n = baseN + fm * 16;
#pragma unroll
        for (int fn = 0; fn < 4; ++fn) {
            int d = wn * 32 + fn * 8 + (l & 3) * 2;
            size_t m0i = (size_t)bt * Nn + n;
            size_t m1i = m0i + 8;
            float2 ov0 = __half22float2(*(const __half2*)(OUT + m0i * Dd + h * hd + d));
            float2 ov1 = __half22float2(*(const __half2*)(OUT + m1i * Dd + h * hd + d));
            float2 ev0 = *(const float2*)(QE + m0i * 1024 + 512 + h * hd + d);
            float2 ev1 = *(const float2*)(QE + m1i * 1024 + 512 + h * hd + d);
            *(__half2*)(OH + m0i * Dd + h * hd + d) =
                __floats2half2_rn(acc[fm][fn][0] + ov0.x + ev0.x,
                                  acc[fm][fn][1] + ov0.y + ev0.y);
            *(__half2*)(OH + m1i * Dd + h * hd + d) =
                __floats2half2_rn(acc[fm][fn][2] + ov1.x + ev1.x,
                                  acc[fm][fn][3] + ov1.y + ev1.y);
        }
    }
}

// ---------------- launch ----------------
extern "C" void kernel_launch(void* const* d_in, const int* in_sizes, int n_in,
                              void* d_out, int out_size) {
    const float* x   = (const float*)d_in[0];
    const float* Wq  = (const float*)d_in[1];
    const float* bq  = (const float*)d_in[2];
    const float* Wk  = (const float*)d_in[3];
    const float* bk  = (const float*)d_in[4];
    const float* Wv  = (const float*)d_in[5];
    const float* bv  = (const float*)d_in[6];
    const float* We  = (const float*)d_in[7];
    const float* be  = (const float*)d_in[8];
    const float* Wo  = (const float*)d_in[9];
    const float* bo  = (const float*)d_in[10];
    const float* adp = (const float*)d_in[11];
    const float* U1  = (const float*)d_in[12];
    const float* U2  = (const float*)d_in[13];
    float* out = (float*)d_out;

    float *QE, *KV, *CL;
    cudaGetSymbolAddress((void**)&QE,  g_QE);
    cudaGetSymbolAddress((void**)&KV,  g_KV);
    cudaGetSymbolAddress((void**)&CL,  g_CL);

    __half *OUTh, *xh, *xph, *oh, *wqeh, *wkvh, *woh, *qeh, *kvh, *EXP1;
    cudaGetSymbolAddress((void**)&OUTh, g_OUTh);
    cudaGetSymbolAddress((void**)&xh,   g_xh);
    cudaGetSymbolAddress((void**)&xph,  g_xph);
    cudaGetSymbolAddress((void**)&oh,   g_oh);
    cudaGetSymbolAddress((void**)&wqeh, g_wqeh);
    cudaGetSymbolAddress((void**)&wkvh, g_wkvh);
    cudaGetSymbolAddress((void**)&woh,  g_woh);
    cudaGetSymbolAddress((void**)&qeh,  g_qeh);
    cudaGetSymbolAddress((void**)&kvh,  g_kvh);
    cudaGetSymbolAddress((void**)&EXP1, g_EXP1);

    cudaFuncSetAttribute(gemm_f16, cudaFuncAttributeMaxDynamicSharedMemorySize, GEMM_SMEM);
    cudaFuncSetAttribute(attn_tc,  cudaFuncAttributeMaxDynamicSharedMemorySize, ATTN_SMEM);

    const int WN = Dd * Dd;            // 262144

    // ---- multi-stream fork/join (capturable; deterministic) ----
    cudaStream_t s1, s3;
    cudaStreamCreateWithFlags(&s1, cudaStreamNonBlocking);
    cudaStreamCreateWithFlags(&s3, cudaStreamNonBlocking);
    cudaEvent_t eStart, eW, eKV, eQE, eE1;
    cudaEventCreateWithFlags(&eStart, cudaEventDisableTiming);
    cudaEventCreateWithFlags(&eW,     cudaEventDisableTiming);
    cudaEventCreateWithFlags(&eKV,    cudaEventDisableTiming);
    cudaEventCreateWithFlags(&eQE,    cudaEventDisableTiming);
    cudaEventCreateWithFlags(&eE1,    cudaEventDisableTiming);

    cudaEventRecord(eStart, 0);
    cudaStreamWaitEvent(s1, eStart, 0);

    // s1: weights -> pooled x -> KV GEMM (fp16 mirror kvh)
    convert_w5<<<dim3(256, 5), 256, 0, s1>>>(Wq, We, Wk, Wv, Wo,
                                             wqeh, wqeh + WN, wkvh, wkvh + WN, woh);
    cudaEventRecord(eW, s1);
    pool_convert_kernel<<<M_POOL, 128, 0, s1>>>(x, xph);
    gemm_f16<<<dim3(8, M_POOL / 128), 256, GEMM_SMEM, s1>>>(xph, wkvh, bk, bv, KV, 1024,
                                                            kvh);
    cudaEventRecord(eKV, s1);

    // s0: x convert -> QE GEMM (fp16 mirror qeh)
    convert_f16<<<(M_BIG * Dd / 4 + 255) / 256, 256>>>(x, xh, M_BIG * Dd / 4);
    cudaStreamWaitEvent(0, eW, 0);
    gemm_f16<<<dim3(8, M_BIG / 128), 256, GEMM_SMEM>>>(xh, wqeh, bq, be, QE, 1024, qeh);
    cudaEventRecord(eQE, 0);

    // s3: external-branch e1 + colsum (parallel with attention)
    cudaStreamWaitEvent(s3, eQE, 0);
    e1_gemm<<<dim3(8, Gg), 256, 0, s3>>>(qeh, U1, EXP1);
    colsum_kernel<<<Gg, 256, 0, s3>>>(EXP1, CL);
    cudaEventRecord(eE1, s3);

    // s0: attention -> apply -> Wo GEMM
    cudaStreamWaitEvent(0, eKV, 0);
    attn_tc<<<dim3(8, Gg), 256, ATTN_SMEM>>>(qeh, kvh, adp, OUTh);
    cudaStreamWaitEvent(0, eE1, 0);
    apply_gemm<<<dim3(8, Gg), 256>>>(EXP1, U2, CL, QE, OUTh, oh);
    gemm_f16<<<dim3(4, M_BIG / 128), 256, GEMM_SMEM>>>(oh, woh, bo, bo, out, Dd, nullptr);

    // cleanup only outside capture
    cudaStreamCaptureStatus st = cudaStreamCaptureStatusNone;
    cudaStreamIsCapturing(0, &st);
    if (st == cudaStreamCaptureStatusNone) {
        cudaEventDestroy(eStart); cudaEventDestroy(eW); cudaEventDestroy(eKV);
        cudaEventDestroy(eQE);    cudaEventDestroy(eE1);
        cudaStreamDestroy(s1); cudaStreamDestroy(s3);
    }
}

// round 15
// speedup vs baseline: 2.1235x; 1.0371x over previous
#include <cuda_runtime.h>
#include <cuda_fp16.h>
#include <math.h>
#include <stdint.h>

// ---------------- problem dims ----------------
#define Bb   4
#define Tt   12
#define Nn   1024
#define Dd   512
#define Hh   8
#define hd   64
#define Cc   128
#define Ss   60
#define BT   48            // Bb*Tt
#define M_BIG  49152       // BT*Nn
#define M_POOL 6144        // BT*Cc
#define Gg   384           // BT*Hh

// ---------------- device scratch (allocation-free) ----------------
__device__ float g_CL [Gg * 64];         // 0.5 / colsum  (s padded to 64)

__device__ __half g_OUTh[M_BIG * Dd];    // attention branch output (fp16)
__device__ __half g_EXP1[(size_t)Gg * Nn * 64];  // exp(e1), [g][n][64]
__device__ __half g_qeh [M_BIG  * 1024]; // fp16 QE: [m][0:512]=q, [512:1024]=ev
__device__ __half g_kvh [M_POOL * 1024]; // fp16 KV: [c][0:512]=k, [512:1024]=v
__device__ __half g_xh  [M_BIG  * Dd];
__device__ __half g_xph [M_POOL * Dd];
__device__ __half g_oh  [M_BIG  * Dd];
__device__ __half g_wqeh[1024 * Dd];
__device__ __half g_wkvh[1024 * Dd];
__device__ __half g_woh [Dd * Dd];

// ---------------- helpers ----------------
__device__ __forceinline__ uint32_t smem_u32(const void* p) {
    uint32_t a;
    asm("{ .reg .u64 t; cvta.to.shared.u64 t, %1; cvt.u32.u64 %0, t; }" : "=r"(a) : "l"(p));
    return a;
}
#define CP_ASYNC16(dst, src) \
    asm volatile("cp.async.cg.shared.global [%0], [%1], 16;" :: "r"(dst), "l"(src) : "memory")
#define CP_COMMIT() asm volatile("cp.async.commit_group;" ::: "memory")
#define CP_WAIT2()  asm volatile("cp.async.wait_group 2;" ::: "memory")
#define CP_WAIT0()  asm volatile("cp.async.wait_group 0;" ::: "memory")
#define LDSM4(r, addr) \
    asm volatile("ldmatrix.sync.aligned.m8n8.x4.shared.b16 {%0,%1,%2,%3}, [%4];" \
        : "=r"((r)[0]), "=r"((r)[1]), "=r"((r)[2]), "=r"((r)[3]) : "r"(addr))
__device__ __forceinline__ void mma16816(float* c, const uint32_t* a,
                                         uint32_t b0, uint32_t b1) {
    asm volatile("mma.sync.aligned.m16n8k16.row.col.f32.f16.f16.f32 "
                 "{%0,%1,%2,%3}, {%4,%5,%6,%7}, {%8,%9}, {%0,%1,%2,%3};"
                 : "+f"(c[0]), "+f"(c[1]), "+f"(c[2]), "+f"(c[3])
                 : "r"(a[0]), "r"(a[1]), "r"(a[2]), "r"(a[3]), "r"(b0), "r"(b1));
}

// ---------------- conversions ----------------
__global__ void __launch_bounds__(256) convert_f16(const float* __restrict__ src,
                                                   __half* __restrict__ dst, int n4) {
    int i = blockIdx.x * 256 + threadIdx.x;
    if (i >= n4) return;
    float4 v = ((const float4*)src)[i];
    __half2* D = (__half2*)dst;
    D[2 * i]     = __floats2half2_rn(v.x, v.y);
    D[2 * i + 1] = __floats2half2_rn(v.z, v.w);
}

__global__ void __launch_bounds__(256) convert_w5(
    const float* __restrict__ s0, const float* __restrict__ s1,
    const float* __restrict__ s2, const float* __restrict__ s3,
    const float* __restrict__ s4,
    __half* __restrict__ d0, __half* __restrict__ d1, __half* __restrict__ d2,
    __half* __restrict__ d3, __half* __restrict__ d4) {
    const float* s; __half* d;
    switch (blockIdx.y) {
        case 0:  s = s0; d = d0; break;
        case 1:  s = s1; d = d1; break;
        case 2:  s = s2; d = d2; break;
        case 3:  s = s3; d = d3; break;
        default: s = s4; d = d4; break;
    }
    int i = blockIdx.x * 256 + threadIdx.x;
    float4 v = ((const float4*)s)[i];
    __half2* D = (__half2*)d;
    D[2 * i]     = __floats2half2_rn(v.x, v.y);
    D[2 * i + 1] = __floats2half2_rn(v.z, v.w);
}

__global__ void __launch_bounds__(128) pool_convert_kernel(const float* __restrict__ X,
                                                           __half* __restrict__ XH) {
    int row = blockIdx.x;
    int bt = row >> 7, c = row & 127;
    int tid = threadIdx.x;
    const float4* xr = (const float4*)(X + ((size_t)bt * Nn + (size_t)c * 8) * Dd);
    float4 s = make_float4(0.f, 0.f, 0.f, 0.f);
#pragma unroll
    for (int j = 0; j < 8; j++) {
        float4 v = xr[(size_t)j * (Dd / 4) + tid];
        s.x += v.x; s.y += v.y; s.z += v.z; s.w += v.w;
    }
    s.x *= 0.125f; s.y *= 0.125f; s.z *= 0.125f; s.w *= 0.125f;
    size_t o = (size_t)row * Dd + tid * 4;
    *(__half2*)(XH + o)     = __floats2half2_rn(s.x, s.y);
    *(__half2*)(XH + o + 2) = __floats2half2_rn(s.z, s.w);
}

// ---------------- HMMA GEMM fp16: C = Ah.Bh + bias, K=512 ----------------
// C (fp32) and FH (fp16) outputs are each optional (nullptr to skip).
#define ST_BYTES  20480
#define GEMM_SMEM (4 * ST_BYTES)
#define ROWB      80

__global__ void __launch_bounds__(256, 2)
gemm_f16(const __half* __restrict__ Ah, const __half* __restrict__ Bh,
         const float* __restrict__ bias0, const float* __restrict__ bias1,
         float* __restrict__ C, int Nout, __half* __restrict__ FH) {
    extern __shared__ __align__(1024) char smem[];
    uint32_t sb = smem_u32(smem);
    const int tid = threadIdx.x;
    const int n0 = blockIdx.x * 128;
    const int m0 = blockIdx.y * 128;
    const int l = tid & 31, w = tid >> 5;
    const int wm = w & 3, wn = w >> 2;
    const float* bias = (n0 < 512) ? bias0 : bias1;
    const int nb = (n0 < 512) ? n0 : n0 - 512;

    float acc[2][8][4];
#pragma unroll
    for (int i = 0; i < 2; i++)
#pragma unroll
        for (int j = 0; j < 8; j++)
#pragma unroll
            for (int k = 0; k < 4; k++) acc[i][j][k] = 0.f;

    auto load_stage = [&](int slot, int kc) {
        int kt = kc * 32;
        uint32_t base = sb + (uint32_t)(slot * ST_BYTES);
#pragma unroll
        for (int it = 0; it < 4; ++it) {
            int idx = tid + it * 256;
            int half = idx >> 9;
            int r = (idx >> 2) & 127, ch = idx & 3;
            uint32_t d = base + (uint32_t)(half * 10240 + r * ROWB + ch * 16);
            const __half* src = half ? (Bh + (size_t)(n0 + r) * Dd + kt + ch * 8)
                                     : (Ah + (size_t)(m0 + r) * Dd + kt + ch * 8);
            CP_ASYNC16(d, src);
        }
    };

    load_stage(0, 0); CP_COMMIT();
    load_stage(1, 1); CP_COMMIT();
    load_stage(2, 2); CP_COMMIT();

    const uint32_t lrow = (uint32_t)(l & 15) * ROWB + (uint32_t)(l >> 4) * 16;

    for (int c = 0; c < 16; ++c) {
        CP_WAIT2();
        __syncthreads();
        if (c + 3 < 16) { load_stage((c + 3) & 3, c + 3); }
        CP_COMMIT();

        uint32_t stb = sb + (uint32_t)((c & 3) * ST_BYTES);
#pragma unroll
        for (int kk = 0; kk < 2; ++kk) {
            uint32_t aoff = stb + (uint32_t)(wm * 32) * ROWB + lrow + kk * 32;
            uint32_t boff = stb + 10240 + (uint32_t)(wn * 64) * ROWB + lrow + kk * 32;
            uint32_t a[2][4], b[4][4];
            LDSM4(a[0], aoff);
            LDSM4(a[1], aoff + 16 * ROWB);
#pragma unroll
            for (int fp = 0; fp < 4; ++fp) LDSM4(b[fp], boff + fp * 16 * ROWB);
#pragma unroll
            for (int fm = 0; fm < 2; ++fm)
#pragma unroll
                for (int fp = 0; fp < 4; ++fp) {
                    mma16816(acc[fm][2 * fp],     a[fm], b[fp][0], b[fp][2]);
                    mma16816(acc[fm][2 * fp + 1], a[fm], b[fp][1], b[fp][3]);
                }
        }
    }

#pragma unroll
    for (int fm = 0; fm < 2; ++fm) {
        int mrow = m0 + wm * 32 + fm * 16 + (l >> 2);
#pragma unroll
        for (int fn = 0; fn < 8; ++fn) {
            int nc = wn * 64 + fn * 8 + (l & 3) * 2;
            float b0 = bias[nb + nc], b1 = bias[nb + nc + 1];
            float2 o0, o1;
            o0.x = acc[fm][fn][0] + b0; o0.y = acc[fm][fn][1] + b1;
            o1.x = acc[fm][fn][2] + b0; o1.y = acc[fm][fn][3] + b1;
            if (C != nullptr) {
                *(float2*)(C + (size_t)mrow * Nout + n0 + nc)       = o0;
                *(float2*)(C + (size_t)(mrow + 8) * Nout + n0 + nc) = o1;
            }
            if (FH != nullptr) {
                *(__half2*)(FH + (size_t)mrow * Nout + n0 + nc) =
                    __floats2half2_rn(o0.x, o0.y);
                *(__half2*)(FH + (size_t)(mrow + 8) * Nout + n0 + nc) =
                    __floats2half2_rn(o1.x, o1.y);
            }
        }
    }
}

// ---------------- tensor-core attention ----------------
#define EP1   144
#define EP2   272
#define AQS   0
#define AKS   18432
#define AVT   36864
#define AAD   54272
#define APS   89088
#define ARED  123904
#define ATTN_SMEM 125952

__global__ void __launch_bounds__(256, 1)
attn_tc(const __half* __restrict__ QEH, const __half* __restrict__ KVH,
        const float* __restrict__ ADP, __half* __restrict__ OUT) {
    extern __shared__ __align__(1024) char sm[];
    uint32_t sb = smem_u32(sm);
    int nt = blockIdx.x, g = blockIdx.y;
    int bt = g >> 3, hh = g & 7;
    int tid = threadIdx.x;
    int n0 = nt * 128;
    const int l = tid & 31, w = tid >> 5;
    const int wm = w & 3, wn = w >> 2;

#pragma unroll
    for (int it = 0; it < 12; ++it) {
        int idx = tid + it * 256;
        int tile = idx >> 10, j = idx & 1023;
        int r = j >> 3, ch = j & 7;
        uint32_t d;
        const __half* src;
        if (tile == 0) {
            d = sb + AQS + (uint32_t)(r * EP1 + ch * 16);
            src = QEH + ((size_t)(bt * Nn + n0 + r) * 1024 + hh * hd + ch * 8);
        } else if (tile == 1) {
            d = sb + AKS + (uint32_t)(r * EP1 + ch * 16);
            src = KVH + ((size_t)(bt * Cc + r) * 1024 + hh * hd + ch * 8);
        } else {
            d = sb + APS + (uint32_t)(r * EP1 + ch * 16);
            src = KVH + ((size_t)(bt * Cc + r) * 1024 + 512 + hh * hd + ch * 8);
        }
        CP_ASYNC16(d, src);
    }
    CP_COMMIT();
#pragma unroll
    for (int it = 0; it < 16; ++it) {
        int i = tid + it * 256;
        int r = i >> 5, c4 = i & 31;
        float4 v = *(const float4*)(ADP + (size_t)(n0 + r) * Cc + c4 * 4);
        char* p = sm + AAD + r * EP2 + c4 * 8;
        *(__half2*)p       = __floats2half2_rn(v.x, v.y);
        *(__half2*)(p + 4) = __floats2half2_rn(v.z, v.w);
    }
    CP_WAIT0();
    __syncthreads();

#pragma unroll
    for (int it = 0; it < 32; ++it) {
        int i = tid + it * 256;
        int d = i & 63, c = i >> 6;
        __half v = *(const __half*)(sm + APS + c * EP1 + d * 2);
        *(__half*)(sm + AVT + d * EP2 + c * 2) = v;
    }
    __syncthreads();

    float acc[2][8][4];
#pragma unroll
    for (int i = 0; i < 2; i++)
#pragma unroll
        for (int j = 0; j < 8; j++)
#pragma unroll
            for (int k = 0; k < 4; k++) acc[i][j][k] = 0.f;
    const uint32_t lrow1 = (uint32_t)(l & 15) * EP1 + (uint32_t)(l >> 4) * 16;
#pragma unroll
    for (int kc = 0; kc < 4; ++kc) {
        uint32_t aoff = sb + AQS + (uint32_t)(wm * 32) * EP1 + lrow1 + kc * 32;
        uint32_t boff = sb + AKS + (uint32_t)(wn * 64) * EP1 + lrow1 + kc * 32;
        uint32_t a[2][4], b[4][4];
        LDSM4(a[0], aoff);
        LDSM4(a[1], aoff + 16 * EP1);
#pragma unroll
        for (int fp = 0; fp < 4; ++fp) LDSM4(b[fp], boff + fp * 16 * EP1);
#pragma unroll
        for (int fm = 0; fm < 2; ++fm)
#pragma unroll
            for (int fp = 0; fp < 4; ++fp) {
                mma16816(acc[fm][2 * fp],     a[fm], b[fp][0], b[fp][2]);
                mma16816(acc[fm][2 * fp + 1], a[fm], b[fp][1], b[fp][3]);
            }
    }

#pragma unroll
    for (int fm = 0; fm < 2; ++fm) {
        int rbase = wm * 32 + fm * 16 + (l >> 2);
#pragma unroll
        for (int fn = 0; fn < 8; ++fn) {
            int cb = wn * 64 + fn * 8 + (l & 3) * 2;
#pragma unroll
            for (int k2 = 0; k2 < 2; ++k2) {
                int r = rbase + k2 * 8;
                float2 ad = __half22float2(*(const __half2*)(sm + AAD + r * EP2 + cb * 2));
                acc[fm][fn][2 * k2]     = acc[fm][fn][2 * k2]     * 0.125f + ad.x;
                acc[fm][fn][2 * k2 + 1] = acc[fm][fn][2 * k2 + 1] * 0.125f + ad.y;
            }
        }
    }

    float* REDm = (float*)(sm + ARED);
    float* REDs = (float*)(sm + ARED + 1024);

#pragma unroll
    for (int fm = 0; fm < 2; ++fm)
#pragma unroll
        for (int k2 = 0; k2 < 2; ++k2) {
            float m = -1e30f;
#pragma unroll
            for (int fn = 0; fn < 8; ++fn) {
                m = fmaxf(m, acc[fm][fn][2 * k2]);
                m = fmaxf(m, acc[fm][fn][2 * k2 + 1]);
            }
            m = fmaxf(m, __shfl_xor_sync(0xffffffffu, m, 1));
            m = fmaxf(m, __shfl_xor_sync(0xffffffffu, m, 2));
            if ((l & 3) == 0) {
                int r = wm * 32 + fm * 16 + (l >> 2) + k2 * 8;
                REDm[r * 2 + wn] = m;
            }
        }
    __syncthreads();
    float cmax[2][2];
#pragma unroll
    for (int fm = 0; fm < 2; ++fm)
#pragma unroll
        for (int k2 = 0; k2 < 2; ++k2) {
            int r = wm * 32 + fm * 16 + (l >> 2) + k2 * 8;
            cmax[fm][k2] = fmaxf(REDm[r * 2], REDm[r * 2 + 1]);
        }
    float rsum[2][2] = {{0.f, 0.f}, {0.f, 0.f}};
#pragma unroll
    for (int fm = 0; fm < 2; ++fm)
#pragma unroll
        for (int fn = 0; fn < 8; ++fn)
#pragma unroll
            for (int k = 0; k < 4; ++k) {
                float e = __expf(acc[fm][fn][k] - cmax[fm][k >> 1]);
                acc[fm][fn][k] = e;
                rsum[fm][k >> 1] += e;
            }
#pragma unroll
    for (int fm = 0; fm < 2; ++fm)
#pragma unroll
        for (int k2 = 0; k2 < 2; ++k2) {
            float s = rsum[fm][k2];
            s += __shfl_xor_sync(0xffffffffu, s, 1);
            s += __shfl_xor_sync(0xffffffffu, s, 2);
            if ((l & 3) == 0) {
                int r = wm * 32 + fm * 16 + (l >> 2) + k2 * 8;
                REDs[r * 2 + wn] = s;
            }
        }
    __syncthreads();
#pragma unroll
    for (int fm = 0; fm < 2; ++fm)
#pragma unroll
        for (int k2 = 0; k2 < 2; ++k2) {
            int r = wm * 32 + fm * 16 + (l >> 2) + k2 * 8;
            float inv = 1.f / (REDs[r * 2] + REDs[r * 2 + 1]);
#pragma unroll
            for (int fn = 0; fn < 8; ++fn) {
                int cb = wn * 64 + fn * 8 + (l & 3) * 2;
                *(__half2*)(sm + APS + r * EP2 + cb * 2) =
                    __floats2half2_rn(acc[fm][fn][2 * k2] * inv,
                                      acc[fm][fn][2 * k2 + 1] * inv);
            }
        }
    __syncthreads();

    float acc2[2][4][4];
#pragma unroll
    for (int i = 0; i < 2; i++)
#pragma unroll
        for (int j = 0; j < 4; j++)
#pragma unroll
            for (int k = 0; k < 4; k++) acc2[i][j][k] = 0.f;
    const uint32_t lrow2 = (uint32_t)(l & 15) * EP2 + (uint32_t)(l >> 4) * 16;
#pragma unroll
    for (int kc = 0; kc < 8; ++kc) {
        uint32_t aoff = sb + APS + (uint32_t)(wm * 32) * EP2 + lrow2 + kc * 32;
        uint32_t boff = sb + AVT + (uint32_t)(wn * 32) * EP2 + lrow2 + kc * 32;
        uint32_t a0[4], a1[4], b0[4], b1[4];
        LDSM4(a0, aoff);
        LDSM4(a1, aoff + 16 * EP2);
        LDSM4(b0, boff);
        LDSM4(b1, boff + 16 * EP2);
#pragma unroll
        for (int fm = 0; fm < 2; ++fm) {
            uint32_t* a = fm ? a1 : a0;
            mma16816(acc2[fm][0], a, b0[0], b0[2]);
            mma16816(acc2[fm][1], a, b0[1], b0[3]);
            mma16816(acc2[fm][2], a, b1[0], b1[2]);
            mma16816(acc2[fm][3], a, b1[1], b1[3]);
        }
    }
#pragma unroll
    for (int fm = 0; fm < 2; ++fm) {
        int rb = wm * 32 + fm * 16 + (l >> 2);
#pragma unroll
        for (int fn = 0; fn < 4; ++fn) {
            int d = wn * 32 + fn * 8 + (l & 3) * 2;
            size_t m0i = (size_t)(bt * Nn + n0 + rb) * Dd + hh * hd + d;
            size_t m1i = (size_t)(bt * Nn + n0 + rb + 8) * Dd + hh * hd + d;
            *(__half2*)(OUT + m0i) = __floats2half2_rn(acc2[fm][fn][0], acc2[fm][fn][1]);
            *(__half2*)(OUT + m1i) = __floats2half2_rn(acc2[fm][fn][2], acc2[fm][fn][3]);
        }
    }
}

// ---------------- external branch, tensor-core version ----------------
#define EPITCH 144

__global__ void __launch_bounds__(256) e1_gemm(const __half* __restrict__ QEH,
                                               const float* __restrict__ U1,
                                               __half* __restrict__ EXP1) {
    __shared__ __align__(16) char sm[128 * EPITCH + 64 * EPITCH];
    uint32_t sb = smem_u32(sm);
    int nt = blockIdx.x, g = blockIdx.y;
    int bt = g >> 3, h = g & 7;
    int tid = threadIdx.x;

#pragma unroll
    for (int it = 0; it < 4; ++it) {
        int idx = tid + it * 256;
        int r = idx >> 3, ch = idx & 7;
        uint32_t d = sb + (uint32_t)(r * EPITCH + ch * 16);
        CP_ASYNC16(d, QEH + ((size_t)(bt * Nn + nt * 128 + r) * 1024 + 512 + h * hd + ch * 8));
    }
    CP_COMMIT();
    char* Bsm = sm + 128 * EPITCH;
    for (int i = tid; i < 64 * 64; i += 256) {
        int s = i >> 6, d = i & 63;
        float v = (s < Ss) ? U1[d * Ss + s] : 0.f;
        *(__half*)(Bsm + s * EPITCH + d * 2) = __float2half_rn(v);
    }
    CP_WAIT0();
    __syncthreads();

    int l = tid & 31, w = tid >> 5;
    int wm = w & 3, wn = w >> 2;
    float acc[2][4][4];
#pragma unroll
    for (int i = 0; i < 2; i++)
#pragma unroll
        for (int j = 0; j < 4; j++)
#pragma unroll
            for (int k = 0; k < 4; k++) acc[i][j][k] = 0.f;

    uint32_t lrow = (uint32_t)(l & 15) * EPITCH + (uint32_t)(l >> 4) * 16;
    uint32_t Abase = sb + (uint32_t)(wm * 32) * EPITCH;
    uint32_t Bbase = sb + 128 * EPITCH + (uint32_t)(wn * 32) * EPITCH;
#pragma unroll
    for (int k = 0; k < 4; ++k) {
        uint32_t a0[4], a1[4], b0[4], b1[4];
        LDSM4(a0, Abase + lrow + k * 32);
        LDSM4(a1, Abase + 16 * EPITCH + lrow + k * 32);
        LDSM4(b0, Bbase + lrow + k * 32);
        LDSM4(b1, Bbase + 16 * EPITCH + lrow + k * 32);
#pragma unroll
        for (int fm = 0; fm < 2; ++fm) {
            uint32_t* a = fm ? a1 : a0;
            mma16816(acc[fm][0], a, b0[0], b0[2]);
            mma16816(acc[fm][1], a, b0[1], b0[3]);
            mma16816(acc[fm][2], a, b1[0], b1[2]);
            mma16816(acc[fm][3], a, b1[1], b1[3]);
        }
    }
    int baseN = nt * 128 + wm * 32 + (l >> 2);
#pragma unroll
    for (int fm = 0; fm < 2; ++fm) {
        int n = baseN + fm * 16;
#pragma unroll
        for (int fn = 0; fn < 4; ++fn) {
            int s = wn * 32 + fn * 8 + (l & 3) * 2;
            bool ok = (s < Ss);
            float v0 = ok ? __expf(fminf(acc[fm][fn][0], 11.f)) : 0.f;
            float v1 = ok ? __expf(fminf(acc[fm][fn][1], 11.f)) : 0.f;
            float v2 = ok ? __expf(fminf(acc[fm][fn][2], 11.f)) : 0.f;
            float v3 = ok ? __expf(fminf(acc[fm][fn][3], 11.f)) : 0.f;
            *(__half2*)(EXP1 + ((size_t)g * Nn + n) * 64 + s)     = __floats2half2_rn(v0, v1);
            *(__half2*)(EXP1 + ((size_t)g * Nn + n + 8) * 64 + s) = __floats2half2_rn(v2, v3);
        }
    }
}

__global__ void __launch_bounds__(256) colsum_kernel(const __half* __restrict__ EXP1,
                                                     float* __restrict__ CL) {
    __shared__ float red[4][64];
    int g = blockIdx.x;
    int tid = threadIdx.x;
    int s = tid & 63, lane = tid >> 6;
    float sum = 0.f;
    const __half* base = EXP1 + (size_t)g * Nn * 64 + s;
    for (int n = lane; n < Nn; n += 4)
        sum += __half2float(base[(size_t)n * 64]);
    red[lane][s] = sum;
    __syncthreads();
    if (tid < 64) {
        float t = red[0][tid] + red[1][tid] + red[2][tid] + red[3][tid];
        CL[g * 64 + tid] = 0.5f / fmaxf(t, 1e-30f);
    }
}

__global__ void __launch_bounds__(256) apply_gemm(const __half* __restrict__ EXP1,
                                                  const float* __restrict__ U2,
                                                  const float* __restrict__ CL,
                                                  const __half* __restrict__ EVH,
                                                  const __half* __restrict__ OUT,
                                                  __half* __restrict__ OH) {
    __shared__ __align__(16) char sm[128 * EPITCH + 64 * EPITCH];
    __shared__ float rls[64];
    uint32_t sb = smem_u32(sm);
    int nt = blockIdx.x, g = blockIdx.y;
    int bt = g >> 3, h = g & 7;
    int tid = threadIdx.x;

#pragma unroll
    for (int it = 0; it < 4; ++it) {
        int idx = tid + it * 256;
        int r = idx >> 3, ch = idx & 7;
        uint32_t d = sb + (uint32_t)(r * EPITCH + ch * 16);
        CP_ASYNC16(d, EXP1 + ((size_t)g * Nn + nt * 128 + r) * 64 + ch * 8);
    }
    CP_COMMIT();
    if (tid < 64) rls[tid] = CL[g * 64 + tid];
    __syncthreads();
    char* Bsm = sm + 128 * EPITCH;
    for (int i = tid; i < 64 * 64; i += 256) {
        int d = i >> 6, s = i & 63;
        float v = (s < Ss) ? U2[s * hd + d] * rls[s] : 0.f;
        *(__half*)(Bsm + d * EPITCH + s * 2) = __float2half_rn(v);
    }
    CP_WAIT0();
    __syncthreads();

    int l = tid & 31, w = tid >> 5;
    int wm = w & 3, wn = w >> 2;
    float acc[2][4][4];
#pragma unroll
    for (int i = 0; i < 2; i++)
#pragma unroll
        for (int j = 0; j < 4; j++)
#pragma unroll
            for (int k = 0; k < 4; k++) acc[i][j][k] = 0.f;

    uint32_t lrow = (uint32_t)(l & 15) * EPITCH + (uint32_t)(l >> 4) * 16;
    uint32_t Abase = sb + (uint32_t)(wm * 32) * EPITCH;
    uint32_t Bbase = sb + 128 * EPITCH + (uint32_t)(wn * 32) * EPITCH;
#pragma unroll
    for (int k = 0; k < 4; ++k) {
        uint32_t a0[4], a1[4], b0[4], b1[4];
        LDSM4(a0, Abase + lrow + k * 32);
        LDSM4(a1, Abase + 16 * EPITCH + lrow + k * 32);
        LDSM4(b0, Bbase + lrow + k * 32);
        LDSM4(b1, Bbase + 16 * EPITCH + lrow + k * 32);
#pragma unroll
        for (int fm = 0; fm < 2; ++fm) {
            uint32_t* a = fm ? a1 : a0;
            mma16816(acc[fm][0], a, b0[0], b0[2]);
            mma16816(acc[fm][1], a, b0[1], b0[3]);
            mma16816(acc[fm][2], a, b1[0], b1[2]);
            mma16816(acc[fm][3], a, b1[1], b1[3]);
        }
    }
    int baseN = nt * 128 + wm * 32 + (l >> 2);
#pragma unroll
    for (int fm = 0; fm < 2; ++fm) {
        int n = baseN + fm * 16;
#pragma unroll
        for (int fn = 0; fn < 4; ++fn) {
            int d = wn * 32 + fn * 8 + (l & 3) * 2;
            size_t m0i = (size_t)bt * Nn + n;
            size_t m1i = m0i + 8;
            float2 ov0 = __half22float2(*(const __half2*)(OUT + m0i * Dd + h * hd + d));
            float2 ov1 = __half22float2(*(const __half2*)(OUT + m1i * Dd + h * hd + d));
            float2 ev0 = __half22float2(*(const __half2*)(EVH + m0i * 1024 + 512 + h * hd + d));
            float2 ev1 = __half22float2(*(const __half2*)(EVH + m1i * 1024 + 512 + h * hd + d));
            *(__half2*)(OH + m0i * Dd + h * hd + d) =
                __floats2half2_rn(acc[fm][fn][0] + ov0.x + ev0.x,
                                  acc[fm][fn][1] + ov0.y + ev0.y);
            *(__half2*)(OH + m1i * Dd + h * hd + d) =
                __floats2half2_rn(acc[fm][fn][2] + ov1.x + ev1.x,
                                  acc[fm][fn][3] + ov1.y + ev1.y);
        }
    }
}

// ---------------- launch ----------------
extern "C" void kernel_launch(void* const* d_in, const int* in_sizes, int n_in,
                              void* d_out, int out_size) {
    const float* x   = (const float*)d_in[0];
    const float* Wq  = (const float*)d_in[1];
    const float* bq  = (const float*)d_in[2];
    const float* Wk  = (const float*)d_in[3];
    const float* bk  = (const float*)d_in[4];
    const float* Wv  = (const float*)d_in[5];
    const float* bv  = (const float*)d_in[6];
    const float* We  = (const float*)d_in[7];
    const float* be  = (const float*)d_in[8];
    const float* Wo  = (const float*)d_in[9];
    const float* bo  = (const float*)d_in[10];
    const float* adp = (const float*)d_in[11];
    const float* U1  = (const float*)d_in[12];
    const float* U2  = (const float*)d_in[13];
    float* out = (float*)d_out;

    float* CL;
    cudaGetSymbolAddress((void**)&CL,  g_CL);

    __half *OUTh, *xh, *xph, *oh, *wqeh, *wkvh, *woh, *qeh, *kvh, *EXP1;
    cudaGetSymbolAddress((void**)&OUTh, g_OUTh);
    cudaGetSymbolAddress((void**)&xh,   g_xh);
    cudaGetSymbolAddress((void**)&xph,  g_xph);
    cudaGetSymbolAddress((void**)&oh,   g_oh);
    cudaGetSymbolAddress((void**)&wqeh, g_wqeh);
    cudaGetSymbolAddress((void**)&wkvh, g_wkvh);
    cudaGetSymbolAddress((void**)&woh,  g_woh);
    cudaGetSymbolAddress((void**)&qeh,  g_qeh);
    cudaGetSymbolAddress((void**)&kvh,  g_kvh);
    cudaGetSymbolAddress((void**)&EXP1, g_EXP1);

    cudaFuncSetAttribute(gemm_f16, cudaFuncAttributeMaxDynamicSharedMemorySize, GEMM_SMEM);
    cudaFuncSetAttribute(attn_tc,  cudaFuncAttributeMaxDynamicSharedMemorySize, ATTN_SMEM);

    const int WN = Dd * Dd;            // 262144

    // ---- multi-stream fork/join (capturable; deterministic) ----
    cudaStream_t s1, s3;
    cudaStreamCreateWithFlags(&s1, cudaStreamNonBlocking);
    cudaStreamCreateWithFlags(&s3, cudaStreamNonBlocking);
    cudaEvent_t eStart, eW, eKV, eQE, eE1;
    cudaEventCreateWithFlags(&eStart, cudaEventDisableTiming);
    cudaEventCreateWithFlags(&eW,     cudaEventDisableTiming);
    cudaEventCreateWithFlags(&eKV,    cudaEventDisableTiming);
    cudaEventCreateWithFlags(&eQE,    cudaEventDisableTiming);
    cudaEventCreateWithFlags(&eE1,    cudaEventDisableTiming);

    cudaEventRecord(eStart, 0);
    cudaStreamWaitEvent(s1, eStart, 0);

    // s1: weights -> pooled x -> KV GEMM (fp16 only)
    convert_w5<<<dim3(256, 5), 256, 0, s1>>>(Wq, We, Wk, Wv, Wo,
                                             wqeh, wqeh + WN, wkvh, wkvh + WN, woh);
    cudaEventRecord(eW, s1);
    pool_convert_kernel<<<M_POOL, 128, 0, s1>>>(x, xph);
    gemm_f16<<<dim3(8, M_POOL / 128), 256, GEMM_SMEM, s1>>>(xph, wkvh, bk, bv,
                                                            nullptr, 1024, kvh);
    cudaEventRecord(eKV, s1);

    // s0: x convert -> QE GEMM (fp16 only)
    convert_f16<<<(M_BIG * Dd / 4 + 255) / 256, 256>>>(x, xh, M_BIG * Dd / 4);
    cudaStreamWaitEvent(0, eW, 0);
    gemm_f16<<<dim3(8, M_BIG / 128), 256, GEMM_SMEM>>>(xh, wqeh, bq, be,
                                                       nullptr, 1024, qeh);
    cudaEventRecord(eQE, 0);

    // s3: external-branch e1 + colsum (parallel with attention)
    cudaStreamWaitEvent(s3, eQE, 0);
    e1_gemm<<<dim3(8, Gg), 256, 0, s3>>>(qeh, U1, EXP1);
    colsum_kernel<<<Gg, 256, 0, s3>>>(EXP1, CL);
    cudaEventRecord(eE1, s3);

    // s0: attention -> apply -> Wo GEMM
    cudaStreamWaitEvent(0, eKV, 0);
    attn_tc<<<dim3(8, Gg), 256, ATTN_SMEM>>>(qeh, kvh, adp, OUTh);
    cudaStreamWaitEvent(0, eE1, 0);
    apply_gemm<<<dim3(8, Gg), 256>>>(EXP1, U2, CL, qeh, OUTh, oh);
    gemm_f16<<<dim3(4, M_BIG / 128), 256, GEMM_SMEM>>>(oh, woh, bo, bo, out, Dd, nullptr);

    // cleanup only outside capture
    cudaStreamCaptureStatus st = cudaStreamCaptureStatusNone;
    cudaStreamIsCapturing(0, &st);
    if (st == cudaStreamCaptureStatusNone) {
        cudaEventDestroy(eStart); cudaEventDestroy(eW); cudaEventDestroy(eKV);
        cudaEventDestroy(eQE);    cudaEventDestroy(eE1);
        cudaStreamDestroy(s1); cudaStreamDestroy(s3);
    }
}

// round 16
// speedup vs baseline: 2.1799x; 1.0266x over previous
#include <cuda_runtime.h>
#include <cuda_fp16.h>
#include <math.h>
#include <stdint.h>

// ---------------- problem dims ----------------
#define Bb   4
#define Tt   12
#define Nn   1024
#define Dd   512
#define Hh   8
#define hd   64
#define Cc   128
#define Ss   60
#define BT   48            // Bb*Tt
#define M_BIG  49152       // BT*Nn
#define M_POOL 6144        // BT*Cc
#define Gg   384           // BT*Hh

// ---------------- device scratch (allocation-free) ----------------
__device__ float g_CL [Gg * 64];         // 0.5 / colsum  (s padded to 64)

__device__ __half g_OUTh[M_BIG * Dd];    // attention branch output (fp16)
__device__ __half g_EXP1[(size_t)Gg * Nn * 64];  // exp(e1), [g][n][64]
__device__ __half g_qeh [M_BIG  * 1024]; // fp16 QE: [m][0:512]=q, [512:1024]=ev
__device__ __half g_kvh [M_POOL * 1024]; // fp16 KV: [c][0:512]=k, [512:1024]=v
__device__ __half g_xh  [M_BIG  * Dd];
__device__ __half g_xph [M_POOL * Dd];
__device__ __half g_oh  [M_BIG  * Dd];
__device__ __half g_wqeh[1024 * Dd];
__device__ __half g_wkvh[1024 * Dd];
__device__ __half g_woh [Dd * Dd];

// ---------------- helpers ----------------
__device__ __forceinline__ uint32_t smem_u32(const void* p) {
    uint32_t a;
    asm("{ .reg .u64 t; cvta.to.shared.u64 t, %1; cvt.u32.u64 %0, t; }" : "=r"(a) : "l"(p));
    return a;
}
#define CP_ASYNC16(dst, src) \
    asm volatile("cp.async.cg.shared.global [%0], [%1], 16;" :: "r"(dst), "l"(src) : "memory")
#define CP_COMMIT() asm volatile("cp.async.commit_group;" ::: "memory")
#define CP_WAIT2()  asm volatile("cp.async.wait_group 2;" ::: "memory")
#define CP_WAIT0()  asm volatile("cp.async.wait_group 0;" ::: "memory")
#define LDSM4(r, addr) \
    asm volatile("ldmatrix.sync.aligned.m8n8.x4.shared.b16 {%0,%1,%2,%3}, [%4];" \
        : "=r"((r)[0]), "=r"((r)[1]), "=r"((r)[2]), "=r"((r)[3]) : "r"(addr))
__device__ __forceinline__ void mma16816(float* c, const uint32_t* a,
                                         uint32_t b0, uint32_t b1) {
    asm volatile("mma.sync.aligned.m16n8k16.row.col.f32.f16.f16.f32 "
                 "{%0,%1,%2,%3}, {%4,%5,%6,%7}, {%8,%9}, {%0,%1,%2,%3};"
                 : "+f"(c[0]), "+f"(c[1]), "+f"(c[2]), "+f"(c[3])
                 : "r"(a[0]), "r"(a[1]), "r"(a[2]), "r"(a[3]), "r"(b0), "r"(b1));
}

// ---------------- conversions ----------------
__global__ void __launch_bounds__(256) convert_f16(const float* __restrict__ src,
                                                   __half* __restrict__ dst, int n4) {
    int i = blockIdx.x * 256 + threadIdx.x;
    if (i >= n4) return;
    float4 v = ((const float4*)src)[i];
    __half2* D = (__half2*)dst;
    D[2 * i]     = __floats2half2_rn(v.x, v.y);
    D[2 * i + 1] = __floats2half2_rn(v.z, v.w);
}

__global__ void __launch_bounds__(256) convert_w5(
    const float* __restrict__ s0, const float* __restrict__ s1,
    const float* __restrict__ s2, const float* __restrict__ s3,
    const float* __restrict__ s4,
    __half* __restrict__ d0, __half* __restrict__ d1, __half* __restrict__ d2,
    __half* __restrict__ d3, __half* __restrict__ d4) {
    const float* s; __half* d;
    switch (blockIdx.y) {
        case 0:  s = s0; d = d0; break;
        case 1:  s = s1; d = d1; break;
        case 2:  s = s2; d = d2; break;
        case 3:  s = s3; d = d3; break;
        default: s = s4; d = d4; break;
    }
    int i = blockIdx.x * 256 + threadIdx.x;
    float4 v = ((const float4*)s)[i];
    __half2* D = (__half2*)d;
    D[2 * i]     = __floats2half2_rn(v.x, v.y);
    D[2 * i + 1] = __floats2half2_rn(v.z, v.w);
}

__global__ void __launch_bounds__(128) pool_convert_kernel(const float* __restrict__ X,
                                                           __half* __restrict__ XH) {
    int row = blockIdx.x;
    int bt = row >> 7, c = row & 127;
    int tid = threadIdx.x;
    const float4* xr = (const float4*)(X + ((size_t)bt * Nn + (size_t)c * 8) * Dd);
    float4 s = make_float4(0.f, 0.f, 0.f, 0.f);
#pragma unroll
    for (int j = 0; j < 8; j++) {
        float4 v = xr[(size_t)j * (Dd / 4) + tid];
        s.x += v.x; s.y += v.y; s.z += v.z; s.w += v.w;
    }
    s.x *= 0.125f; s.y *= 0.125f; s.z *= 0.125f; s.w *= 0.125f;
    size_t o = (size_t)row * Dd + tid * 4;
    *(__half2*)(XH + o)     = __floats2half2_rn(s.x, s.y);
    *(__half2*)(XH + o + 2) = __floats2half2_rn(s.z, s.w);
}

// ---------------- HMMA GEMM fp16: C = Ah.Bh + bias, K=512 ----------------
#define ST_BYTES  20480
#define GEMM_SMEM (4 * ST_BYTES)
#define ROWB      80

__global__ void __launch_bounds__(256, 2)
gemm_f16(const __half* __restrict__ Ah, const __half* __restrict__ Bh,
         const float* __restrict__ bias0, const float* __restrict__ bias1,
         float* __restrict__ C, int Nout, __half* __restrict__ FH) {
    extern __shared__ __align__(1024) char smem[];
    uint32_t sb = smem_u32(smem);
    const int tid = threadIdx.x;
    const int n0 = blockIdx.x * 128;
    const int m0 = blockIdx.y * 128;
    const int l = tid & 31, w = tid >> 5;
    const int wm = w & 3, wn = w >> 2;
    const float* bias = (n0 < 512) ? bias0 : bias1;
    const int nb = (n0 < 512) ? n0 : n0 - 512;

    float acc[2][8][4];
#pragma unroll
    for (int i = 0; i < 2; i++)
#pragma unroll
        for (int j = 0; j < 8; j++)
#pragma unroll
            for (int k = 0; k < 4; k++) acc[i][j][k] = 0.f;

    auto load_stage = [&](int slot, int kc) {
        int kt = kc * 32;
        uint32_t base = sb + (uint32_t)(slot * ST_BYTES);
#pragma unroll
        for (int it = 0; it < 4; ++it) {
            int idx = tid + it * 256;
            int half = idx >> 9;
            int r = (idx >> 2) & 127, ch = idx & 3;
            uint32_t d = base + (uint32_t)(half * 10240 + r * ROWB + ch * 16);
            const __half* src = half ? (Bh + (size_t)(n0 + r) * Dd + kt + ch * 8)
                                     : (Ah + (size_t)(m0 + r) * Dd + kt + ch * 8);
            CP_ASYNC16(d, src);
        }
    };

    load_stage(0, 0); CP_COMMIT();
    load_stage(1, 1); CP_COMMIT();
    load_stage(2, 2); CP_COMMIT();

    const uint32_t lrow = (uint32_t)(l & 15) * ROWB + (uint32_t)(l >> 4) * 16;

    for (int c = 0; c < 16; ++c) {
        CP_WAIT2();
        __syncthreads();
        if (c + 3 < 16) { load_stage((c + 3) & 3, c + 3); }
        CP_COMMIT();

        uint32_t stb = sb + (uint32_t)((c & 3) * ST_BYTES);
#pragma unroll
        for (int kk = 0; kk < 2; ++kk) {
            uint32_t aoff = stb + (uint32_t)(wm * 32) * ROWB + lrow + kk * 32;
            uint32_t boff = stb + 10240 + (uint32_t)(wn * 64) * ROWB + lrow + kk * 32;
            uint32_t a[2][4], b[4][4];
            LDSM4(a[0], aoff);
            LDSM4(a[1], aoff + 16 * ROWB);
#pragma unroll
            for (int fp = 0; fp < 4; ++fp) LDSM4(b[fp], boff + fp * 16 * ROWB);
#pragma unroll
            for (int fm = 0; fm < 2; ++fm)
#pragma unroll
                for (int fp = 0; fp < 4; ++fp) {
                    mma16816(acc[fm][2 * fp],     a[fm], b[fp][0], b[fp][2]);
                    mma16816(acc[fm][2 * fp + 1], a[fm], b[fp][1], b[fp][3]);
                }
        }
    }

#pragma unroll
    for (int fm = 0; fm < 2; ++fm) {
        int mrow = m0 + wm * 32 + fm * 16 + (l >> 2);
#pragma unroll
        for (int fn = 0; fn < 8; ++fn) {
            int nc = wn * 64 + fn * 8 + (l & 3) * 2;
            float b0 = bias[nb + nc], b1 = bias[nb + nc + 1];
            float2 o0, o1;
            o0.x = acc[fm][fn][0] + b0; o0.y = acc[fm][fn][1] + b1;
            o1.x = acc[fm][fn][2] + b0; o1.y = acc[fm][fn][3] + b1;
            if (C != nullptr) {
                *(float2*)(C + (size_t)mrow * Nout + n0 + nc)       = o0;
                *(float2*)(C + (size_t)(mrow + 8) * Nout + n0 + nc) = o1;
            }
            if (FH != nullptr) {
                *(__half2*)(FH + (size_t)mrow * Nout + n0 + nc) =
                    __floats2half2_rn(o0.x, o0.y);
                *(__half2*)(FH + (size_t)(mrow + 8) * Nout + n0 + nc) =
                    __floats2half2_rn(o1.x, o1.y);
            }
        }
    }
}

// ---------------- tensor-core attention (2 CTAs/SM; adp read from L2) -----
#define EP1   144
#define EP2   272
#define AQS   0
#define AKS   18432
#define AVT   36864                  // Vt: 64 x EP2
#define APS   54272                  // P: 128 x EP2 (also V staging 128 x EP1)
#define ARED  89088                  // float[2][128][2]
#define ATTN_SMEM 91136

__global__ void __launch_bounds__(256, 2)
attn_tc(const __half* __restrict__ QEH, const __half* __restrict__ KVH,
        const float* __restrict__ ADP, __half* __restrict__ OUT) {
    extern __shared__ __align__(1024) char sm[];
    uint32_t sb = smem_u32(sm);
    int nt = blockIdx.x, g = blockIdx.y;
    int bt = g >> 3, hh = g & 7;
    int tid = threadIdx.x;
    int n0 = nt * 128;
    const int l = tid & 31, w = tid >> 5;
    const int wm = w & 3, wn = w >> 2;

#pragma unroll
    for (int it = 0; it < 12; ++it) {
        int idx = tid + it * 256;
        int tile = idx >> 10, j = idx & 1023;
        int r = j >> 3, ch = j & 7;
        uint32_t d;
        const __half* src;
        if (tile == 0) {
            d = sb + AQS + (uint32_t)(r * EP1 + ch * 16);
            src = QEH + ((size_t)(bt * Nn + n0 + r) * 1024 + hh * hd + ch * 8);
        } else if (tile == 1) {
            d = sb + AKS + (uint32_t)(r * EP1 + ch * 16);
            src = KVH + ((size_t)(bt * Cc + r) * 1024 + hh * hd + ch * 8);
        } else {
            d = sb + APS + (uint32_t)(r * EP1 + ch * 16);
            src = KVH + ((size_t)(bt * Cc + r) * 1024 + 512 + hh * hd + ch * 8);
        }
        CP_ASYNC16(d, src);
    }
    CP_COMMIT();
    CP_WAIT0();
    __syncthreads();

    // transpose V staging [c][d] -> Vt [d][c]
#pragma unroll
    for (int it = 0; it < 32; ++it) {
        int i = tid + it * 256;
        int d = i & 63, c = i >> 6;
        __half v = *(const __half*)(sm + APS + c * EP1 + d * 2);
        *(__half*)(sm + AVT + d * EP2 + c * 2) = v;
    }
    __syncthreads();

    // MMA1: S = Q.K^T (K-dim 64)
    float acc[2][8][4];
#pragma unroll
    for (int i = 0; i < 2; i++)
#pragma unroll
        for (int j = 0; j < 8; j++)
#pragma unroll
            for (int k = 0; k < 4; k++) acc[i][j][k] = 0.f;
    const uint32_t lrow1 = (uint32_t)(l & 15) * EP1 + (uint32_t)(l >> 4) * 16;
#pragma unroll
    for (int kc = 0; kc < 4; ++kc) {
        uint32_t aoff = sb + AQS + (uint32_t)(wm * 32) * EP1 + lrow1 + kc * 32;
        uint32_t boff = sb + AKS + (uint32_t)(wn * 64) * EP1 + lrow1 + kc * 32;
        uint32_t a[2][4], b[4][4];
        LDSM4(a[0], aoff);
        LDSM4(a[1], aoff + 16 * EP1);
#pragma unroll
        for (int fp = 0; fp < 4; ++fp) LDSM4(b[fp], boff + fp * 16 * EP1);
#pragma unroll
        for (int fm = 0; fm < 2; ++fm)
#pragma unroll
            for (int fp = 0; fp < 4; ++fp) {
                mma16816(acc[fm][2 * fp],     a[fm], b[fp][0], b[fp][2]);
                mma16816(acc[fm][2 * fp + 1], a[fm], b[fp][1], b[fp][3]);
            }
    }

    // scale + adp (adp read directly: L2-resident, shared across all g/bt)
#pragma unroll
    for (int fm = 0; fm < 2; ++fm) {
        int rbase = wm * 32 + fm * 16 + (l >> 2);
#pragma unroll
        for (int fn = 0; fn < 8; ++fn) {
            int cb = wn * 64 + fn * 8 + (l & 3) * 2;
#pragma unroll
            for (int k2 = 0; k2 < 2; ++k2) {
                int r = rbase + k2 * 8;
                float2 ad = *(const float2*)(ADP + (size_t)(n0 + r) * Cc + cb);
                acc[fm][fn][2 * k2]     = acc[fm][fn][2 * k2]     * 0.125f + ad.x;
                acc[fm][fn][2 * k2 + 1] = acc[fm][fn][2 * k2 + 1] * 0.125f + ad.y;
            }
        }
    }

    float* REDm = (float*)(sm + ARED);
    float* REDs = (float*)(sm + ARED + 1024);

#pragma unroll
    for (int fm = 0; fm < 2; ++fm)
#pragma unroll
        for (int k2 = 0; k2 < 2; ++k2) {
            float m = -1e30f;
#pragma unroll
            for (int fn = 0; fn < 8; ++fn) {
                m = fmaxf(m, acc[fm][fn][2 * k2]);
                m = fmaxf(m, acc[fm][fn][2 * k2 + 1]);
            }
            m = fmaxf(m, __shfl_xor_sync(0xffffffffu, m, 1));
            m = fmaxf(m, __shfl_xor_sync(0xffffffffu, m, 2));
            if ((l & 3) == 0) {
                int r = wm * 32 + fm * 16 + (l >> 2) + k2 * 8;
                REDm[r * 2 + wn] = m;
            }
        }
    __syncthreads();
    float cmax[2][2];
#pragma unroll
    for (int fm = 0; fm < 2; ++fm)
#pragma unroll
        for (int k2 = 0; k2 < 2; ++k2) {
            int r = wm * 32 + fm * 16 + (l >> 2) + k2 * 8;
            cmax[fm][k2] = fmaxf(REDm[r * 2], REDm[r * 2 + 1]);
        }
    float rsum[2][2] = {{0.f, 0.f}, {0.f, 0.f}};
#pragma unroll
    for (int fm = 0; fm < 2; ++fm)
#pragma unroll
        for (int fn = 0; fn < 8; ++fn)
#pragma unroll
            for (int k = 0; k < 4; ++k) {
                float e = __expf(acc[fm][fn][k] - cmax[fm][k >> 1]);
                acc[fm][fn][k] = e;
                rsum[fm][k >> 1] += e;
            }
#pragma unroll
    for (int fm = 0; fm < 2; ++fm)
#pragma unroll
        for (int k2 = 0; k2 < 2; ++k2) {
            float s = rsum[fm][k2];
            s += __shfl_xor_sync(0xffffffffu, s, 1);
            s += __shfl_xor_sync(0xffffffffu, s, 2);
            if ((l & 3) == 0) {
                int r = wm * 32 + fm * 16 + (l >> 2) + k2 * 8;
                REDs[r * 2 + wn] = s;
            }
        }
    __syncthreads();
#pragma unroll
    for (int fm = 0; fm < 2; ++fm)
#pragma unroll
        for (int k2 = 0; k2 < 2; ++k2) {
            int r = wm * 32 + fm * 16 + (l >> 2) + k2 * 8;
            float inv = 1.f / (REDs[r * 2] + REDs[r * 2 + 1]);
#pragma unroll
            for (int fn = 0; fn < 8; ++fn) {
                int cb = wn * 64 + fn * 8 + (l & 3) * 2;
                *(__half2*)(sm + APS + r * EP2 + cb * 2) =
                    __floats2half2_rn(acc[fm][fn][2 * k2] * inv,
                                      acc[fm][fn][2 * k2 + 1] * inv);
            }
        }
    __syncthreads();

    // MMA2: O = P.Vt (K-dim 128)
    float acc2[2][4][4];
#pragma unroll
    for (int i = 0; i < 2; i++)
#pragma unroll
        for (int j = 0; j < 4; j++)
#pragma unroll
            for (int k = 0; k < 4; k++) acc2[i][j][k] = 0.f;
    const uint32_t lrow2 = (uint32_t)(l & 15) * EP2 + (uint32_t)(l >> 4) * 16;
#pragma unroll
    for (int kc = 0; kc < 8; ++kc) {
        uint32_t aoff = sb + APS + (uint32_t)(wm * 32) * EP2 + lrow2 + kc * 32;
        uint32_t boff = sb + AVT + (uint32_t)(wn * 32) * EP2 + lrow2 + kc * 32;
        uint32_t a0[4], a1[4], b0[4], b1[4];
        LDSM4(a0, aoff);
        LDSM4(a1, aoff + 16 * EP2);
        LDSM4(b0, boff);
        LDSM4(b1, boff + 16 * EP2);
#pragma unroll
        for (int fm = 0; fm < 2; ++fm) {
            uint32_t* a = fm ? a1 : a0;
            mma16816(acc2[fm][0], a, b0[0], b0[2]);
            mma16816(acc2[fm][1], a, b0[1], b0[3]);
            mma16816(acc2[fm][2], a, b1[0], b1[2]);
            mma16816(acc2[fm][3], a, b1[1], b1[3]);
        }
    }
#pragma unroll
    for (int fm = 0; fm < 2; ++fm) {
        int rb = wm * 32 + fm * 16 + (l >> 2);
#pragma unroll
        for (int fn = 0; fn < 4; ++fn) {
            int d = wn * 32 + fn * 8 + (l & 3) * 2;
            size_t m0i = (size_t)(bt * Nn + n0 + rb) * Dd + hh * hd + d;
            size_t m1i = (size_t)(bt * Nn + n0 + rb + 8) * Dd + hh * hd + d;
            *(__half2*)(OUT + m0i) = __floats2half2_rn(acc2[fm][fn][0], acc2[fm][fn][1]);
            *(__half2*)(OUT + m1i) = __floats2half2_rn(acc2[fm][fn][2], acc2[fm][fn][3]);
        }
    }
}

// ---------------- external branch, tensor-core version ----------------
#define EPITCH 144

__global__ void __launch_bounds__(256) e1_gemm(const __half* __restrict__ QEH,
                                               const float* __restrict__ U1,
                                               __half* __restrict__ EXP1) {
    __shared__ __align__(16) char sm[128 * EPITCH + 64 * EPITCH];
    uint32_t sb = smem_u32(sm);
    int nt = blockIdx.x, g = blockIdx.y;
    int bt = g >> 3, h = g & 7;
    int tid = threadIdx.x;

#pragma unroll
    for (int it = 0; it < 4; ++it) {
        int idx = tid + it * 256;
        int r = idx >> 3, ch = idx & 7;
        uint32_t d = sb + (uint32_t)(r * EPITCH + ch * 16);
        CP_ASYNC16(d, QEH + ((size_t)(bt * Nn + nt * 128 + r) * 1024 + 512 + h * hd + ch * 8));
    }
    CP_COMMIT();
    char* Bsm = sm + 128 * EPITCH;
    for (int i = tid; i < 64 * 64; i += 256) {
        int s = i >> 6, d = i & 63;
        float v = (s < Ss) ? U1[d * Ss + s] : 0.f;
        *(__half*)(Bsm + s * EPITCH + d * 2) = __float2half_rn(v);
    }
    CP_WAIT0();
    __syncthreads();

    int l = tid & 31, w = tid >> 5;
    int wm = w & 3, wn = w >> 2;
    float acc[2][4][4];
#pragma unroll
    for (int i = 0; i < 2; i++)
#pragma unroll
        for (int j = 0; j < 4; j++)
#pragma unroll
            for (int k = 0; k < 4; k++) acc[i][j][k] = 0.f;

    uint32_t lrow = (uint32_t)(l & 15) * EPITCH + (uint32_t)(l >> 4) * 16;
    uint32_t Abase = sb + (uint32_t)(wm * 32) * EPITCH;
    uint32_t Bbase = sb + 128 * EPITCH + (uint32_t)(wn * 32) * EPITCH;
#pragma unroll
    for (int k = 0; k < 4; ++k) {
        uint32_t a0[4], a1[4], b0[4], b1[4];
        LDSM4(a0, Abase + lrow + k * 32);
        LDSM4(a1, Abase + 16 * EPITCH + lrow + k * 32);
        LDSM4(b0, Bbase + lrow + k * 32);
        LDSM4(b1, Bbase + 16 * EPITCH + lrow + k * 32);
#pragma unroll
        for (int fm = 0; fm < 2; ++fm) {
            uint32_t* a = fm ? a1 : a0;
            mma16816(acc[fm][0], a, b0[0], b0[2]);
            mma16816(acc[fm][1], a, b0[1], b0[3]);
            mma16816(acc[fm][2], a, b1[0], b1[2]);
            mma16816(acc[fm][3], a, b1[1], b1[3]);
        }
    }
    int baseN = nt * 128 + wm * 32 + (l >> 2);
#pragma unroll
    for (int fm = 0; fm < 2; ++fm) {
        int n = baseN + fm * 16;
#pragma unroll
        for (int fn = 0; fn < 4; ++fn) {
            int s = wn * 32 + fn * 8 + (l & 3) * 2;
            bool ok = (s < Ss);
            float v0 = ok ? __expf(fminf(acc[fm][fn][0], 11.f)) : 0.f;
            float v1 = ok ? __expf(fminf(acc[fm][fn][1], 11.f)) : 0.f;
            float v2 = ok ? __expf(fminf(acc[fm][fn][2], 11.f)) : 0.f;
            float v3 = ok ? __expf(fminf(acc[fm][fn][3], 11.f)) : 0.f;
            *(__half2*)(EXP1 + ((size_t)g * Nn + n) * 64 + s)     = __floats2half2_rn(v0, v1);
            *(__half2*)(EXP1 + ((size_t)g * Nn + n + 8) * 64 + s) = __floats2half2_rn(v2, v3);
        }
    }
}

__global__ void __launch_bounds__(256) colsum_kernel(const __half* __restrict__ EXP1,
                                                     float* __restrict__ CL) {
    __shared__ float red[4][64];
    int g = blockIdx.x;
    int tid = threadIdx.x;
    int s = tid & 63, lane = tid >> 6;
    float sum = 0.f;
    const __half* base = EXP1 + (size_t)g * Nn * 64 + s;
    for (int n = lane; n < Nn; n += 4)
        sum += __half2float(base[(size_t)n * 64]);
    red[lane][s] = sum;
    __syncthreads();
    if (tid < 64) {
        float t = red[0][tid] + red[1][tid] + red[2][tid] + red[3][tid];
        CL[g * 64 + tid] = 0.5f / fmaxf(t, 1e-30f);
    }
}

__global__ void __launch_bounds__(256) apply_gemm(const __half* __restrict__ EXP1,
                                                  const float* __restrict__ U2,
                                                  const float* __restrict__ CL,
                                                  const __half* __restrict__ EVH,
                                                  const __half* __restrict__ OUT,
                                                  __half* __restrict__ OH) {
    __shared__ __align__(16) char sm[128 * EPITCH + 64 * EPITCH];
    __shared__ float rls[64];
    uint32_t sb = smem_u32(sm);
    int nt = blockIdx.x, g = blockIdx.y;
    int bt = g >> 3, h = g & 7;
    int tid = threadIdx.x;

#pragma unroll
    for (int it = 0; it < 4; ++it) {
        int idx = tid + it * 256;
        int r = idx >> 3, ch = idx & 7;
        uint32_t d = sb + (uint32_t)(r * EPITCH + ch * 16);
        CP_ASYNC16(d, EXP1 + ((size_t)g * Nn + nt * 128 + r) * 64 + ch * 8);
    }
    CP_COMMIT();
    if (tid < 64) rls[tid] = CL[g * 64 + tid];
    __syncthreads();
    char* Bsm = sm + 128 * EPITCH;
    for (int i = tid; i < 64 * 64; i += 256) {
        int d = i >> 6, s = i & 63;
        float v = (s < Ss) ? U2[s * hd + d] * rls[s] : 0.f;
        *(__half*)(Bsm + d * EPITCH + s * 2) = __float2half_rn(v);
    }
    CP_WAIT0();
    __syncthreads();

    int l = tid & 31, w = tid >> 5;
    int wm = w & 3, wn = w >> 2;
    float acc[2][4][4];
#pragma unroll
    for (int i = 0; i < 2; i++)
#pragma unroll
        for (int j = 0; j < 4; j++)
#pragma unroll
            for (int k = 0; k < 4; k++) acc[i][j][k] = 0.f;

    uint32_t lrow = (uint32_t)(l & 15) * EPITCH + (uint32_t)(l >> 4) * 16;
    uint32_t Abase = sb + (uint32_t)(wm * 32) * EPITCH;
    uint32_t Bbase = sb + 128 * EPITCH + (uint32_t)(wn * 32) * EPITCH;
#pragma unroll
    for (int k = 0; k < 4; ++k) {
        uint32_t a0[4], a1[4], b0[4], b1[4];
        LDSM4(a0, Abase + lrow + k * 32);
        LDSM4(a1, Abase + 16 * EPITCH + lrow + k * 32);
        LDSM4(b0, Bbase + lrow + k * 32);
        LDSM4(b1, Bbase + 16 * EPITCH + lrow + k * 32);
#pragma unroll
        for (int fm = 0; fm < 2; ++fm) {
            uint32_t* a = fm ? a1 : a0;
            mma16816(acc[fm][0], a, b0[0], b0[2]);
            mma16816(acc[fm][1], a, b0[1], b0[3]);
            mma16816(acc[fm][2], a, b1[0], b1[2]);
            mma16816(acc[fm][3], a, b1[1], b1[3]);
        }
    }
    int baseN = nt * 128 + wm * 32 + (l >> 2);
#pragma unroll
    for (int fm = 0; fm < 2; ++fm) {
        int n = baseN + fm * 16;
#pragma unroll
        for (int fn = 0; fn < 4; ++fn) {
            int d = wn * 32 + fn * 8 + (l & 3) * 2;
            size_t m0i = (size_t)bt * Nn + n;
            size_t m1i = m0i + 8;
            float2 ov0 = __half22float2(*(const __half2*)(OUT + m0i * Dd + h * hd + d));
            float2 ov1 = __half22float2(*(const __half2*)(OUT + m1i * Dd + h * hd + d));
            float2 ev0 = __half22float2(*(const __half2*)(EVH + m0i * 1024 + 512 + h * hd + d));
            float2 ev1 = __half22float2(*(const __half2*)(EVH + m1i * 1024 + 512 + h * hd + d));
            *(__half2*)(OH + m0i * Dd + h * hd + d) =
                __floats2half2_rn(acc[fm][fn][0] + ov0.x + ev0.x,
                                  acc[fm][fn][1] + ov0.y + ev0.y);
            *(__half2*)(OH + m1i * Dd + h * hd + d) =
                __floats2half2_rn(acc[fm][fn][2] + ov1.x + ev1.x,
                                  acc[fm][fn][3] + ov1.y + ev1.y);
        }
    }
}

// ---------------- launch ----------------
extern "C" void kernel_launch(void* const* d_in, const int* in_sizes, int n_in,
                              void* d_out, int out_size) {
    const float* x   = (const float*)d_in[0];
    const float* Wq  = (const float*)d_in[1];
    const float* bq  = (const float*)d_in[2];
    const float* Wk  = (const float*)d_in[3];
    const float* bk  = (const float*)d_in[4];
    const float* Wv  = (const float*)d_in[5];
    const float* bv  = (const float*)d_in[6];
    const float* We  = (const float*)d_in[7];
    const float* be  = (const float*)d_in[8];
    const float* Wo  = (const float*)d_in[9];
    const float* bo  = (const float*)d_in[10];
    const float* adp = (const float*)d_in[11];
    const float* U1  = (const float*)d_in[12];
    const float* U2  = (const float*)d_in[13];
    float* out = (float*)d_out;

    float* CL;
    cudaGetSymbolAddress((void**)&CL,  g_CL);

    __half *OUTh, *xh, *xph, *oh, *wqeh, *wkvh, *woh, *qeh, *kvh, *EXP1;
    cudaGetSymbolAddress((void**)&OUTh, g_OUTh);
    cudaGetSymbolAddress((void**)&xh,   g_xh);
    cudaGetSymbolAddress((void**)&xph,  g_xph);
    cudaGetSymbolAddress((void**)&oh,   g_oh);
    cudaGetSymbolAddress((void**)&wqeh, g_wqeh);
    cudaGetSymbolAddress((void**)&wkvh, g_wkvh);
    cudaGetSymbolAddress((void**)&woh,  g_woh);
    cudaGetSymbolAddress((void**)&qeh,  g_qeh);
    cudaGetSymbolAddress((void**)&kvh,  g_kvh);
    cudaGetSymbolAddress((void**)&EXP1, g_EXP1);

    cudaFuncSetAttribute(gemm_f16, cudaFuncAttributeMaxDynamicSharedMemorySize, GEMM_SMEM);
    cudaFuncSetAttribute(attn_tc,  cudaFuncAttributeMaxDynamicSharedMemorySize, ATTN_SMEM);

    const int WN = Dd * Dd;            // 262144

    // ---- multi-stream fork/join (capturable; deterministic) ----
    cudaStream_t s1, s3;
    cudaStreamCreateWithFlags(&s1, cudaStreamNonBlocking);
    cudaStreamCreateWithFlags(&s3, cudaStreamNonBlocking);
    cudaEvent_t eStart, eW, eKV, eQE, eE1;
    cudaEventCreateWithFlags(&eStart, cudaEventDisableTiming);
    cudaEventCreateWithFlags(&eW,     cudaEventDisableTiming);
    cudaEventCreateWithFlags(&eKV,    cudaEventDisableTiming);
    cudaEventCreateWithFlags(&eQE,    cudaEventDisableTiming);
    cudaEventCreateWithFlags(&eE1,    cudaEventDisableTiming);

    cudaEventRecord(eStart, 0);
    cudaStreamWaitEvent(s1, eStart, 0);

    // s1: weights -> pooled x -> KV GEMM (fp16 only)
    convert_w5<<<dim3(256, 5), 256, 0, s1>>>(Wq, We, Wk, Wv, Wo,
                                             wqeh, wqeh + WN, wkvh, wkvh + WN, woh);
    cudaEventRecord(eW, s1);
    pool_convert_kernel<<<M_POOL, 128, 0, s1>>>(x, xph);
    gemm_f16<<<dim3(8, M_POOL / 128), 256, GEMM_SMEM, s1>>>(xph, wkvh, bk, bv,
                                                            nullptr, 1024, kvh);
    cudaEventRecord(eKV, s1);

    // s0: x convert -> QE GEMM (fp16 only)
    convert_f16<<<(M_BIG * Dd / 4 + 255) / 256, 256>>>(x, xh, M_BIG * Dd / 4);
    cudaStreamWaitEvent(0, eW, 0);
    gemm_f16<<<dim3(8, M_BIG / 128), 256, GEMM_SMEM>>>(xh, wqeh, bq, be,
                                                       nullptr, 1024, qeh);
    cudaEventRecord(eQE, 0);

    // s3: external-branch e1 + colsum (parallel with attention)
    cudaStreamWaitEvent(s3, eQE, 0);
    e1_gemm<<<dim3(8, Gg), 256, 0, s3>>>(qeh, U1, EXP1);
    colsum_kernel<<<Gg, 256, 0, s3>>>(EXP1, CL);
    cudaEventRecord(eE1, s3);

    // s0: attention -> apply -> Wo GEMM
    cudaStreamWaitEvent(0, eKV, 0);
    attn_tc<<<dim3(8, Gg), 256, ATTN_SMEM>>>(qeh, kvh, adp, OUTh);
    cudaStreamWaitEvent(0, eE1, 0);
    apply_gemm<<<dim3(8, Gg), 256>>>(EXP1, U2, CL, qeh, OUTh, oh);
    gemm_f16<<<dim3(4, M_BIG / 128), 256, GEMM_SMEM>>>(oh, woh, bo, bo, out, Dd, nullptr);

    // cleanup only outside capture
    cudaStreamCaptureStatus st = cudaStreamCaptureStatusNone;
    cudaStreamIsCapturing(0, &st);
    if (st == cudaStreamCaptureStatusNone) {
        cudaEventDestroy(eStart); cudaEventDestroy(eW); cudaEventDestroy(eKV);
        cudaEventDestroy(eQE);    cudaEventDestroy(eE1);
        cudaStreamDestroy(s1); cudaStreamDestroy(s3);
    }
}

// round 17
// speedup vs baseline: 2.2866x; 1.0489x over previous
#include <cuda_runtime.h>
#include <cuda_fp16.h>
#include <math.h>
#include <stdint.h>

// ---------------- problem dims ----------------
#define Bb   4
#define Tt   12
#define Nn   1024
#define Dd   512
#define Hh   8
#define hd   64
#define Cc   128
#define Ss   60
#define BT   48            // Bb*Tt
#define M_BIG  49152       // BT*Nn
#define M_POOL 6144        // BT*Cc
#define Gg   384           // BT*Hh

// ---------------- device scratch (allocation-free) ----------------
__device__ float g_CL [Gg * 64];         // raw column sums (s padded to 64)

__device__ __half g_OUTh[M_BIG * Dd];    // attention branch output (fp16)
__device__ __half g_EXP1[(size_t)Gg * Nn * 64];  // exp(e1), [g][n][64]
__device__ __half g_qeh [M_BIG  * 1024]; // fp16 QE: [m][0:512]=q, [512:1024]=ev
__device__ __half g_kvh [M_POOL * 1024]; // fp16 KV: [c][0:512]=k, [512:1024]=v
__device__ __half g_xh  [M_BIG  * Dd];
__device__ __half g_xph [M_POOL * Dd];
__device__ __half g_oh  [M_BIG  * Dd];
__device__ __half g_wqeh[1024 * Dd];
__device__ __half g_wkvh[1024 * Dd];
__device__ __half g_woh [Dd * Dd];

// ---------------- helpers ----------------
__device__ __forceinline__ uint32_t smem_u32(const void* p) {
    uint32_t a;
    asm("{ .reg .u64 t; cvta.to.shared.u64 t, %1; cvt.u32.u64 %0, t; }" : "=r"(a) : "l"(p));
    return a;
}
#define CP_ASYNC16(dst, src) \
    asm volatile("cp.async.cg.shared.global [%0], [%1], 16;" :: "r"(dst), "l"(src) : "memory")
#define CP_COMMIT() asm volatile("cp.async.commit_group;" ::: "memory")
#define CP_WAIT2()  asm volatile("cp.async.wait_group 2;" ::: "memory")
#define CP_WAIT0()  asm volatile("cp.async.wait_group 0;" ::: "memory")
#define LDSM4(r, addr) \
    asm volatile("ldmatrix.sync.aligned.m8n8.x4.shared.b16 {%0,%1,%2,%3}, [%4];" \
        : "=r"((r)[0]), "=r"((r)[1]), "=r"((r)[2]), "=r"((r)[3]) : "r"(addr))
__device__ __forceinline__ void mma16816(float* c, const uint32_t* a,
                                         uint32_t b0, uint32_t b1) {
    asm volatile("mma.sync.aligned.m16n8k16.row.col.f32.f16.f16.f32 "
                 "{%0,%1,%2,%3}, {%4,%5,%6,%7}, {%8,%9}, {%0,%1,%2,%3};"
                 : "+f"(c[0]), "+f"(c[1]), "+f"(c[2]), "+f"(c[3])
                 : "r"(a[0]), "r"(a[1]), "r"(a[2]), "r"(a[3]), "r"(b0), "r"(b1));
}

// ---------------- conversions ----------------
__global__ void __launch_bounds__(256) convert_f16(const float* __restrict__ src,
                                                   __half* __restrict__ dst, int n4) {
    int i = blockIdx.x * 256 + threadIdx.x;
    if (i >= n4) return;
    float4 v = ((const float4*)src)[i];
    __half2* D = (__half2*)dst;
    D[2 * i]     = __floats2half2_rn(v.x, v.y);
    D[2 * i + 1] = __floats2half2_rn(v.z, v.w);
}

__global__ void __launch_bounds__(256) convert_w5(
    const float* __restrict__ s0, const float* __restrict__ s1,
    const float* __restrict__ s2, const float* __restrict__ s3,
    const float* __restrict__ s4,
    __half* __restrict__ d0, __half* __restrict__ d1, __half* __restrict__ d2,
    __half* __restrict__ d3, __half* __restrict__ d4) {
    const float* s; __half* d;
    switch (blockIdx.y) {
        case 0:  s = s0; d = d0; break;
        case 1:  s = s1; d = d1; break;
        case 2:  s = s2; d = d2; break;
        case 3:  s = s3; d = d3; break;
        default: s = s4; d = d4; break;
    }
    int i = blockIdx.x * 256 + threadIdx.x;
    float4 v = ((const float4*)s)[i];
    __half2* D = (__half2*)d;
    D[2 * i]     = __floats2half2_rn(v.x, v.y);
    D[2 * i + 1] = __floats2half2_rn(v.z, v.w);
}

__global__ void __launch_bounds__(128) pool_convert_kernel(const float* __restrict__ X,
                                                           __half* __restrict__ XH) {
    int row = blockIdx.x;
    int bt = row >> 7, c = row & 127;
    int tid = threadIdx.x;
    const float4* xr = (const float4*)(X + ((size_t)bt * Nn + (size_t)c * 8) * Dd);
    float4 s = make_float4(0.f, 0.f, 0.f, 0.f);
#pragma unroll
    for (int j = 0; j < 8; j++) {
        float4 v = xr[(size_t)j * (Dd / 4) + tid];
        s.x += v.x; s.y += v.y; s.z += v.z; s.w += v.w;
    }
    s.x *= 0.125f; s.y *= 0.125f; s.z *= 0.125f; s.w *= 0.125f;
    size_t o = (size_t)row * Dd + tid * 4;
    *(__half2*)(XH + o)     = __floats2half2_rn(s.x, s.y);
    *(__half2*)(XH + o + 2) = __floats2half2_rn(s.z, s.w);
}

__global__ void __launch_bounds__(256) zero_cl(float* __restrict__ CL) {
    CL[blockIdx.x * 256 + threadIdx.x] = 0.f;
}

// ---------------- HMMA GEMM fp16: C = Ah.Bh + bias, K=512 ----------------
// msel < 0: m-block = blockIdx.y. msel >= 0: m-block = (y>>2)*8 + (y&3) + msel
// (selects the n<512 / n>=512 half of each bt's row group, for split Wo).
#define ST_BYTES  20480
#define GEMM_SMEM (4 * ST_BYTES)
#define ROWB      80

__global__ void __launch_bounds__(256, 2)
gemm_f16(const __half* __restrict__ Ah, const __half* __restrict__ Bh,
         const float* __restrict__ bias0, const float* __restrict__ bias1,
         float* __restrict__ C, int Nout, __half* __restrict__ FH, int msel) {
    extern __shared__ __align__(1024) char smem[];
    uint32_t sb = smem_u32(smem);
    const int tid = threadIdx.x;
    const int n0 = blockIdx.x * 128;
    const int m0 = (msel < 0) ? (blockIdx.y * 128)
                 : ((((blockIdx.y >> 2) << 3) + (blockIdx.y & 3) + msel) * 128);
    const int l = tid & 31, w = tid >> 5;
    const int wm = w & 3, wn = w >> 2;
    const float* bias = (n0 < 512) ? bias0 : bias1;
    const int nb = (n0 < 512) ? n0 : n0 - 512;

    float acc[2][8][4];
#pragma unroll
    for (int i = 0; i < 2; i++)
#pragma unroll
        for (int j = 0; j < 8; j++)
#pragma unroll
            for (int k = 0; k < 4; k++) acc[i][j][k] = 0.f;

    auto load_stage = [&](int slot, int kc) {
        int kt = kc * 32;
        uint32_t base = sb + (uint32_t)(slot * ST_BYTES);
#pragma unroll
        for (int it = 0; it < 4; ++it) {
            int idx = tid + it * 256;
            int half = idx >> 9;
            int r = (idx >> 2) & 127, ch = idx & 3;
            uint32_t d = base + (uint32_t)(half * 10240 + r * ROWB + ch * 16);
            const __half* src = half ? (Bh + (size_t)(n0 + r) * Dd + kt + ch * 8)
                                     : (Ah + (size_t)(m0 + r) * Dd + kt + ch * 8);
            CP_ASYNC16(d, src);
        }
    };

    load_stage(0, 0); CP_COMMIT();
    load_stage(1, 1); CP_COMMIT();
    load_stage(2, 2); CP_COMMIT();

    const uint32_t lrow = (uint32_t)(l & 15) * ROWB + (uint32_t)(l >> 4) * 16;

    for (int c = 0; c < 16; ++c) {
        CP_WAIT2();
        __syncthreads();
        if (c + 3 < 16) { load_stage((c + 3) & 3, c + 3); }
        CP_COMMIT();

        uint32_t stb = sb + (uint32_t)((c & 3) * ST_BYTES);
#pragma unroll
        for (int kk = 0; kk < 2; ++kk) {
            uint32_t aoff = stb + (uint32_t)(wm * 32) * ROWB + lrow + kk * 32;
            uint32_t boff = stb + 10240 + (uint32_t)(wn * 64) * ROWB + lrow + kk * 32;
            uint32_t a[2][4], b[4][4];
            LDSM4(a[0], aoff);
            LDSM4(a[1], aoff + 16 * ROWB);
#pragma unroll
            for (int fp = 0; fp < 4; ++fp) LDSM4(b[fp], boff + fp * 16 * ROWB);
#pragma unroll
            for (int fm = 0; fm < 2; ++fm)
#pragma unroll
                for (int fp = 0; fp < 4; ++fp) {
                    mma16816(acc[fm][2 * fp],     a[fm], b[fp][0], b[fp][2]);
                    mma16816(acc[fm][2 * fp + 1], a[fm], b[fp][1], b[fp][3]);
                }
        }
    }

#pragma unroll
    for (int fm = 0; fm < 2; ++fm) {
        int mrow = m0 + wm * 32 + fm * 16 + (l >> 2);
#pragma unroll
        for (int fn = 0; fn < 8; ++fn) {
            int nc = wn * 64 + fn * 8 + (l & 3) * 2;
            float b0 = bias[nb + nc], b1 = bias[nb + nc + 1];
            float2 o0, o1;
            o0.x = acc[fm][fn][0] + b0; o0.y = acc[fm][fn][1] + b1;
            o1.x = acc[fm][fn][2] + b0; o1.y = acc[fm][fn][3] + b1;
            if (C != nullptr) {
                *(float2*)(C + (size_t)mrow * Nout + n0 + nc)       = o0;
                *(float2*)(C + (size_t)(mrow + 8) * Nout + n0 + nc) = o1;
            }
            if (FH != nullptr) {
                *(__half2*)(FH + (size_t)mrow * Nout + n0 + nc) =
                    __floats2half2_rn(o0.x, o0.y);
                *(__half2*)(FH + (size_t)(mrow + 8) * Nout + n0 + nc) =
                    __floats2half2_rn(o1.x, o1.y);
            }
        }
    }
}

// ---------------- tensor-core attention (2 CTAs/SM; adp read from L2) -----
#define EP1   144
#define EP2   272
#define AQS   0
#define AKS   18432
#define AVT   36864
#define APS   54272
#define ARED  89088
#define ATTN_SMEM 91136

__global__ void __launch_bounds__(256, 2)
attn_tc(const __half* __restrict__ QEH, const __half* __restrict__ KVH,
        const float* __restrict__ ADP, __half* __restrict__ OUT) {
    extern __shared__ __align__(1024) char sm[];
    uint32_t sb = smem_u32(sm);
    int nt = blockIdx.x, g = blockIdx.y;
    int bt = g >> 3, hh = g & 7;
    int tid = threadIdx.x;
    int n0 = nt * 128;
    const int l = tid & 31, w = tid >> 5;
    const int wm = w & 3, wn = w >> 2;

#pragma unroll
    for (int it = 0; it < 12; ++it) {
        int idx = tid + it * 256;
        int tile = idx >> 10, j = idx & 1023;
        int r = j >> 3, ch = j & 7;
        uint32_t d;
        const __half* src;
        if (tile == 0) {
            d = sb + AQS + (uint32_t)(r * EP1 + ch * 16);
            src = QEH + ((size_t)(bt * Nn + n0 + r) * 1024 + hh * hd + ch * 8);
        } else if (tile == 1) {
            d = sb + AKS + (uint32_t)(r * EP1 + ch * 16);
            src = KVH + ((size_t)(bt * Cc + r) * 1024 + hh * hd + ch * 8);
        } else {
            d = sb + APS + (uint32_t)(r * EP1 + ch * 16);
            src = KVH + ((size_t)(bt * Cc + r) * 1024 + 512 + hh * hd + ch * 8);
        }
        CP_ASYNC16(d, src);
    }
    CP_COMMIT();
    CP_WAIT0();
    __syncthreads();

#pragma unroll
    for (int it = 0; it < 32; ++it) {
        int i = tid + it * 256;
        int d = i & 63, c = i >> 6;
        __half v = *(const __half*)(sm + APS + c * EP1 + d * 2);
        *(__half*)(sm + AVT + d * EP2 + c * 2) = v;
    }
    __syncthreads();

    float acc[2][8][4];
#pragma unroll
    for (int i = 0; i < 2; i++)
#pragma unroll
        for (int j = 0; j < 8; j++)
#pragma unroll
            for (int k = 0; k < 4; k++) acc[i][j][k] = 0.f;
    const uint32_t lrow1 = (uint32_t)(l & 15) * EP1 + (uint32_t)(l >> 4) * 16;
#pragma unroll
    for (int kc = 0; kc < 4; ++kc) {
        uint32_t aoff = sb + AQS + (uint32_t)(wm * 32) * EP1 + lrow1 + kc * 32;
        uint32_t boff = sb + AKS + (uint32_t)(wn * 64) * EP1 + lrow1 + kc * 32;
        uint32_t a[2][4], b[4][4];
        LDSM4(a[0], aoff);
        LDSM4(a[1], aoff + 16 * EP1);
#pragma unroll
        for (int fp = 0; fp < 4; ++fp) LDSM4(b[fp], boff + fp * 16 * EP1);
#pragma unroll
        for (int fm = 0; fm < 2; ++fm)
#pragma unroll
            for (int fp = 0; fp < 4; ++fp) {
                mma16816(acc[fm][2 * fp],     a[fm], b[fp][0], b[fp][2]);
                mma16816(acc[fm][2 * fp + 1], a[fm], b[fp][1], b[fp][3]);
            }
    }

#pragma unroll
    for (int fm = 0; fm < 2; ++fm) {
        int rbase = wm * 32 + fm * 16 + (l >> 2);
#pragma unroll
        for (int fn = 0; fn < 8; ++fn) {
            int cb = wn * 64 + fn * 8 + (l & 3) * 2;
#pragma unroll
            for (int k2 = 0; k2 < 2; ++k2) {
                int r = rbase + k2 * 8;
                float2 ad = *(const float2*)(ADP + (size_t)(n0 + r) * Cc + cb);
                acc[fm][fn][2 * k2]     = acc[fm][fn][2 * k2]     * 0.125f + ad.x;
                acc[fm][fn][2 * k2 + 1] = acc[fm][fn][2 * k2 + 1] * 0.125f + ad.y;
            }
        }
    }

    float* REDm = (float*)(sm + ARED);
    float* REDs = (float*)(sm + ARED + 1024);

#pragma unroll
    for (int fm = 0; fm < 2; ++fm)
#pragma unroll
        for (int k2 = 0; k2 < 2; ++k2) {
            float m = -1e30f;
#pragma unroll
            for (int fn = 0; fn < 8; ++fn) {
                m = fmaxf(m, acc[fm][fn][2 * k2]);
                m = fmaxf(m, acc[fm][fn][2 * k2 + 1]);
            }
            m = fmaxf(m, __shfl_xor_sync(0xffffffffu, m, 1));
            m = fmaxf(m, __shfl_xor_sync(0xffffffffu, m, 2));
            if ((l & 3) == 0) {
                int r = wm * 32 + fm * 16 + (l >> 2) + k2 * 8;
                REDm[r * 2 + wn] = m;
            }
        }
    __syncthreads();
    float cmax[2][2];
#pragma unroll
    for (int fm = 0; fm < 2; ++fm)
#pragma unroll
        for (int k2 = 0; k2 < 2; ++k2) {
            int r = wm * 32 + fm * 16 + (l >> 2) + k2 * 8;
            cmax[fm][k2] = fmaxf(REDm[r * 2], REDm[r * 2 + 1]);
        }
    float rsum[2][2] = {{0.f, 0.f}, {0.f, 0.f}};
#pragma unroll
    for (int fm = 0; fm < 2; ++fm)
#pragma unroll
        for (int fn = 0; fn < 8; ++fn)
#pragma unroll
            for (int k = 0; k < 4; ++k) {
                float e = __expf(acc[fm][fn][k] - cmax[fm][k >> 1]);
                acc[fm][fn][k] = e;
                rsum[fm][k >> 1] += e;
            }
#pragma unroll
    for (int fm = 0; fm < 2; ++fm)
#pragma unroll
        for (int k2 = 0; k2 < 2; ++k2) {
            float s = rsum[fm][k2];
            s += __shfl_xor_sync(0xffffffffu, s, 1);
            s += __shfl_xor_sync(0xffffffffu, s, 2);
            if ((l & 3) == 0) {
                int r = wm * 32 + fm * 16 + (l >> 2) + k2 * 8;
                REDs[r * 2 + wn] = s;
            }
        }
    __syncthreads();
#pragma unroll
    for (int fm = 0; fm < 2; ++fm)
#pragma unroll
        for (int k2 = 0; k2 < 2; ++k2) {
            int r = wm * 32 + fm * 16 + (l >> 2) + k2 * 8;
            float inv = 1.f / (REDs[r * 2] + REDs[r * 2 + 1]);
#pragma unroll
            for (int fn = 0; fn < 8; ++fn) {
                int cb = wn * 64 + fn * 8 + (l & 3) * 2;
                *(__half2*)(sm + APS + r * EP2 + cb * 2) =
                    __floats2half2_rn(acc[fm][fn][2 * k2] * inv,
                                      acc[fm][fn][2 * k2 + 1] * inv);
            }
        }
    __syncthreads();

    float acc2[2][4][4];
#pragma unroll
    for (int i = 0; i < 2; i++)
#pragma unroll
        for (int j = 0; j < 4; j++)
#pragma unroll
            for (int k = 0; k < 4; k++) acc2[i][j][k] = 0.f;
    const uint32_t lrow2 = (uint32_t)(l & 15) * EP2 + (uint32_t)(l >> 4) * 16;
#pragma unroll
    for (int kc = 0; kc < 8; ++kc) {
        uint32_t aoff = sb + APS + (uint32_t)(wm * 32) * EP2 + lrow2 + kc * 32;
        uint32_t boff = sb + AVT + (uint32_t)(wn * 32) * EP2 + lrow2 + kc * 32;
        uint32_t a0[4], a1[4], b0[4], b1[4];
        LDSM4(a0, aoff);
        LDSM4(a1, aoff + 16 * EP2);
        LDSM4(b0, boff);
        LDSM4(b1, boff + 16 * EP2);
#pragma unroll
        for (int fm = 0; fm < 2; ++fm) {
            uint32_t* a = fm ? a1 : a0;
            mma16816(acc2[fm][0], a, b0[0], b0[2]);
            mma16816(acc2[fm][1], a, b0[1], b0[3]);
            mma16816(acc2[fm][2], a, b1[0], b1[2]);
            mma16816(acc2[fm][3], a, b1[1], b1[3]);
        }
    }
#pragma unroll
    for (int fm = 0; fm < 2; ++fm) {
        int rb = wm * 32 + fm * 16 + (l >> 2);
#pragma unroll
        for (int fn = 0; fn < 4; ++fn) {
            int d = wn * 32 + fn * 8 + (l & 3) * 2;
            size_t m0i = (size_t)(bt * Nn + n0 + rb) * Dd + hh * hd + d;
            size_t m1i = (size_t)(bt * Nn + n0 + rb + 8) * Dd + hh * hd + d;
            *(__half2*)(OUT + m0i) = __floats2half2_rn(acc2[fm][fn][0], acc2[fm][fn][1]);
            *(__half2*)(OUT + m1i) = __floats2half2_rn(acc2[fm][fn][2], acc2[fm][fn][3]);
        }
    }
}

// ---------------- external branch: e1 GEMM with fused column-sum ----------
#define EPITCH 144

__global__ void __launch_bounds__(256) e1_gemm(const __half* __restrict__ QEH,
                                               const float* __restrict__ U1,
                                               __half* __restrict__ EXP1,
                                               float* __restrict__ CL) {
    __shared__ __align__(16) char sm[128 * EPITCH + 64 * EPITCH];
    uint32_t sb = smem_u32(sm);
    int nt = blockIdx.x, g = blockIdx.y;
    int bt = g >> 3, h = g & 7;
    int tid = threadIdx.x;

#pragma unroll
    for (int it = 0; it < 4; ++it) {
        int idx = tid + it * 256;
        int r = idx >> 3, ch = idx & 7;
        uint32_t d = sb + (uint32_t)(r * EPITCH + ch * 16);
        CP_ASYNC16(d, QEH + ((size_t)(bt * Nn + nt * 128 + r) * 1024 + 512 + h * hd + ch * 8));
    }
    CP_COMMIT();
    char* Bsm = sm + 128 * EPITCH;
    for (int i = tid; i < 64 * 64; i += 256) {
        int s = i >> 6, d = i & 63;
        float v = (s < Ss) ? U1[d * Ss + s] : 0.f;
        *(__half*)(Bsm + s * EPITCH + d * 2) = __float2half_rn(v);
    }
    CP_WAIT0();
    __syncthreads();

    int l = tid & 31, w = tid >> 5;
    int wm = w & 3, wn = w >> 2;
    float acc[2][4][4];
#pragma unroll
    for (int i = 0; i < 2; i++)
#pragma unroll
        for (int j = 0; j < 4; j++)
#pragma unroll
            for (int k = 0; k < 4; k++) acc[i][j][k] = 0.f;

    uint32_t lrow = (uint32_t)(l & 15) * EPITCH + (uint32_t)(l >> 4) * 16;
    uint32_t Abase = sb + (uint32_t)(wm * 32) * EPITCH;
    uint32_t Bbase = sb + 128 * EPITCH + (uint32_t)(wn * 32) * EPITCH;
#pragma unroll
    for (int k = 0; k < 4; ++k) {
        uint32_t a0[4], a1[4], b0[4], b1[4];
        LDSM4(a0, Abase + lrow + k * 32);
        LDSM4(a1, Abase + 16 * EPITCH + lrow + k * 32);
        LDSM4(b0, Bbase + lrow + k * 32);
        LDSM4(b1, Bbase + 16 * EPITCH + lrow + k * 32);
#pragma unroll
        for (int fm = 0; fm < 2; ++fm) {
            uint32_t* a = fm ? a1 : a0;
            mma16816(acc[fm][0], a, b0[0], b0[2]);
            mma16816(acc[fm][1], a, b0[1], b0[3]);
            mma16816(acc[fm][2], a, b1[0], b1[2]);
            mma16816(acc[fm][3], a, b1[1], b1[3]);
        }
    }
    int baseN = nt * 128 + wm * 32 + (l >> 2);
    float csum[4][2];
#pragma unroll
    for (int i = 0; i < 4; i++) { csum[i][0] = 0.f; csum[i][1] = 0.f; }
#pragma unroll
    for (int fm = 0; fm < 2; ++fm) {
        int n = baseN + fm * 16;
#pragma unroll
        for (int fn = 0; fn < 4; ++fn) {
            int s = wn * 32 + fn * 8 + (l & 3) * 2;
            bool ok = (s < Ss);
            float v0 = ok ? __expf(fminf(acc[fm][fn][0], 11.f)) : 0.f;
            float v1 = ok ? __expf(fminf(acc[fm][fn][1], 11.f)) : 0.f;
            float v2 = ok ? __expf(fminf(acc[fm][fn][2], 11.f)) : 0.f;
            float v3 = ok ? __expf(fminf(acc[fm][fn][3], 11.f)) : 0.f;
            *(__half2*)(EXP1 + ((size_t)g * Nn + n) * 64 + s)     = __floats2half2_rn(v0, v1);
            *(__half2*)(EXP1 + ((size_t)g * Nn + n + 8) * 64 + s) = __floats2half2_rn(v2, v3);
            csum[fn][0] += v0 + v2;
            csum[fn][1] += v1 + v3;
        }
    }
    // reduce column sums over rows (lanes l>>2) and atomically accumulate
#pragma unroll
    for (int fn = 0; fn < 4; ++fn) {
#pragma unroll
        for (int off = 4; off < 32; off <<= 1) {
            csum[fn][0] += __shfl_xor_sync(0xffffffffu, csum[fn][0], off);
            csum[fn][1] += __shfl_xor_sync(0xffffffffu, csum[fn][1], off);
        }
        if (l < 4) {
            int s = wn * 32 + fn * 8 + l * 2;
            atomicAdd(&CL[g * 64 + s],     csum[fn][0]);
            atomicAdd(&CL[g * 64 + s + 1], csum[fn][1]);
        }
    }
}

__global__ void __launch_bounds__(256) apply_gemm(const __half* __restrict__ EXP1,
                                                  const float* __restrict__ U2,
                                                  const float* __restrict__ CL,
                                                  const __half* __restrict__ EVH,
                                                  const __half* __restrict__ OUT,
                                                  __half* __restrict__ OH, int nt0) {
    __shared__ __align__(16) char sm[128 * EPITCH + 64 * EPITCH];
    __shared__ float rls[64];
    uint32_t sb = smem_u32(sm);
    int nt = blockIdx.x + nt0, g = blockIdx.y;
    int bt = g >> 3, h = g & 7;
    int tid = threadIdx.x;

#pragma unroll
    for (int it = 0; it < 4; ++it) {
        int idx = tid + it * 256;
        int r = idx >> 3, ch = idx & 7;
        uint32_t d = sb + (uint32_t)(r * EPITCH + ch * 16);
        CP_ASYNC16(d, EXP1 + ((size_t)g * Nn + nt * 128 + r) * 64 + ch * 8);
    }
    CP_COMMIT();
    if (tid < 64) rls[tid] = 0.5f / fmaxf(CL[g * 64 + tid], 1e-30f);
    __syncthreads();
    char* Bsm = sm + 128 * EPITCH;
    for (int i = tid; i < 64 * 64; i += 256) {
        int d = i >> 6, s = i & 63;
        float v = (s < Ss) ? U2[s * hd + d] * rls[s] : 0.f;
        *(__half*)(Bsm + d * EPITCH + s * 2) = __float2half_rn(v);
    }
    CP_WAIT0();
    __syncthreads();

    int l = tid & 31, w = tid >> 5;
    int wm = w & 3, wn = w >> 2;
    float acc[2][4][4];
#pragma unroll
    for (int i = 0; i < 2; i++)
#pragma unroll
        for (int j = 0; j < 4; j++)
#pragma unroll
            for (int k = 0; k < 4; k++) acc[i][j][k] = 0.f;

    uint32_t lrow = (uint32_t)(l & 15) * EPITCH + (uint32_t)(l >> 4) * 16;
    uint32_t Abase = sb + (uint32_t)(wm * 32) * EPITCH;
    uint32_t Bbase = sb + 128 * EPITCH + (uint32_t)(wn * 32) * EPITCH;
#pragma unroll
    for (int k = 0; k < 4; ++k) {
        uint32_t a0[4], a1[4], b0[4], b1[4];
        LDSM4(a0, Abase + lrow + k * 32);
        LDSM4(a1, Abase + 16 * EPITCH + lrow + k * 32);
        LDSM4(b0, Bbase + lrow + k * 32);
        LDSM4(b1, Bbase + 16 * EPITCH + lrow + k * 32);
#pragma unroll
        for (int fm = 0; fm < 2; ++fm) {
            uint32_t* a = fm ? a1 : a0;
            mma16816(acc[fm][0], a, b0[0], b0[2]);
            mma16816(acc[fm][1], a, b0[1], b0[3]);
            mma16816(acc[fm][2], a, b1[0], b1[2]);
            mma16816(acc[fm][3], a, b1[1], b1[3]);
        }
    }
    int baseN = nt * 128 + wm * 32 + (l >> 2);
#pragma unroll
    for (int fm = 0; fm < 2; ++fm) {
        int n = baseN + fm * 16;
#pragma unroll
        for (int fn = 0; fn < 4; ++fn) {
            int d = wn * 32 + fn * 8 + (l & 3) * 2;
            size_t m0i = (size_t)bt * Nn + n;
            size_t m1i = m0i + 8;
            float2 ov0 = __half22float2(*(const __half2*)(OUT + m0i * Dd + h * hd + d));
            float2 ov1 = __half22float2(*(const __half2*)(OUT + m1i * Dd + h * hd + d));
            float2 ev0 = __half22float2(*(const __half2*)(EVH + m0i * 1024 + 512 + h * hd + d));
            float2 ev1 = __half22float2(*(const __half2*)(EVH + m1i * 1024 + 512 + h * hd + d));
            *(__half2*)(OH + m0i * Dd + h * hd + d) =
                __floats2half2_rn(acc[fm][fn][0] + ov0.x + ev0.x,
                                  acc[fm][fn][1] + ov0.y + ev0.y);
            *(__half2*)(OH + m1i * Dd + h * hd + d) =
                __floats2half2_rn(acc[fm][fn][2] + ov1.x + ev1.x,
                                  acc[fm][fn][3] + ov1.y + ev1.y);
        }
    }
}

// ---------------- launch ----------------
extern "C" void kernel_launch(void* const* d_in, const int* in_sizes, int n_in,
                              void* d_out, int out_size) {
    const float* x   = (const float*)d_in[0];
    const float* Wq  = (const float*)d_in[1];
    const float* bq  = (const float*)d_in[2];
    const float* Wk  = (const float*)d_in[3];
    const float* bk  = (const float*)d_in[4];
    const float* Wv  = (const float*)d_in[5];
    const float* bv  = (const float*)d_in[6];
    const float* We  = (const float*)d_in[7];
    const float* be  = (const float*)d_in[8];
    const float* Wo  = (const float*)d_in[9];
    const float* bo  = (const float*)d_in[10];
    const float* adp = (const float*)d_in[11];
    const float* U1  = (const float*)d_in[12];
    const float* U2  = (const float*)d_in[13];
    float* out = (float*)d_out;

    float* CL;
    cudaGetSymbolAddress((void**)&CL,  g_CL);

    __half *OUTh, *xh, *xph, *oh, *wqeh, *wkvh, *woh, *qeh, *kvh, *EXP1;
    cudaGetSymbolAddress((void**)&OUTh, g_OUTh);
    cudaGetSymbolAddress((void**)&xh,   g_xh);
    cudaGetSymbolAddress((void**)&xph,  g_xph);
    cudaGetSymbolAddress((void**)&oh,   g_oh);
    cudaGetSymbolAddress((void**)&wqeh, g_wqeh);
    cudaGetSymbolAddress((void**)&wkvh, g_wkvh);
    cudaGetSymbolAddress((void**)&woh,  g_woh);
    cudaGetSymbolAddress((void**)&qeh,  g_qeh);
    cudaGetSymbolAddress((void**)&kvh,  g_kvh);
    cudaGetSymbolAddress((void**)&EXP1, g_EXP1);

    cudaFuncSetAttribute(gemm_f16, cudaFuncAttributeMaxDynamicSharedMemorySize, GEMM_SMEM);
    cudaFuncSetAttribute(attn_tc,  cudaFuncAttributeMaxDynamicSharedMemorySize, ATTN_SMEM);

    const int WN = Dd * Dd;            // 262144

    // ---- multi-stream fork/join (capturable; deterministic work) ----
    cudaStream_t s1, s3;
    cudaStreamCreateWithFlags(&s1, cudaStreamNonBlocking);
    cudaStreamCreateWithFlags(&s3, cudaStreamNonBlocking);
    cudaEvent_t eStart, eW, eKV, eQE, eE1, eAT, eWoB;
    cudaEventCreateWithFlags(&eStart, cudaEventDisableTiming);
    cudaEventCreateWithFlags(&eW,     cudaEventDisableTiming);
    cudaEventCreateWithFlags(&eKV,    cudaEventDisableTiming);
    cudaEventCreateWithFlags(&eQE,    cudaEventDisableTiming);
    cudaEventCreateWithFlags(&eE1,    cudaEventDisableTiming);
    cudaEventCreateWithFlags(&eAT,    cudaEventDisableTiming);
    cudaEventCreateWithFlags(&eWoB,   cudaEventDisableTiming);

    cudaEventRecord(eStart, 0);
    cudaStreamWaitEvent(s1, eStart, 0);
    cudaStreamWaitEvent(s3, eStart, 0);

    // s3: zero the column-sum accumulator early
    zero_cl<<<Gg * 64 / 256, 256, 0, s3>>>(CL);

    // s1: weights -> pooled x -> KV GEMM (fp16 only)
    convert_w5<<<dim3(256, 5), 256, 0, s1>>>(Wq, We, Wk, Wv, Wo,
                                             wqeh, wqeh + WN, wkvh, wkvh + WN, woh);
    cudaEventRecord(eW, s1);
    pool_convert_kernel<<<M_POOL, 128, 0, s1>>>(x, xph);
    gemm_f16<<<dim3(8, M_POOL / 128), 256, GEMM_SMEM, s1>>>(xph, wkvh, bk, bv,
                                                            nullptr, 1024, kvh, -1);
    cudaEventRecord(eKV, s1);

    // s0: x convert -> QE GEMM (fp16 only)
    convert_f16<<<(M_BIG * Dd / 4 + 255) / 256, 256>>>(x, xh, M_BIG * Dd / 4);
    cudaStreamWaitEvent(0, eW, 0);
    gemm_f16<<<dim3(8, M_BIG / 128), 256, GEMM_SMEM>>>(xh, wqeh, bq, be,
                                                       nullptr, 1024, qeh, -1);
    cudaEventRecord(eQE, 0);

    // s3: e1 GEMM with fused colsum (parallel with attention)
    cudaStreamWaitEvent(s3, eQE, 0);
    e1_gemm<<<dim3(8, Gg), 256, 0, s3>>>(qeh, U1, EXP1, CL);
    cudaEventRecord(eE1, s3);

    // s0: attention
    cudaStreamWaitEvent(0, eKV, 0);
    attn_tc<<<dim3(8, Gg), 256, ATTN_SMEM>>>(qeh, kvh, adp, OUTh);
    cudaEventRecord(eAT, 0);

    // s0: applyA (n < 512) -> WoA
    cudaStreamWaitEvent(0, eE1, 0);
    apply_gemm<<<dim3(4, Gg), 256>>>(EXP1, U2, CL, qeh, OUTh, oh, 0);
    gemm_f16<<<dim3(4, 192), 256, GEMM_SMEM>>>(oh, woh, bo, bo, out, Dd, nullptr, 0);

    // s3: applyB (n >= 512) -> WoB (e1 already in-stream; needs attention)
    cudaStreamWaitEvent(s3, eAT, 0);
    apply_gemm<<<dim3(4, Gg), 256, 0, s3>>>(EXP1, U2, CL, qeh, OUTh, oh, 4);
    gemm_f16<<<dim3(4, 192), 256, GEMM_SMEM, s3>>>(oh, woh, bo, bo, out, Dd, nullptr, 4);
    cudaEventRecord(eWoB, s3);
    cudaStreamWaitEvent(0, eWoB, 0);

    // cleanup only outside capture
    cudaStreamCaptureStatus st = cudaStreamCaptureStatusNone;
    cudaStreamIsCapturing(0, &st);
    if (st == cudaStreamCaptureStatusNone) {
        cudaEventDestroy(eStart); cudaEventDestroy(eW); cudaEventDestroy(eKV);
        cudaEventDestroy(eQE);    cudaEventDestroy(eE1);
        cudaEventDestroy(eAT);    cudaEventDestroy(eWoB);
        cudaStreamDestroy(s1); cudaStreamDestroy(s3);
    }
}